// round 1
// baseline (speedup 1.0000x reference)
#include <cuda_runtime.h>
#include <math.h>

#define HEADS 8
#define DH    64
#define DIM   512
#define NTOK  15130
#define NPAD  15360
#define PADR  230
#define NL    256
#define LCH   60
#define IMGH  123
#define NPIX  15129
#define NSPLIT 16

// ---------------- static scratch (allocation-free rule) ----------------
__device__ float g_h   [NTOK*DIM];
__device__ float g_xln [NPAD*DIM];
__device__ float g_qkv [NPAD*3*DIM];
__device__ float g_Qh  [HEADS*NPAD*DH];
__device__ float g_Kh  [HEADS*NPAD*DH];
__device__ float g_Vh  [HEADS*NPAD*DH];
__device__ float g_QL  [HEADS*NL*DH];
__device__ float g_KL  [HEADS*NL*DH];
__device__ float g_A1  [HEADS*NPAD*NL];
__device__ float g_A3  [HEADS*NL*NPAD];
__device__ float g_S2  [HEADS*NL*NL];
__device__ float g_XZ  [HEADS*NL*NL];
__device__ float g_T1  [HEADS*NL*NL];
__device__ float g_T2  [HEADS*NL*NL];
__device__ float g_Zb  [HEADS*NL*NL];
__device__ float g_Z2b [HEADS*NL*NL];
__device__ float g_Tb  [HEADS*NL*DH];
__device__ float g_Ub  [HEADS*NL*DH];
__device__ float g_attn[NPAD*DIM];
__device__ float g_y   [NPAD*DIM];
__device__ float g_scal[2];

// ---------------- generic tiled GEMM ----------------
// C = alpha * A @ B (+bias) (+beta on diagonal) (+relu), batched over blockIdx.z.
// NT=true means B is (N x K) row-major and we compute A @ B^T.
#define BM 64
#define BN 64
#define BKT 16

template<bool NT>
__global__ void gemm_tile(const float* __restrict__ A, const float* __restrict__ B,
                          float* __restrict__ C,
                          int M, int N, int K, int lda, int ldb, int ldc,
                          long sA, long sB, long sC,
                          float alpha, float beta_diag,
                          const float* __restrict__ bias, int relu)
{
    int bz = blockIdx.z;
    A += (long)bz * sA;  B += (long)bz * sB;  C += (long)bz * sC;
    __shared__ float As[BKT][BM+1];
    __shared__ float Bs[BKT][BN+1];
    int tid = threadIdx.x;
    int tx = tid & 15, ty = tid >> 4;
    int row0 = blockIdx.y * BM;
    int col0 = blockIdx.x * BN;
    float acc[4][4] = {};
    for (int k0 = 0; k0 < K; k0 += BKT) {
        for (int i = tid; i < BM*BKT; i += 256) {
            int m = i / BKT, kk = i % BKT;
            int gm = row0 + m, gk = k0 + kk;
            As[kk][m] = (gm < M && gk < K) ? A[(long)gm*lda + gk] : 0.f;
        }
        for (int i = tid; i < BKT*BN; i += 256) {
            if (!NT) {
                int kk = i / BN, n = i % BN;
                int gk = k0 + kk, gn = col0 + n;
                Bs[kk][n] = (gk < K && gn < N) ? B[(long)gk*ldb + gn] : 0.f;
            } else {
                int n = i / BKT, kk = i % BKT;
                int gk = k0 + kk, gn = col0 + n;
                Bs[kk][n] = (gk < K && gn < N) ? B[(long)gn*ldb + gk] : 0.f;
            }
        }
        __syncthreads();
        #pragma unroll
        for (int kk = 0; kk < BKT; kk++) {
            float a[4], bb[4];
            #pragma unroll
            for (int i = 0; i < 4; i++) a[i]  = As[kk][ty*4+i];
            #pragma unroll
            for (int j = 0; j < 4; j++) bb[j] = Bs[kk][tx*4+j];
            #pragma unroll
            for (int i = 0; i < 4; i++)
                #pragma unroll
                for (int j = 0; j < 4; j++) acc[i][j] += a[i]*bb[j];
        }
        __syncthreads();
    }
    #pragma unroll
    for (int i = 0; i < 4; i++) {
        int gm = row0 + ty*4 + i;
        if (gm >= M) continue;
        #pragma unroll
        for (int j = 0; j < 4; j++) {
            int gn = col0 + tx*4 + j;
            if (gn >= N) continue;
            float v = alpha * acc[i][j];
            if (bias) v += bias[gn];
            if (beta_diag != 0.f && gm == gn) v += beta_diag;
            if (relu) v = fmaxf(v, 0.f);
            C[(long)gm*ldc + gn] = v;
        }
    }
}

// split-K GEMM (NN) with atomicAdd epilogue, for a3 @ v (M=256, N=64, K=15360)
__global__ void gemm_splitk(const float* __restrict__ A, const float* __restrict__ B,
                            float* __restrict__ C,
                            int M, int N, int K, int lda, int ldb, int ldc,
                            long sA, long sB, long sC)
{
    int bz = blockIdx.z;
    int batch = bz / NSPLIT, split = bz % NSPLIT;
    A += (long)batch * sA;  B += (long)batch * sB;  C += (long)batch * sC;
    int kchunk = (K + NSPLIT - 1) / NSPLIT;
    int kbeg = split * kchunk;
    int kend = min(K, kbeg + kchunk);
    __shared__ float As[BKT][BM+1];
    __shared__ float Bs[BKT][BN+1];
    int tid = threadIdx.x;
    int tx = tid & 15, ty = tid >> 4;
    int row0 = blockIdx.y * BM;
    int col0 = blockIdx.x * BN;
    float acc[4][4] = {};
    for (int k0 = kbeg; k0 < kend; k0 += BKT) {
        for (int i = tid; i < BM*BKT; i += 256) {
            int m = i / BKT, kk = i % BKT;
            int gm = row0 + m, gk = k0 + kk;
            As[kk][m] = (gm < M && gk < kend) ? A[(long)gm*lda + gk] : 0.f;
        }
        for (int i = tid; i < BKT*BN; i += 256) {
            int kk = i / BN, n = i % BN;
            int gk = k0 + kk, gn = col0 + n;
            Bs[kk][n] = (gk < kend && gn < N) ? B[(long)gk*ldb + gn] : 0.f;
        }
        __syncthreads();
        #pragma unroll
        for (int kk = 0; kk < BKT; kk++) {
            float a[4], bb[4];
            #pragma unroll
            for (int i = 0; i < 4; i++) a[i]  = As[kk][ty*4+i];
            #pragma unroll
            for (int j = 0; j < 4; j++) bb[j] = Bs[kk][tx*4+j];
            #pragma unroll
            for (int i = 0; i < 4; i++)
                #pragma unroll
                for (int j = 0; j < 4; j++) acc[i][j] += a[i]*bb[j];
        }
        __syncthreads();
    }
    #pragma unroll
    for (int i = 0; i < 4; i++) {
        int gm = row0 + ty*4 + i;
        if (gm >= M) continue;
        #pragma unroll
        for (int j = 0; j < 4; j++) {
            int gn = col0 + tx*4 + j;
            if (gn >= N) continue;
            atomicAdd(&C[(long)gm*ldc + gn], acc[i][j]);
        }
    }
}

// ---------------- misc kernels ----------------
__global__ void zero_kernel(float* p, long n) {
    long i = (long)blockIdx.x * blockDim.x + threadIdx.x;
    if (i < n) p[i] = 0.f;
}

__global__ void set_cls(float* h, const float* __restrict__ cls) {
    h[threadIdx.x] = cls[threadIdx.x];   // 512 threads
}

__global__ void dup_rows(float* h) {
    int i = blockIdx.x * blockDim.x + threadIdx.x;
    if (i < 129*DIM) {
        int t = i / DIM, c = i % DIM;
        h[(long)(15001 + t)*DIM + c] = h[(long)(1 + t)*DIM + c];
    }
}

// layernorm with front zero padding: rows [0,PADR) zero, row p>=PADR = LN(h[p-PADR])
__global__ void ln_pad(const float* __restrict__ h, float* __restrict__ xo,
                       const float* __restrict__ g, const float* __restrict__ b)
{
    int row = blockIdx.x;
    float* out = xo + (long)row * DIM;
    int tid = threadIdx.x;
    if (row < PADR) {
        for (int c = tid; c < DIM; c += blockDim.x) out[c] = 0.f;
        return;
    }
    const float* x = h + (long)(row - PADR) * DIM;
    __shared__ float red[256];
    float s = 0.f;
    for (int c = tid; c < DIM; c += blockDim.x) s += x[c];
    red[tid] = s; __syncthreads();
    for (int st = blockDim.x/2; st > 0; st >>= 1) {
        if (tid < st) red[tid] += red[tid+st];
        __syncthreads();
    }
    float mu = red[0] / DIM; __syncthreads();
    float v = 0.f;
    for (int c = tid; c < DIM; c += blockDim.x) { float d = x[c]-mu; v += d*d; }
    red[tid] = v; __syncthreads();
    for (int st = blockDim.x/2; st > 0; st >>= 1) {
        if (tid < st) red[tid] += red[tid+st];
        __syncthreads();
    }
    float rstd = rsqrtf(red[0]/DIM + 1e-5f);
    for (int c = tid; c < DIM; c += blockDim.x)
        out[c] = (x[c]-mu)*rstd*g[c] + b[c];
}

__global__ void split_qkv(const float* __restrict__ qkv, float* __restrict__ Q,
                          float* __restrict__ K, float* __restrict__ V)
{
    int idx = blockIdx.x * blockDim.x + threadIdx.x;
    if (idx >= NPAD*DIM) return;
    int t = idx / DIM, c = idx % DIM;
    int h = c >> 6, d = c & 63;
    long o = ((long)h*NPAD + t)*DH + d;
    const float* row = qkv + (long)t * (3*DIM);
    Q[o] = row[c] * 0.125f;           // DIM_HEAD^-0.5 = 1/8
    K[o] = row[DIM + c];
    V[o] = row[2*DIM + c];
}

__global__ void landmarks_k(const float* __restrict__ Q, const float* __restrict__ K,
                            float* __restrict__ QL, float* __restrict__ KL)
{
    int idx = blockIdx.x * blockDim.x + threadIdx.x;
    if (idx >= HEADS*NL*DH) return;
    int h = idx / (NL*DH);
    int j = (idx / DH) % NL;
    int d = idx % DH;
    const float* qb = Q + ((long)h*NPAD + j*LCH)*DH + d;
    const float* kb = K + ((long)h*NPAD + j*LCH)*DH + d;
    float sq = 0.f, sk = 0.f;
    for (int i = 0; i < LCH; i++) { sq += qb[(long)i*DH]; sk += kb[(long)i*DH]; }
    QL[idx] = sq * (1.f/LCH);
    KL[idx] = sk * (1.f/LCH);
}

__global__ void softmax_rows(float* __restrict__ X, int cols) {
    long r = blockIdx.x;
    float* x = X + r * (long)cols;
    __shared__ float red[256];
    int tid = threadIdx.x, nt = blockDim.x;
    float mx = -1e30f;
    for (int c = tid; c < cols; c += nt) mx = fmaxf(mx, x[c]);
    red[tid] = mx; __syncthreads();
    for (int st = nt/2; st > 0; st >>= 1) {
        if (tid < st) red[tid] = fmaxf(red[tid], red[tid+st]);
        __syncthreads();
    }
    mx = red[0]; __syncthreads();
    float s = 0.f;
    for (int c = tid; c < cols; c += nt) { float e = expf(x[c]-mx); x[c] = e; s += e; }
    red[tid] = s; __syncthreads();
    for (int st = nt/2; st > 0; st >>= 1) {
        if (tid < st) red[tid] += red[tid+st];
        __syncthreads();
    }
    float inv = 1.f / red[0];
    for (int c = tid; c < cols; c += nt) x[c] *= inv;
}

__device__ __forceinline__ void atomicMaxFloatPos(float* addr, float v) {
    atomicMax((int*)addr, __float_as_int(v));   // valid for non-negative floats
}

__global__ void pinv_scalars(const float* __restrict__ A2, float* __restrict__ scal) {
    int hb = blockIdx.x;
    int h = hb / NL, i = hb % NL;
    int mode = blockIdx.y;     // 0: row-sums (col vec), 1: col-sums (row vec)
    const float* base = A2 + (long)h*NL*NL;
    float s = 0.f;
    if (mode == 0) { for (int j = threadIdx.x; j < NL; j += blockDim.x) s += fabsf(base[(long)i*NL + j]); }
    else           { for (int j = threadIdx.x; j < NL; j += blockDim.x) s += fabsf(base[(long)j*NL + i]); }
    __shared__ float red[256];
    red[threadIdx.x] = s; __syncthreads();
    for (int st = blockDim.x/2; st > 0; st >>= 1) {
        if (threadIdx.x < st) red[threadIdx.x] += red[threadIdx.x+st];
        __syncthreads();
    }
    if (threadIdx.x == 0) atomicMaxFloatPos(&scal[mode], red[0]);
}

__global__ void zinit(const float* __restrict__ A2, float* __restrict__ Z,
                      const float* __restrict__ scal)
{
    int idx = blockIdx.x * blockDim.x + threadIdx.x;
    if (idx >= HEADS*NL*NL) return;
    int h = idx / (NL*NL);
    int r = (idx / NL) % NL;
    int c = idx % NL;
    float denom = scal[0] * scal[1];
    Z[idx] = A2[(long)h*NL*NL + (long)c*NL + r] / denom;
}

__global__ void negdiag(const float* __restrict__ X, float* __restrict__ Y, float d) {
    int idx = blockIdx.x * blockDim.x + threadIdx.x;
    if (idx >= HEADS*NL*NL) return;
    int r = (idx / NL) % NL;
    int c = idx % NL;
    Y[idx] = ((r == c) ? d : 0.f) - X[idx];
}

// depthwise 1D conv (kernel 33) over sequence, per head, added into attn out
__global__ void res_conv_add(float* __restrict__ attn, const float* __restrict__ V,
                             const float* __restrict__ w)
{
    int t = blockIdx.x;
    int c = threadIdx.x;         // 512
    int h = c >> 6, d = c & 63;
    float s = 0.f;
    #pragma unroll
    for (int k = 0; k < 33; k++) {
        int tt = t + k - 16;
        if (tt >= 0 && tt < NPAD)
            s += w[h*33 + k] * V[((long)h*NPAD + tt)*DH + d];
    }
    attn[(long)t*DIM + c] += s;
}

__global__ void add_tail(float* __restrict__ h, const float* __restrict__ y) {
    int i = blockIdx.x * blockDim.x + threadIdx.x;
    if (i >= NTOK*DIM) return;
    int t = i / DIM, c = i % DIM;
    h[i] += y[(long)(PADR + t)*DIM + c];
}

// PPEG: conv7 + identity + conv5 + conv3, depthwise per channel, on 123x123 image
__global__ void ppeg_kernel(const float* __restrict__ h, float* __restrict__ out,
                            const float* __restrict__ w7, const float* __restrict__ b7,
                            const float* __restrict__ w5, const float* __restrict__ b5,
                            const float* __restrict__ w3, const float* __restrict__ b3)
{
    int p = blockIdx.x;          // pixel 0..15128
    int ch = threadIdx.x;        // 512
    int r = p / IMGH, c = p % IMGH;
    float acc = h[(long)(1 + p)*DIM + ch] + b7[ch] + b5[ch] + b3[ch];
    #pragma unroll
    for (int dy = -3; dy <= 3; dy++) {
        int rr = r + dy;
        if (rr < 0 || rr >= IMGH) continue;
        #pragma unroll
        for (int dx = -3; dx <= 3; dx++) {
            int cc = c + dx;
            if (cc < 0 || cc >= IMGH) continue;
            float v = h[(long)(1 + rr*IMGH + cc)*DIM + ch];
            acc += v * w7[(long)ch*49 + (dy+3)*7 + (dx+3)];
            if (dy >= -2 && dy <= 2 && dx >= -2 && dx <= 2)
                acc += v * w5[(long)ch*25 + (dy+2)*5 + (dx+2)];
            if (dy >= -1 && dy <= 1 && dx >= -1 && dx <= 1)
                acc += v * w3[(long)ch*9 + (dy+1)*3 + (dx+1)];
        }
    }
    out[(long)p*DIM + ch] = acc;
}

__global__ void ppeg_copyback(float* __restrict__ h, const float* __restrict__ y) {
    long i = (long)blockIdx.x * blockDim.x + threadIdx.x;
    if (i < (long)NPIX*DIM) h[DIM + i] = y[i];
}

// final LN(token0) -> 5 logits -> softmax -> argmax
__global__ void final_head(const float* __restrict__ h, const float* __restrict__ g,
                           const float* __restrict__ b, const float* __restrict__ W,
                           const float* __restrict__ bias, float* __restrict__ out,
                           int out_size)
{
    __shared__ float red[512];
    __shared__ float xn[512];
    int tid = threadIdx.x;       // 512
    float x = h[tid];
    red[tid] = x; __syncthreads();
    for (int st = 256; st > 0; st >>= 1) {
        if (tid < st) red[tid] += red[tid+st];
        __syncthreads();
    }
    float mu = red[0] / DIM; __syncthreads();
    float d = x - mu;
    red[tid] = d*d; __syncthreads();
    for (int st = 256; st > 0; st >>= 1) {
        if (tid < st) red[tid] += red[tid+st];
        __syncthreads();
    }
    float rstd = rsqrtf(red[0]/DIM + 1e-5f); __syncthreads();
    xn[tid] = d*rstd*g[tid] + b[tid];
    __syncthreads();
    if (tid < 5) {
        float s = bias[tid];
        for (int c = 0; c < DIM; c++) s += xn[c] * W[c*5 + tid];
        red[tid] = s;
    }
    __syncthreads();
    if (tid == 0) {
        float lg[5], mx = -1e30f;
        for (int j = 0; j < 5; j++) { lg[j] = red[j]; mx = fmaxf(mx, lg[j]); }
        float se = 0.f, pr[5];
        for (int j = 0; j < 5; j++) { pr[j] = expf(lg[j]-mx); se += pr[j]; }
        int am = 0;
        for (int j = 1; j < 5; j++) if (lg[j] > lg[am]) am = j;
        for (int j = 0; j < 5; j++) {
            if (j < out_size)     out[j]     = lg[j];
            if (5 + j < out_size) out[5 + j] = pr[j]/se;
        }
        if (10 < out_size) out[10] = (float)am;
        for (int j = 11; j < out_size; j++) out[j] = 0.f;
    }
}

// ---------------- host orchestration ----------------
struct Ptrs {
    float *h, *xln, *qkv, *Q, *K, *V, *QL, *KL, *A1, *A3;
    float *S2, *XZ, *T1, *T2, *Z, *Z2, *T, *U, *attn, *y, *scal;
};

static void get_ptrs(Ptrs& P) {
    cudaGetSymbolAddress((void**)&P.h,    g_h);
    cudaGetSymbolAddress((void**)&P.xln,  g_xln);
    cudaGetSymbolAddress((void**)&P.qkv,  g_qkv);
    cudaGetSymbolAddress((void**)&P.Q,    g_Qh);
    cudaGetSymbolAddress((void**)&P.K,    g_Kh);
    cudaGetSymbolAddress((void**)&P.V,    g_Vh);
    cudaGetSymbolAddress((void**)&P.QL,   g_QL);
    cudaGetSymbolAddress((void**)&P.KL,   g_KL);
    cudaGetSymbolAddress((void**)&P.A1,   g_A1);
    cudaGetSymbolAddress((void**)&P.A3,   g_A3);
    cudaGetSymbolAddress((void**)&P.S2,   g_S2);
    cudaGetSymbolAddress((void**)&P.XZ,   g_XZ);
    cudaGetSymbolAddress((void**)&P.T1,   g_T1);
    cudaGetSymbolAddress((void**)&P.T2,   g_T2);
    cudaGetSymbolAddress((void**)&P.Z,    g_Zb);
    cudaGetSymbolAddress((void**)&P.Z2,   g_Z2b);
    cudaGetSymbolAddress((void**)&P.T,    g_Tb);
    cudaGetSymbolAddress((void**)&P.U,    g_Ub);
    cudaGetSymbolAddress((void**)&P.attn, g_attn);
    cudaGetSymbolAddress((void**)&P.y,    g_y);
    cudaGetSymbolAddress((void**)&P.scal, g_scal);
}

static inline dim3 gemm_grid(int M, int N, int batch) {
    return dim3((N + BN - 1)/BN, (M + BM - 1)/BM, batch);
}

static void run_attention(const Ptrs& P, const float* lng, const float* lnb,
                          const float* Wqkv, const float* Wout, const float* bout,
                          const float* resw)
{
    // 1. LN + front pad
    ln_pad<<<NPAD, 256>>>(P.h, P.xln, lng, lnb);
    // 2. qkv = x_ln @ Wqkv
    gemm_tile<false><<<gemm_grid(NPAD, 3*DIM, 1), 256>>>(
        P.xln, Wqkv, P.qkv, NPAD, 3*DIM, DIM, DIM, 3*DIM, 3*DIM,
        0, 0, 0, 1.f, 0.f, nullptr, 0);
    // 3. split heads (+ q scaling)
    split_qkv<<<(NPAD*DIM + 255)/256, 256>>>(P.qkv, P.Q, P.K, P.V);
    // 4. landmarks
    landmarks_k<<<(HEADS*NL*DH + 255)/256, 256>>>(P.Q, P.K, P.QL, P.KL);
    // 5. sim2 = QL @ KL^T, softmax
    gemm_tile<true><<<gemm_grid(NL, NL, HEADS), 256>>>(
        P.QL, P.KL, P.S2, NL, NL, DH, DH, DH, NL,
        (long)NL*DH, (long)NL*DH, (long)NL*NL, 1.f, 0.f, nullptr, 0);
    softmax_rows<<<HEADS*NL, 256>>>(P.S2, NL);
    // 6. Moore-Penrose pinv
    zero_kernel<<<1, 32>>>(P.scal, 2);
    pinv_scalars<<<dim3(HEADS*NL, 2, 1), 256>>>(P.S2, P.scal);
    zinit<<<(HEADS*NL*NL + 255)/256, 256>>>(P.S2, P.Z, P.scal);
    long sQ = (long)NL*NL;
    for (int it = 0; it < 6; it++) {
        float* zin  = (it % 2 == 0) ? P.Z  : P.Z2;
        float* zout = (it % 2 == 0) ? P.Z2 : P.Z;
        gemm_tile<false><<<gemm_grid(NL, NL, HEADS), 256>>>(
            P.S2, zin, P.XZ, NL, NL, NL, NL, NL, NL, sQ, sQ, sQ, 1.f, 0.f, nullptr, 0);
        negdiag<<<(HEADS*NL*NL + 255)/256, 256>>>(P.XZ, P.T1, 7.f);
        gemm_tile<false><<<gemm_grid(NL, NL, HEADS), 256>>>(
            P.XZ, P.T1, P.T2, NL, NL, NL, NL, NL, NL, sQ, sQ, sQ, -1.f, 15.f, nullptr, 0);
        gemm_tile<false><<<gemm_grid(NL, NL, HEADS), 256>>>(
            P.XZ, P.T2, P.T1, NL, NL, NL, NL, NL, NL, sQ, sQ, sQ, -1.f, 13.f, nullptr, 0);
        gemm_tile<false><<<gemm_grid(NL, NL, HEADS), 256>>>(
            zin, P.T1, zout, NL, NL, NL, NL, NL, NL, sQ, sQ, sQ, 0.25f, 0.f, nullptr, 0);
    }
    // result in P.Z after 6 iterations
    // 7. a1 = softmax(Q @ KL^T)
    gemm_tile<true><<<gemm_grid(NPAD, NL, HEADS), 256>>>(
        P.Q, P.KL, P.A1, NPAD, NL, DH, DH, DH, NL,
        (long)NPAD*DH, (long)NL*DH, (long)NPAD*NL, 1.f, 0.f, nullptr, 0);
    softmax_rows<<<HEADS*NPAD, 128>>>(P.A1, NL);
    // 8. a3 = softmax(QL @ K^T)
    gemm_tile<true><<<gemm_grid(NL, NPAD, HEADS), 256>>>(
        P.QL, P.K, P.A3, NL, NPAD, DH, DH, DH, NPAD,
        (long)NL*DH, (long)NPAD*DH, (long)NL*NPAD, 1.f, 0.f, nullptr, 0);
    softmax_rows<<<HEADS*NL, 256>>>(P.A3, NPAD);
    // 9. T = a3 @ V  (split-K)
    zero_kernel<<<(HEADS*NL*DH + 255)/256, 256>>>(P.T, (long)HEADS*NL*DH);
    gemm_splitk<<<dim3(1, (NL+BM-1)/BM, HEADS*NSPLIT), 256>>>(
        P.A3, P.V, P.T, NL, DH, NPAD, NPAD, DH, DH,
        (long)NL*NPAD, (long)NPAD*DH, (long)NL*DH);
    // 10. U = a2_inv @ T
    gemm_tile<false><<<gemm_grid(NL, DH, HEADS), 256>>>(
        P.Z, P.T, P.U, NL, DH, NL, NL, DH, DH,
        sQ, (long)NL*DH, (long)NL*DH, 1.f, 0.f, nullptr, 0);
    // 11. attn = a1 @ U  (written head-interleaved into [NPAD][512])
    gemm_tile<false><<<gemm_grid(NPAD, DH, HEADS), 256>>>(
        P.A1, P.U, P.attn, NPAD, DH, NL, NL, DH, DIM,
        (long)NPAD*NL, (long)NL*DH, (long)DH, 1.f, 0.f, nullptr, 0);
    // 12. residual depthwise conv (k=33) on V, added in
    res_conv_add<<<NPAD, DIM>>>(P.attn, P.V, resw);
    // 13. out projection + bias
    gemm_tile<false><<<gemm_grid(NPAD, DIM, 1), 256>>>(
        P.attn, Wout, P.y, NPAD, DIM, DIM, DIM, DIM, DIM,
        0, 0, 0, 1.f, 0.f, bout, 0);
    // 14. h += y[last NTOK rows]
    add_tail<<<(NTOK*DIM + 255)/256, 256>>>(P.h, P.y);
}

extern "C" void kernel_launch(void* const* d_in, const int* in_sizes, int n_in,
                              void* d_out, int out_size)
{
    const float* data      = (const float*)d_in[0];
    const float* W_fc1     = (const float*)d_in[1];
    const float* b_fc1     = (const float*)d_in[2];
    const float* cls_token = (const float*)d_in[3];
    const float* ln1_g     = (const float*)d_in[4];
    const float* ln1_b     = (const float*)d_in[5];
    const float* qkv1      = (const float*)d_in[6];
    const float* out1_w    = (const float*)d_in[7];
    const float* out1_b    = (const float*)d_in[8];
    const float* res1      = (const float*)d_in[9];
    const float* w7        = (const float*)d_in[10];
    const float* b7        = (const float*)d_in[11];
    const float* w5        = (const float*)d_in[12];
    const float* b5        = (const float*)d_in[13];
    const float* w3        = (const float*)d_in[14];
    const float* b3        = (const float*)d_in[15];
    const float* ln2_g     = (const float*)d_in[16];
    const float* ln2_b     = (const float*)d_in[17];
    const float* qkv2      = (const float*)d_in[18];
    const float* out2_w    = (const float*)d_in[19];
    const float* out2_b    = (const float*)d_in[20];
    const float* res2      = (const float*)d_in[21];
    const float* norm_g    = (const float*)d_in[22];
    const float* norm_b    = (const float*)d_in[23];
    const float* W_fc2     = (const float*)d_in[24];
    const float* b_fc2     = (const float*)d_in[25];

    Ptrs P;
    get_ptrs(P);

    // stage A: token assembly
    set_cls<<<1, DIM>>>(P.h, cls_token);
    gemm_tile<false><<<gemm_grid(15000, DIM, 1), 256>>>(
        data, W_fc1, P.h + DIM, 15000, DIM, 1024, 1024, DIM, DIM,
        0, 0, 0, 1.f, 0.f, b_fc1, 1);
    dup_rows<<<(129*DIM + 255)/256, 256>>>(P.h);

    // block 1
    run_attention(P, ln1_g, ln1_b, qkv1, out1_w, out1_b, res1);

    // PPEG
    ppeg_kernel<<<NPIX, DIM>>>(P.h, P.y, w7, b7, w5, b5, w3, b3);
    ppeg_copyback<<<(int)(((long)NPIX*DIM + 255)/256), 256>>>(P.h, P.y);

    // block 2
    run_attention(P, ln2_g, ln2_b, qkv2, out2_w, out2_b, res2);

    // head
    final_head<<<1, DIM>>>(P.h, norm_g, norm_b, W_fc2, b_fc2, (float*)d_out, out_size);
}

// round 2
// speedup vs baseline: 1.2905x; 1.2905x over previous
#include <cuda_runtime.h>
#include <math.h>

#define HEADS 8
#define DH    64
#define DIM   512
#define NTOK  15130
#define NPAD  15360
#define PADR  230
#define NL    256
#define LCH   60
#define IMGH  123
#define NPIX  15129
#define NSPLIT 16

// ---------------- static scratch (allocation-free rule) ----------------
__device__ float g_h   [NTOK*DIM];
__device__ float g_xln [NPAD*DIM];
__device__ float g_qkv [NPAD*3*DIM];
__device__ float g_Qh  [HEADS*NPAD*DH];
__device__ float g_Kh  [HEADS*NPAD*DH];
__device__ float g_Vh  [HEADS*NPAD*DH];
__device__ float g_QL  [HEADS*NL*DH];
__device__ float g_KL  [HEADS*NL*DH];
__device__ float g_A1  [HEADS*NPAD*NL];
__device__ float g_A3  [HEADS*NL*NPAD];
__device__ float g_S2  [HEADS*NL*NL];
__device__ float g_XZ  [HEADS*NL*NL];
__device__ float g_T1  [HEADS*NL*NL];
__device__ float g_T2  [HEADS*NL*NL];
__device__ float g_Zb  [HEADS*NL*NL];
__device__ float g_Z2b [HEADS*NL*NL];
__device__ float g_Tb  [HEADS*NL*DH];
__device__ float g_Ub  [HEADS*NL*DH];
__device__ float g_attn[NPAD*DIM];
__device__ float g_y   [NPAD*DIM];
__device__ float g_scal[2];

// ================= big GEMM: 128x128x8, double-buffered, 8x8/thread =================
// C = A @ B (+bias) (+relu). NT: B is N x K row-major (compute A @ B^T).
// Requirements: K % 8 == 0, N % 128 == 0 (all big-path call sites satisfy both).
#define GBM 128
#define GBN 128
#define GBK 8

template<bool NT>
__global__ void __launch_bounds__(256) gemm_big(
    const float* __restrict__ A, const float* __restrict__ B, float* __restrict__ C,
    int M, int N, int K, int lda, int ldb, int ldc,
    long sA, long sB, long sC,
    const float* __restrict__ bias, int relu)
{
    A += (long)blockIdx.z * sA;  B += (long)blockIdx.z * sB;  C += (long)blockIdx.z * sC;
    __shared__ float As[2][GBK][GBM];
    __shared__ float Bs[2][GBK][GBN];
    const int tid = threadIdx.x;
    const int row0 = blockIdx.y * GBM;
    const int col0 = blockIdx.x * GBN;
    const int tx = tid & 15, ty = tid >> 4;

    // A loading map: thread -> (row tid/2, kcol (tid&1)*4), float4 along K
    const int arow = tid >> 1, acol = (tid & 1) * 4;
    // B loading map (!NT): (krow tid/32, ncol (tid&31)*4), float4 along N
    const int bk = tid >> 5, bn = (tid & 31) * 4;

    const int ntiles = K / GBK;
    float4 ar, br;

    auto load_regs = [&](int k0) {
        int gm = row0 + arow;
        ar = make_float4(0.f, 0.f, 0.f, 0.f);
        if (gm < M) ar = *(const float4*)&A[(long)gm * lda + k0 + acol];
        if (!NT) {
            br = *(const float4*)&B[(long)(k0 + bk) * ldb + col0 + bn];
        } else {
            int gn = col0 + arow;
            br = make_float4(0.f, 0.f, 0.f, 0.f);
            if (gn < N) br = *(const float4*)&B[(long)gn * ldb + k0 + acol];
        }
    };
    auto store_smem = [&](int buf) {
        As[buf][acol + 0][arow] = ar.x;
        As[buf][acol + 1][arow] = ar.y;
        As[buf][acol + 2][arow] = ar.z;
        As[buf][acol + 3][arow] = ar.w;
        if (!NT) {
            *(float4*)&Bs[buf][bk][bn] = br;
        } else {
            Bs[buf][acol + 0][arow] = br.x;
            Bs[buf][acol + 1][arow] = br.y;
            Bs[buf][acol + 2][arow] = br.z;
            Bs[buf][acol + 3][arow] = br.w;
        }
    };

    float acc[8][8] = {};

    load_regs(0);
    store_smem(0);
    __syncthreads();

    for (int kt = 0; kt < ntiles; kt++) {
        if (kt + 1 < ntiles) load_regs((kt + 1) * GBK);
        int buf = kt & 1;
        #pragma unroll
        for (int k = 0; k < GBK; k++) {
            float4 a0 = *(const float4*)&As[buf][k][ty * 4];
            float4 a1 = *(const float4*)&As[buf][k][64 + ty * 4];
            float4 b0 = *(const float4*)&Bs[buf][k][tx * 4];
            float4 b1 = *(const float4*)&Bs[buf][k][64 + tx * 4];
            float av[8] = {a0.x, a0.y, a0.z, a0.w, a1.x, a1.y, a1.z, a1.w};
            float bv[8] = {b0.x, b0.y, b0.z, b0.w, b1.x, b1.y, b1.z, b1.w};
            #pragma unroll
            for (int i = 0; i < 8; i++)
                #pragma unroll
                for (int j = 0; j < 8; j++)
                    acc[i][j] += av[i] * bv[j];
        }
        if (kt + 1 < ntiles) {
            store_smem((kt + 1) & 1);
            __syncthreads();
        }
    }

    // epilogue: float4 stores, N guaranteed multiple of 128
    #pragma unroll
    for (int rc = 0; rc < 2; rc++) {
        #pragma unroll
        for (int i = 0; i < 4; i++) {
            int gm = row0 + rc * 64 + ty * 4 + i;
            if (gm >= M) continue;
            #pragma unroll
            for (int cc = 0; cc < 2; cc++) {
                int gn = col0 + cc * 64 + tx * 4;
                float4 v;
                v.x = acc[rc * 4 + i][cc * 4 + 0];
                v.y = acc[rc * 4 + i][cc * 4 + 1];
                v.z = acc[rc * 4 + i][cc * 4 + 2];
                v.w = acc[rc * 4 + i][cc * 4 + 3];
                if (bias) {
                    float4 bb = *(const float4*)&bias[gn];
                    v.x += bb.x; v.y += bb.y; v.z += bb.z; v.w += bb.w;
                }
                if (relu) {
                    v.x = fmaxf(v.x, 0.f); v.y = fmaxf(v.y, 0.f);
                    v.z = fmaxf(v.z, 0.f); v.w = fmaxf(v.w, 0.f);
                }
                *(float4*)&C[(long)gm * ldc + gn] = v;
            }
        }
    }
}

// ================= small tiled GEMM (64x64x16) =================
// C = alpha * A @ B + beta_diag*I + gammaA*A (+bias) (+relu), batched over z.
#define BM 64
#define BN 64
#define BKT 16

template<bool NT>
__global__ void gemm_tile(const float* __restrict__ A, const float* __restrict__ B,
                          float* __restrict__ C,
                          int M, int N, int K, int lda, int ldb, int ldc,
                          long sA, long sB, long sC,
                          float alpha, float beta_diag, float gammaA,
                          const float* __restrict__ bias, int relu)
{
    int bz = blockIdx.z;
    A += (long)bz * sA;  B += (long)bz * sB;  C += (long)bz * sC;
    __shared__ float As[BKT][BM+1];
    __shared__ float Bs[BKT][BN+1];
    int tid = threadIdx.x;
    int tx = tid & 15, ty = tid >> 4;
    int row0 = blockIdx.y * BM;
    int col0 = blockIdx.x * BN;
    float acc[4][4] = {};
    for (int k0 = 0; k0 < K; k0 += BKT) {
        for (int i = tid; i < BM*BKT; i += 256) {
            int m = i / BKT, kk = i % BKT;
            int gm = row0 + m, gk = k0 + kk;
            As[kk][m] = (gm < M && gk < K) ? A[(long)gm*lda + gk] : 0.f;
        }
        for (int i = tid; i < BKT*BN; i += 256) {
            if (!NT) {
                int kk = i / BN, n = i % BN;
                int gk = k0 + kk, gn = col0 + n;
                Bs[kk][n] = (gk < K && gn < N) ? B[(long)gk*ldb + gn] : 0.f;
            } else {
                int n = i / BKT, kk = i % BKT;
                int gk = k0 + kk, gn = col0 + n;
                Bs[kk][n] = (gk < K && gn < N) ? B[(long)gn*ldb + gk] : 0.f;
            }
        }
        __syncthreads();
        #pragma unroll
        for (int kk = 0; kk < BKT; kk++) {
            float a[4], bb[4];
            #pragma unroll
            for (int i = 0; i < 4; i++) a[i]  = As[kk][ty*4+i];
            #pragma unroll
            for (int j = 0; j < 4; j++) bb[j] = Bs[kk][tx*4+j];
            #pragma unroll
            for (int i = 0; i < 4; i++)
                #pragma unroll
                for (int j = 0; j < 4; j++) acc[i][j] += a[i]*bb[j];
        }
        __syncthreads();
    }
    #pragma unroll
    for (int i = 0; i < 4; i++) {
        int gm = row0 + ty*4 + i;
        if (gm >= M) continue;
        #pragma unroll
        for (int j = 0; j < 4; j++) {
            int gn = col0 + tx*4 + j;
            if (gn >= N) continue;
            float v = alpha * acc[i][j];
            if (bias) v += bias[gn];
            if (beta_diag != 0.f && gm == gn) v += beta_diag;
            if (gammaA != 0.f) v += gammaA * A[(long)gm*lda + gn];  // requires N==K
            if (relu) v = fmaxf(v, 0.f);
            C[(long)gm*ldc + gn] = v;
        }
    }
}

// split-K GEMM (NN) with atomicAdd epilogue, for a3 @ v (M=256, N=64, K=15360)
__global__ void gemm_splitk(const float* __restrict__ A, const float* __restrict__ B,
                            float* __restrict__ C,
                            int M, int N, int K, int lda, int ldb, int ldc,
                            long sA, long sB, long sC)
{
    int bz = blockIdx.z;
    int batch = bz / NSPLIT, split = bz % NSPLIT;
    A += (long)batch * sA;  B += (long)batch * sB;  C += (long)batch * sC;
    int kchunk = (K + NSPLIT - 1) / NSPLIT;
    int kbeg = split * kchunk;
    int kend = min(K, kbeg + kchunk);
    __shared__ float As[BKT][BM+1];
    __shared__ float Bs[BKT][BN+1];
    int tid = threadIdx.x;
    int tx = tid & 15, ty = tid >> 4;
    int row0 = blockIdx.y * BM;
    int col0 = blockIdx.x * BN;
    float acc[4][4] = {};
    for (int k0 = kbeg; k0 < kend; k0 += BKT) {
        for (int i = tid; i < BM*BKT; i += 256) {
            int m = i / BKT, kk = i % BKT;
            int gm = row0 + m, gk = k0 + kk;
            As[kk][m] = (gm < M && gk < kend) ? A[(long)gm*lda + gk] : 0.f;
        }
        for (int i = tid; i < BKT*BN; i += 256) {
            int kk = i / BN, n = i % BN;
            int gk = k0 + kk, gn = col0 + n;
            Bs[kk][n] = (gk < kend && gn < N) ? B[(long)gk*ldb + gn] : 0.f;
        }
        __syncthreads();
        #pragma unroll
        for (int kk = 0; kk < BKT; kk++) {
            float a[4], bb[4];
            #pragma unroll
            for (int i = 0; i < 4; i++) a[i]  = As[kk][ty*4+i];
            #pragma unroll
            for (int j = 0; j < 4; j++) bb[j] = Bs[kk][tx*4+j];
            #pragma unroll
            for (int i = 0; i < 4; i++)
                #pragma unroll
                for (int j = 0; j < 4; j++) acc[i][j] += a[i]*bb[j];
        }
        __syncthreads();
    }
    #pragma unroll
    for (int i = 0; i < 4; i++) {
        int gm = row0 + ty*4 + i;
        if (gm >= M) continue;
        #pragma unroll
        for (int j = 0; j < 4; j++) {
            int gn = col0 + tx*4 + j;
            if (gn >= N) continue;
            atomicAdd(&C[(long)gm*ldc + gn], acc[i][j]);
        }
    }
}

// ---------------- misc kernels ----------------
__global__ void zero_kernel(float* p, long n) {
    long i = (long)blockIdx.x * blockDim.x + threadIdx.x;
    if (i < n) p[i] = 0.f;
}

__global__ void set_cls(float* h, const float* __restrict__ cls) {
    h[threadIdx.x] = cls[threadIdx.x];   // 512 threads
}

__global__ void dup_rows(float* h) {
    int i = blockIdx.x * blockDim.x + threadIdx.x;
    if (i < 129*DIM) {
        int t = i / DIM, c = i % DIM;
        h[(long)(15001 + t)*DIM + c] = h[(long)(1 + t)*DIM + c];
    }
}

// layernorm with front zero padding: rows [0,PADR) zero, row p>=PADR = LN(h[p-PADR])
__global__ void ln_pad(const float* __restrict__ h, float* __restrict__ xo,
                       const float* __restrict__ g, const float* __restrict__ b)
{
    int row = blockIdx.x;
    float* out = xo + (long)row * DIM;
    int tid = threadIdx.x;
    if (row < PADR) {
        for (int c = tid; c < DIM; c += blockDim.x) out[c] = 0.f;
        return;
    }
    const float* x = h + (long)(row - PADR) * DIM;
    __shared__ float red[256];
    float s = 0.f;
    for (int c = tid; c < DIM; c += blockDim.x) s += x[c];
    red[tid] = s; __syncthreads();
    for (int st = blockDim.x/2; st > 0; st >>= 1) {
        if (tid < st) red[tid] += red[tid+st];
        __syncthreads();
    }
    float mu = red[0] / DIM; __syncthreads();
    float v = 0.f;
    for (int c = tid; c < DIM; c += blockDim.x) { float d = x[c]-mu; v += d*d; }
    red[tid] = v; __syncthreads();
    for (int st = blockDim.x/2; st > 0; st >>= 1) {
        if (tid < st) red[tid] += red[tid+st];
        __syncthreads();
    }
    float rstd = rsqrtf(red[0]/DIM + 1e-5f);
    for (int c = tid; c < DIM; c += blockDim.x)
        out[c] = (x[c]-mu)*rstd*g[c] + b[c];
}

__global__ void split_qkv(const float* __restrict__ qkv, float* __restrict__ Q,
                          float* __restrict__ K, float* __restrict__ V)
{
    int idx = blockIdx.x * blockDim.x + threadIdx.x;
    if (idx >= NPAD*DIM) return;
    int t = idx / DIM, c = idx % DIM;
    int h = c >> 6, d = c & 63;
    long o = ((long)h*NPAD + t)*DH + d;
    const float* row = qkv + (long)t * (3*DIM);
    Q[o] = row[c] * 0.125f;           // DIM_HEAD^-0.5 = 1/8
    K[o] = row[DIM + c];
    V[o] = row[2*DIM + c];
}

__global__ void landmarks_k(const float* __restrict__ Q, const float* __restrict__ K,
                            float* __restrict__ QL, float* __restrict__ KL)
{
    int idx = blockIdx.x * blockDim.x + threadIdx.x;
    if (idx >= HEADS*NL*DH) return;
    int h = idx / (NL*DH);
    int j = (idx / DH) % NL;
    int d = idx % DH;
    const float* qb = Q + ((long)h*NPAD + j*LCH)*DH + d;
    const float* kb = K + ((long)h*NPAD + j*LCH)*DH + d;
    float sq = 0.f, sk = 0.f;
    for (int i = 0; i < LCH; i++) { sq += qb[(long)i*DH]; sk += kb[(long)i*DH]; }
    QL[idx] = sq * (1.f/LCH);
    KL[idx] = sk * (1.f/LCH);
}

__global__ void softmax_rows(float* __restrict__ X, int cols) {
    long r = blockIdx.x;
    float* x = X + r * (long)cols;
    __shared__ float red[256];
    int tid = threadIdx.x, nt = blockDim.x;
    float mx = -1e30f;
    for (int c = tid; c < cols; c += nt) mx = fmaxf(mx, x[c]);
    red[tid] = mx; __syncthreads();
    for (int st = nt/2; st > 0; st >>= 1) {
        if (tid < st) red[tid] = fmaxf(red[tid], red[tid+st]);
        __syncthreads();
    }
    mx = red[0]; __syncthreads();
    float s = 0.f;
    for (int c = tid; c < cols; c += nt) { float e = expf(x[c]-mx); x[c] = e; s += e; }
    red[tid] = s; __syncthreads();
    for (int st = nt/2; st > 0; st >>= 1) {
        if (tid < st) red[tid] += red[tid+st];
        __syncthreads();
    }
    float inv = 1.f / red[0];
    for (int c = tid; c < cols; c += nt) x[c] *= inv;
}

__device__ __forceinline__ void atomicMaxFloatPos(float* addr, float v) {
    atomicMax((int*)addr, __float_as_int(v));   // valid for non-negative floats
}

__global__ void pinv_scalars(const float* __restrict__ A2, float* __restrict__ scal) {
    int hb = blockIdx.x;
    int h = hb / NL, i = hb % NL;
    int mode = blockIdx.y;     // 0: row-sums (col vec), 1: col-sums (row vec)
    const float* base = A2 + (long)h*NL*NL;
    float s = 0.f;
    if (mode == 0) { for (int j = threadIdx.x; j < NL; j += blockDim.x) s += fabsf(base[(long)i*NL + j]); }
    else           { for (int j = threadIdx.x; j < NL; j += blockDim.x) s += fabsf(base[(long)j*NL + i]); }
    __shared__ float red[256];
    red[threadIdx.x] = s; __syncthreads();
    for (int st = blockDim.x/2; st > 0; st >>= 1) {
        if (threadIdx.x < st) red[threadIdx.x] += red[threadIdx.x+st];
        __syncthreads();
    }
    if (threadIdx.x == 0) atomicMaxFloatPos(&scal[mode], red[0]);
}

__global__ void zinit(const float* __restrict__ A2, float* __restrict__ Z,
                      const float* __restrict__ scal)
{
    int idx = blockIdx.x * blockDim.x + threadIdx.x;
    if (idx >= HEADS*NL*NL) return;
    int h = idx / (NL*NL);
    int r = (idx / NL) % NL;
    int c = idx % NL;
    float denom = scal[0] * scal[1];
    Z[idx] = A2[(long)h*NL*NL + (long)c*NL + r] / denom;
}

// depthwise 1D conv (kernel 33) over sequence, per head, added into attn out
__global__ void res_conv_add(float* __restrict__ attn, const float* __restrict__ V,
                             const float* __restrict__ w)
{
    int t = blockIdx.x;
    int c = threadIdx.x;         // 512
    int h = c >> 6, d = c & 63;
    float s = 0.f;
    #pragma unroll
    for (int k = 0; k < 33; k++) {
        int tt = t + k - 16;
        if (tt >= 0 && tt < NPAD)
            s += w[h*33 + k] * V[((long)h*NPAD + tt)*DH + d];
    }
    attn[(long)t*DIM + c] += s;
}

__global__ void add_tail(float* __restrict__ h, const float* __restrict__ y) {
    int i = blockIdx.x * blockDim.x + threadIdx.x;
    if (i >= NTOK*DIM) return;
    int t = i / DIM, c = i % DIM;
    h[i] += y[(long)(PADR + t)*DIM + c];
}

// PPEG: conv7 + identity + conv5 + conv3, depthwise per channel, on 123x123 image
__global__ void ppeg_kernel(const float* __restrict__ h, float* __restrict__ out,
                            const float* __restrict__ w7, const float* __restrict__ b7,
                            const float* __restrict__ w5, const float* __restrict__ b5,
                            const float* __restrict__ w3, const float* __restrict__ b3)
{
    int p = blockIdx.x;          // pixel 0..15128
    int ch = threadIdx.x;        // 512
    int r = p / IMGH, c = p % IMGH;
    float acc = h[(long)(1 + p)*DIM + ch] + b7[ch] + b5[ch] + b3[ch];
    #pragma unroll
    for (int dy = -3; dy <= 3; dy++) {
        int rr = r + dy;
        if (rr < 0 || rr >= IMGH) continue;
        #pragma unroll
        for (int dx = -3; dx <= 3; dx++) {
            int cc = c + dx;
            if (cc < 0 || cc >= IMGH) continue;
            float v = h[(long)(1 + rr*IMGH + cc)*DIM + ch];
            acc += v * w7[(long)ch*49 + (dy+3)*7 + (dx+3)];
            if (dy >= -2 && dy <= 2 && dx >= -2 && dx <= 2)
                acc += v * w5[(long)ch*25 + (dy+2)*5 + (dx+2)];
            if (dy >= -1 && dy <= 1 && dx >= -1 && dx <= 1)
                acc += v * w3[(long)ch*9 + (dy+1)*3 + (dx+1)];
        }
    }
    out[(long)p*DIM + ch] = acc;
}

__global__ void ppeg_copyback(float* __restrict__ h, const float* __restrict__ y) {
    long i = (long)blockIdx.x * blockDim.x + threadIdx.x;
    if (i < (long)NPIX*DIM) h[DIM + i] = y[i];
}

// final LN(token0) -> 5 logits -> softmax -> argmax
__global__ void final_head(const float* __restrict__ h, const float* __restrict__ g,
                           const float* __restrict__ b, const float* __restrict__ W,
                           const float* __restrict__ bias, float* __restrict__ out,
                           int out_size)
{
    __shared__ float red[512];
    __shared__ float xn[512];
    int tid = threadIdx.x;       // 512
    float x = h[tid];
    red[tid] = x; __syncthreads();
    for (int st = 256; st > 0; st >>= 1) {
        if (tid < st) red[tid] += red[tid+st];
        __syncthreads();
    }
    float mu = red[0] / DIM; __syncthreads();
    float d = x - mu;
    red[tid] = d*d; __syncthreads();
    for (int st = 256; st > 0; st >>= 1) {
        if (tid < st) red[tid] += red[tid+st];
        __syncthreads();
    }
    float rstd = rsqrtf(red[0]/DIM + 1e-5f); __syncthreads();
    xn[tid] = d*rstd*g[tid] + b[tid];
    __syncthreads();
    if (tid < 5) {
        float s = bias[tid];
        for (int c = 0; c < DIM; c++) s += xn[c] * W[c*5 + tid];
        red[tid] = s;
    }
    __syncthreads();
    if (tid == 0) {
        float lg[5], mx = -1e30f;
        for (int j = 0; j < 5; j++) { lg[j] = red[j]; mx = fmaxf(mx, lg[j]); }
        float se = 0.f, pr[5];
        for (int j = 0; j < 5; j++) { pr[j] = expf(lg[j]-mx); se += pr[j]; }
        int am = 0;
        for (int j = 1; j < 5; j++) if (lg[j] > lg[am]) am = j;
        for (int j = 0; j < 5; j++) {
            if (j < out_size)     out[j]     = lg[j];
            if (5 + j < out_size) out[5 + j] = pr[j]/se;
        }
        if (10 < out_size) out[10] = (float)am;
        for (int j = 11; j < out_size; j++) out[j] = 0.f;
    }
}

// ---------------- host orchestration ----------------
struct Ptrs {
    float *h, *xln, *qkv, *Q, *K, *V, *QL, *KL, *A1, *A3;
    float *S2, *XZ, *T1, *T2, *Z, *Z2, *T, *U, *attn, *y, *scal;
};

static void get_ptrs(Ptrs& P) {
    cudaGetSymbolAddress((void**)&P.h,    g_h);
    cudaGetSymbolAddress((void**)&P.xln,  g_xln);
    cudaGetSymbolAddress((void**)&P.qkv,  g_qkv);
    cudaGetSymbolAddress((void**)&P.Q,    g_Qh);
    cudaGetSymbolAddress((void**)&P.K,    g_Kh);
    cudaGetSymbolAddress((void**)&P.V,    g_Vh);
    cudaGetSymbolAddress((void**)&P.QL,   g_QL);
    cudaGetSymbolAddress((void**)&P.KL,   g_KL);
    cudaGetSymbolAddress((void**)&P.A1,   g_A1);
    cudaGetSymbolAddress((void**)&P.A3,   g_A3);
    cudaGetSymbolAddress((void**)&P.S2,   g_S2);
    cudaGetSymbolAddress((void**)&P.XZ,   g_XZ);
    cudaGetSymbolAddress((void**)&P.T1,   g_T1);
    cudaGetSymbolAddress((void**)&P.T2,   g_T2);
    cudaGetSymbolAddress((void**)&P.Z,    g_Zb);
    cudaGetSymbolAddress((void**)&P.Z2,   g_Z2b);
    cudaGetSymbolAddress((void**)&P.T,    g_Tb);
    cudaGetSymbolAddress((void**)&P.U,    g_Ub);
    cudaGetSymbolAddress((void**)&P.attn, g_attn);
    cudaGetSymbolAddress((void**)&P.y,    g_y);
    cudaGetSymbolAddress((void**)&P.scal, g_scal);
}

static inline dim3 gemm_grid(int M, int N, int batch) {
    return dim3((N + BN - 1)/BN, (M + BM - 1)/BM, batch);
}
static inline dim3 big_grid(int M, int N, int batch) {
    return dim3(N / GBN, (M + GBM - 1)/GBM, batch);
}

static void run_attention(const Ptrs& P, const float* lng, const float* lnb,
                          const float* Wqkv, const float* Wout, const float* bout,
                          const float* resw)
{
    // 1. LN + front pad
    ln_pad<<<NPAD, 256>>>(P.h, P.xln, lng, lnb);
    // 2. qkv = x_ln @ Wqkv  (15360 x 1536 x 512)
    gemm_big<false><<<big_grid(NPAD, 3*DIM, 1), 256>>>(
        P.xln, Wqkv, P.qkv, NPAD, 3*DIM, DIM, DIM, 3*DIM, 3*DIM,
        0, 0, 0, nullptr, 0);
    // 3. split heads (+ q scaling)
    split_qkv<<<(NPAD*DIM + 255)/256, 256>>>(P.qkv, P.Q, P.K, P.V);
    // 4. landmarks
    landmarks_k<<<(HEADS*NL*DH + 255)/256, 256>>>(P.Q, P.K, P.QL, P.KL);
    // 5. sim2 = QL @ KL^T, softmax
    gemm_tile<true><<<gemm_grid(NL, NL, HEADS), 256>>>(
        P.QL, P.KL, P.S2, NL, NL, DH, DH, DH, NL,
        (long)NL*DH, (long)NL*DH, (long)NL*NL, 1.f, 0.f, 0.f, nullptr, 0);
    softmax_rows<<<HEADS*NL, 256>>>(P.S2, NL);
    // 6. Moore-Penrose pinv
    zero_kernel<<<1, 32>>>(P.scal, 2);
    pinv_scalars<<<dim3(HEADS*NL, 2, 1), 256>>>(P.S2, P.scal);
    zinit<<<(HEADS*NL*NL + 255)/256, 256>>>(P.S2, P.Z, P.scal);
    long sQ = (long)NL*NL;
    for (int it = 0; it < 6; it++) {
        float* zin  = (it % 2 == 0) ? P.Z  : P.Z2;
        float* zout = (it % 2 == 0) ? P.Z2 : P.Z;
        // XZ = S2 @ zin
        gemm_tile<false><<<gemm_grid(NL, NL, HEADS), 256>>>(
            P.S2, zin, P.XZ, NL, NL, NL, NL, NL, NL, sQ, sQ, sQ, 1.f, 0.f, 0.f, nullptr, 0);
        // T2 = 15I - XZ @ (7I - XZ) = XZ@XZ - 7*XZ + 15I   (negdiag fused via gammaA)
        gemm_tile<false><<<gemm_grid(NL, NL, HEADS), 256>>>(
            P.XZ, P.XZ, P.T2, NL, NL, NL, NL, NL, NL, sQ, sQ, sQ, 1.f, 15.f, -7.f, nullptr, 0);
        // T1 = 13I - XZ @ T2
        gemm_tile<false><<<gemm_grid(NL, NL, HEADS), 256>>>(
            P.XZ, P.T2, P.T1, NL, NL, NL, NL, NL, NL, sQ, sQ, sQ, -1.f, 13.f, 0.f, nullptr, 0);
        // zout = 0.25 * zin @ T1
        gemm_tile<false><<<gemm_grid(NL, NL, HEADS), 256>>>(
            zin, P.T1, zout, NL, NL, NL, NL, NL, NL, sQ, sQ, sQ, 0.25f, 0.f, 0.f, nullptr, 0);
    }
    // result in P.Z after 6 iterations
    // 7. a1 = softmax(Q @ KL^T)   (15360 x 256 x 64, NT, batched)
    gemm_big<true><<<big_grid(NPAD, NL, HEADS), 256>>>(
        P.Q, P.KL, P.A1, NPAD, NL, DH, DH, DH, NL,
        (long)NPAD*DH, (long)NL*DH, (long)NPAD*NL, nullptr, 0);
    softmax_rows<<<HEADS*NPAD, 128>>>(P.A1, NL);
    // 8. a3 = softmax(QL @ K^T)   (256 x 15360 x 64, NT, batched)
    gemm_big<true><<<big_grid(NL, NPAD, HEADS), 256>>>(
        P.QL, P.K, P.A3, NL, NPAD, DH, DH, DH, NPAD,
        (long)NL*DH, (long)NPAD*DH, (long)NL*NPAD, nullptr, 0);
    softmax_rows<<<HEADS*NL, 256>>>(P.A3, NPAD);
    // 9. T = a3 @ V  (split-K)
    zero_kernel<<<(HEADS*NL*DH + 255)/256, 256>>>(P.T, (long)HEADS*NL*DH);
    gemm_splitk<<<dim3(1, (NL+BM-1)/BM, HEADS*NSPLIT), 256>>>(
        P.A3, P.V, P.T, NL, DH, NPAD, NPAD, DH, DH,
        (long)NL*NPAD, (long)NPAD*DH, (long)NL*DH);
    // 10. U = a2_inv @ T
    gemm_tile<false><<<gemm_grid(NL, DH, HEADS), 256>>>(
        P.Z, P.T, P.U, NL, DH, NL, NL, DH, DH,
        sQ, (long)NL*DH, (long)NL*DH, 1.f, 0.f, 0.f, nullptr, 0);
    // 11. attn = a1 @ U  (written head-interleaved into [NPAD][512])
    gemm_tile<false><<<gemm_grid(NPAD, DH, HEADS), 256>>>(
        P.A1, P.U, P.attn, NPAD, DH, NL, NL, DH, DIM,
        (long)NPAD*NL, (long)NL*DH, (long)DH, 1.f, 0.f, 0.f, nullptr, 0);
    // 12. residual depthwise conv (k=33) on V, added in
    res_conv_add<<<NPAD, DIM>>>(P.attn, P.V, resw);
    // 13. out projection + bias  (15360 x 512 x 512)
    gemm_big<false><<<big_grid(NPAD, DIM, 1), 256>>>(
        P.attn, Wout, P.y, NPAD, DIM, DIM, DIM, DIM, DIM,
        0, 0, 0, bout, 0);
    // 14. h += y[last NTOK rows]
    add_tail<<<(NTOK*DIM + 255)/256, 256>>>(P.h, P.y);
}

extern "C" void kernel_launch(void* const* d_in, const int* in_sizes, int n_in,
                              void* d_out, int out_size)
{
    const float* data      = (const float*)d_in[0];
    const float* W_fc1     = (const float*)d_in[1];
    const float* b_fc1     = (const float*)d_in[2];
    const float* cls_token = (const float*)d_in[3];
    const float* ln1_g     = (const float*)d_in[4];
    const float* ln1_b     = (const float*)d_in[5];
    const float* qkv1      = (const float*)d_in[6];
    const float* out1_w    = (const float*)d_in[7];
    const float* out1_b    = (const float*)d_in[8];
    const float* res1      = (const float*)d_in[9];
    const float* w7        = (const float*)d_in[10];
    const float* b7        = (const float*)d_in[11];
    const float* w5        = (const float*)d_in[12];
    const float* b5        = (const float*)d_in[13];
    const float* w3        = (const float*)d_in[14];
    const float* b3        = (const float*)d_in[15];
    const float* ln2_g     = (const float*)d_in[16];
    const float* ln2_b     = (const float*)d_in[17];
    const float* qkv2      = (const float*)d_in[18];
    const float* out2_w    = (const float*)d_in[19];
    const float* out2_b    = (const float*)d_in[20];
    const float* res2      = (const float*)d_in[21];
    const float* norm_g    = (const float*)d_in[22];
    const float* norm_b    = (const float*)d_in[23];
    const float* W_fc2     = (const float*)d_in[24];
    const float* b_fc2     = (const float*)d_in[25];

    Ptrs P;
    get_ptrs(P);

    // stage A: token assembly
    set_cls<<<1, DIM>>>(P.h, cls_token);
    // fc1: 15000 x 512 x 1024, bias + relu
    gemm_big<false><<<big_grid(15000, DIM, 1), 256>>>(
        data, W_fc1, P.h + DIM, 15000, DIM, 1024, 1024, DIM, DIM,
        0, 0, 0, b_fc1, 1);
    dup_rows<<<(129*DIM + 255)/256, 256>>>(P.h);

    // block 1
    run_attention(P, ln1_g, ln1_b, qkv1, out1_w, out1_b, res1);

    // PPEG
    ppeg_kernel<<<NPIX, DIM>>>(P.h, P.y, w7, b7, w5, b5, w3, b3);
    ppeg_copyback<<<(int)(((long)NPIX*DIM + 255)/256), 256>>>(P.h, P.y);

    // block 2
    run_attention(P, ln2_g, ln2_b, qkv2, out2_w, out2_b, res2);

    // head
    final_head<<<1, DIM>>>(P.h, norm_g, norm_b, W_fc2, b_fc2, (float*)d_out, out_size);
}

// round 3
// speedup vs baseline: 1.9456x; 1.5076x over previous
#include <cuda_runtime.h>
#include <math.h>
#include <stdint.h>

#define HEADS 8
#define DH    64
#define DIM   512
#define NTOK  15130
#define NPAD  15360
#define PADR  230
#define NL    256
#define LCH   60
#define IMGH  123
#define NPIX  15129
#define NSPLIT 16

// ---------------- static scratch (allocation-free rule) ----------------
__device__ __align__(16) float g_h   [NTOK*DIM];
__device__ __align__(16) float g_xln [NPAD*DIM];
__device__ __align__(16) float g_qkv [NPAD*3*DIM];
__device__ __align__(16) float g_Qh  [HEADS*NPAD*DH];
__device__ __align__(16) float g_Kh  [HEADS*NPAD*DH];
__device__ __align__(16) float g_Vh  [HEADS*NPAD*DH];
__device__ __align__(16) float g_QL  [HEADS*NL*DH];
__device__ __align__(16) float g_KL  [HEADS*NL*DH];
__device__ __align__(16) float g_A1  [HEADS*NPAD*NL];
__device__ __align__(16) float g_A3  [HEADS*NL*NPAD];
__device__ __align__(16) float g_S2  [HEADS*NL*NL];
__device__ __align__(16) float g_XZ  [HEADS*NL*NL];
__device__ __align__(16) float g_T1  [HEADS*NL*NL];
__device__ __align__(16) float g_T2  [HEADS*NL*NL];
__device__ __align__(16) float g_Zb  [HEADS*NL*NL];
__device__ __align__(16) float g_Z2b [HEADS*NL*NL];
__device__ __align__(16) float g_Tb  [HEADS*NL*DH];
__device__ __align__(16) float g_Ub  [HEADS*NL*DH];
__device__ __align__(16) float g_attn[NPAD*DIM];
__device__ __align__(16) float g_y   [NPAD*DIM];
__device__ float g_scal[2];

// ================= tf32 split-precision MMA GEMM =================
// D = alpha*(A@B) + beta_diag*I + gammaA*A + bias (+relu)
// Error-compensated: each operand split hi/lo in tf32, 3 MMAs -> ~fp32 accuracy.
// Constraints (honored by all call sites): K % 16 == 0, N % BN == 0,
// lda/ldb/ldc % 4 == 0, pointers 16B-aligned.
__device__ __forceinline__ uint32_t f2tf(float x) {
    uint32_t r;
    asm("cvt.rna.tf32.f32 %0, %1;" : "=r"(r) : "f"(x));
    return r;
}
__device__ __forceinline__ void mma8(float* d,
    uint32_t a0, uint32_t a1, uint32_t a2, uint32_t a3,
    uint32_t b0, uint32_t b1)
{
    asm volatile("mma.sync.aligned.m16n8k8.row.col.f32.tf32.tf32.f32 "
        "{%0,%1,%2,%3},{%4,%5,%6,%7},{%8,%9},{%0,%1,%2,%3};"
        : "+f"(d[0]), "+f"(d[1]), "+f"(d[2]), "+f"(d[3])
        : "r"(a0), "r"(a1), "r"(a2), "r"(a3), "r"(b0), "r"(b1));
}

#define PADS 4

template<int BM, int BN, int WM, int WN, bool NT, bool SPLITK>
__global__ void __launch_bounds__((BM/WM)*(BN/WN)*32)
gemm_mma(const float* __restrict__ A, const float* __restrict__ B,
         float* __restrict__ C,
         int M, int N, int K, int lda, int ldb, int ldc,
         long sA, long sB, long sC,
         float alpha, float beta_diag, float gammaA,
         const float* __restrict__ bias, int relu)
{
    constexpr int NWARP = (BM/WM)*(BN/WN);
    constexpr int T = NWARP * 32;
    constexpr int NWN = BN / WN;
    constexpr int MT = WM / 16, NTL = WN / 8;

    int z = blockIdx.z;
    int kbeg = 0, kend = K;
    if (SPLITK) {
        int batch = z / NSPLIT, split = z % NSPLIT;
        A += (long)batch * sA; B += (long)batch * sB; C += (long)batch * sC;
        int chunk = K / NSPLIT;
        kbeg = split * chunk; kend = kbeg + chunk;
    } else {
        A += (long)z * sA; B += (long)z * sB; C += (long)z * sC;
    }

    __shared__ float As[2][16][BM + PADS];
    __shared__ float Bs[2][16][BN + PADS];

    const int tid = threadIdx.x;
    const int wid = tid >> 5, lane = tid & 31;
    const int g = lane >> 2, t = lane & 3;
    const int row0 = blockIdx.y * BM;
    const int col0 = blockIdx.x * BN;
    const int wm0 = (wid / NWN) * WM;
    const int wn0 = (wid % NWN) * WN;

    float4 ra[2], rb[2];

    auto load_g = [&](int k0) {
        #pragma unroll
        for (int it = 0; it < 2; it++) {
            int i = tid + it * T;
            {
                int m = i >> 2, kq = (i & 3) * 4;
                int gm = row0 + m;
                ra[it] = make_float4(0.f, 0.f, 0.f, 0.f);
                if (gm < M) ra[it] = *(const float4*)&A[(long)gm * lda + k0 + kq];
            }
            if (!NT) {
                int kk = i / (BN / 4), nq = (i % (BN / 4)) * 4;
                rb[it] = *(const float4*)&B[(long)(k0 + kk) * ldb + col0 + nq];
            } else {
                int n = i >> 2, kq = (i & 3) * 4;
                rb[it] = *(const float4*)&B[(long)(col0 + n) * ldb + k0 + kq];
            }
        }
    };
    auto store_s = [&](int buf) {
        #pragma unroll
        for (int it = 0; it < 2; it++) {
            int i = tid + it * T;
            {
                int m = i >> 2, kq = (i & 3) * 4;
                As[buf][kq + 0][m] = ra[it].x;
                As[buf][kq + 1][m] = ra[it].y;
                As[buf][kq + 2][m] = ra[it].z;
                As[buf][kq + 3][m] = ra[it].w;
            }
            if (!NT) {
                int kk = i / (BN / 4), nq = (i % (BN / 4)) * 4;
                *(float4*)&Bs[buf][kk][nq] = rb[it];
            } else {
                int n = i >> 2, kq = (i & 3) * 4;
                Bs[buf][kq + 0][n] = rb[it].x;
                Bs[buf][kq + 1][n] = rb[it].y;
                Bs[buf][kq + 2][n] = rb[it].z;
                Bs[buf][kq + 3][n] = rb[it].w;
            }
        }
    };

    float acc[MT][NTL][4];
    #pragma unroll
    for (int i = 0; i < MT; i++)
        #pragma unroll
        for (int j = 0; j < NTL; j++)
            #pragma unroll
            for (int q = 0; q < 4; q++) acc[i][j][q] = 0.f;

    const int ntiles = (kend - kbeg) / 16;
    load_g(kbeg);
    store_s(0);
    __syncthreads();

    for (int kt = 0; kt < ntiles; kt++) {
        if (kt + 1 < ntiles) load_g(kbeg + (kt + 1) * 16);
        int buf = kt & 1;
        #pragma unroll
        for (int k8 = 0; k8 < 16; k8 += 8) {
            uint32_t Ah[MT][4], Al[MT][4], Bh[NTL][2], Bl[NTL][2];
            #pragma unroll
            for (int mt = 0; mt < MT; mt++) {
                int mb = wm0 + mt * 16 + g;
                float x0 = As[buf][k8 + t    ][mb];
                float x1 = As[buf][k8 + t    ][mb + 8];
                float x2 = As[buf][k8 + t + 4][mb];
                float x3 = As[buf][k8 + t + 4][mb + 8];
                Ah[mt][0] = f2tf(x0); Al[mt][0] = __float_as_uint(x0 - __uint_as_float(Ah[mt][0]));
                Ah[mt][1] = f2tf(x1); Al[mt][1] = __float_as_uint(x1 - __uint_as_float(Ah[mt][1]));
                Ah[mt][2] = f2tf(x2); Al[mt][2] = __float_as_uint(x2 - __uint_as_float(Ah[mt][2]));
                Ah[mt][3] = f2tf(x3); Al[mt][3] = __float_as_uint(x3 - __uint_as_float(Ah[mt][3]));
            }
            #pragma unroll
            for (int nt = 0; nt < NTL; nt++) {
                int nb = wn0 + nt * 8 + g;
                float y0 = Bs[buf][k8 + t    ][nb];
                float y1 = Bs[buf][k8 + t + 4][nb];
                Bh[nt][0] = f2tf(y0); Bl[nt][0] = __float_as_uint(y0 - __uint_as_float(Bh[nt][0]));
                Bh[nt][1] = f2tf(y1); Bl[nt][1] = __float_as_uint(y1 - __uint_as_float(Bh[nt][1]));
            }
            #pragma unroll
            for (int mt = 0; mt < MT; mt++)
                #pragma unroll
                for (int nt = 0; nt < NTL; nt++) {
                    mma8(acc[mt][nt], Ah[mt][0], Ah[mt][1], Ah[mt][2], Ah[mt][3],
                         Bh[nt][0], Bh[nt][1]);
                    mma8(acc[mt][nt], Ah[mt][0], Ah[mt][1], Ah[mt][2], Ah[mt][3],
                         Bl[nt][0], Bl[nt][1]);
                    mma8(acc[mt][nt], Al[mt][0], Al[mt][1], Al[mt][2], Al[mt][3],
                         Bh[nt][0], Bh[nt][1]);
                }
        }
        if (kt + 1 < ntiles) {
            store_s((kt + 1) & 1);
            __syncthreads();
        }
    }

    // epilogue
    auto emit = [&](int r, int c, float v0, float v1) {
        if (r >= M) return;
        v0 *= alpha; v1 *= alpha;
        if (bias) { v0 += bias[c]; v1 += bias[c + 1]; }
        if (beta_diag != 0.f) {
            if (r == c)     v0 += beta_diag;
            if (r == c + 1) v1 += beta_diag;
        }
        if (gammaA != 0.f) {
            v0 += gammaA * A[(long)r * lda + c];
            v1 += gammaA * A[(long)r * lda + c + 1];
        }
        if (relu) { v0 = fmaxf(v0, 0.f); v1 = fmaxf(v1, 0.f); }
        if (SPLITK) {
            atomicAdd(&C[(long)r * ldc + c], v0);
            atomicAdd(&C[(long)r * ldc + c + 1], v1);
        } else {
            *(float2*)&C[(long)r * ldc + c] = make_float2(v0, v1);
        }
    };
    #pragma unroll
    for (int mt = 0; mt < MT; mt++)
        #pragma unroll
        for (int nt = 0; nt < NTL; nt++) {
            int r = row0 + wm0 + mt * 16 + g;
            int c = col0 + wn0 + nt * 8 + 2 * t;
            emit(r,     c, acc[mt][nt][0], acc[mt][nt][1]);
            emit(r + 8, c, acc[mt][nt][2], acc[mt][nt][3]);
        }
}

// ---------------- misc kernels ----------------
__global__ void zero_kernel(float* p, long n) {
    long i = (long)blockIdx.x * blockDim.x + threadIdx.x;
    if (i < n) p[i] = 0.f;
}

__global__ void set_cls(float* h, const float* __restrict__ cls) {
    h[threadIdx.x] = cls[threadIdx.x];   // 512 threads
}

__global__ void dup_rows(float* h) {
    int i = blockIdx.x * blockDim.x + threadIdx.x;
    if (i < 129*DIM) {
        int t = i / DIM, c = i % DIM;
        h[(long)(15001 + t)*DIM + c] = h[(long)(1 + t)*DIM + c];
    }
}

// layernorm with front zero padding: rows [0,PADR) zero, row p>=PADR = LN(h[p-PADR])
__global__ void ln_pad(const float* __restrict__ h, float* __restrict__ xo,
                       const float* __restrict__ g, const float* __restrict__ b)
{
    int row = blockIdx.x;
    float* out = xo + (long)row * DIM;
    int tid = threadIdx.x;
    if (row < PADR) {
        for (int c = tid; c < DIM; c += blockDim.x) out[c] = 0.f;
        return;
    }
    const float* x = h + (long)(row - PADR) * DIM;
    __shared__ float red[256];
    float s = 0.f;
    for (int c = tid; c < DIM; c += blockDim.x) s += x[c];
    red[tid] = s; __syncthreads();
    for (int st = blockDim.x/2; st > 0; st >>= 1) {
        if (tid < st) red[tid] += red[tid+st];
        __syncthreads();
    }
    float mu = red[0] / DIM; __syncthreads();
    float v = 0.f;
    for (int c = tid; c < DIM; c += blockDim.x) { float d = x[c]-mu; v += d*d; }
    red[tid] = v; __syncthreads();
    for (int st = blockDim.x/2; st > 0; st >>= 1) {
        if (tid < st) red[tid] += red[tid+st];
        __syncthreads();
    }
    float rstd = rsqrtf(red[0]/DIM + 1e-5f);
    for (int c = tid; c < DIM; c += blockDim.x)
        out[c] = (x[c]-mu)*rstd*g[c] + b[c];
}

__global__ void split_qkv(const float* __restrict__ qkv, float* __restrict__ Q,
                          float* __restrict__ K, float* __restrict__ V)
{
    int idx = blockIdx.x * blockDim.x + threadIdx.x;
    if (idx >= NPAD*DIM) return;
    int t = idx / DIM, c = idx % DIM;
    int h = c >> 6, d = c & 63;
    long o = ((long)h*NPAD + t)*DH + d;
    const float* row = qkv + (long)t * (3*DIM);
    Q[o] = row[c] * 0.125f;           // DIM_HEAD^-0.5 = 1/8
    K[o] = row[DIM + c];
    V[o] = row[2*DIM + c];
}

__global__ void landmarks_k(const float* __restrict__ Q, const float* __restrict__ K,
                            float* __restrict__ QL, float* __restrict__ KL)
{
    int idx = blockIdx.x * blockDim.x + threadIdx.x;
    if (idx >= HEADS*NL*DH) return;
    int h = idx / (NL*DH);
    int j = (idx / DH) % NL;
    int d = idx % DH;
    const float* qb = Q + ((long)h*NPAD + j*LCH)*DH + d;
    const float* kb = K + ((long)h*NPAD + j*LCH)*DH + d;
    float sq = 0.f, sk = 0.f;
    for (int i = 0; i < LCH; i++) { sq += qb[(long)i*DH]; sk += kb[(long)i*DH]; }
    QL[idx] = sq * (1.f/LCH);
    KL[idx] = sk * (1.f/LCH);
}

__global__ void softmax_rows(float* __restrict__ X, int cols) {
    long r = blockIdx.x;
    float* x = X + r * (long)cols;
    __shared__ float red[256];
    int tid = threadIdx.x, nt = blockDim.x;
    float mx = -1e30f;
    for (int c = tid; c < cols; c += nt) mx = fmaxf(mx, x[c]);
    red[tid] = mx; __syncthreads();
    for (int st = nt/2; st > 0; st >>= 1) {
        if (tid < st) red[tid] = fmaxf(red[tid], red[tid+st]);
        __syncthreads();
    }
    mx = red[0]; __syncthreads();
    float s = 0.f;
    for (int c = tid; c < cols; c += nt) { float e = expf(x[c]-mx); x[c] = e; s += e; }
    red[tid] = s; __syncthreads();
    for (int st = nt/2; st > 0; st >>= 1) {
        if (tid < st) red[tid] += red[tid+st];
        __syncthreads();
    }
    float inv = 1.f / red[0];
    for (int c = tid; c < cols; c += nt) x[c] *= inv;
}

__device__ __forceinline__ void atomicMaxFloatPos(float* addr, float v) {
    atomicMax((int*)addr, __float_as_int(v));   // valid for non-negative floats
}

__global__ void pinv_scalars(const float* __restrict__ A2, float* __restrict__ scal) {
    int hb = blockIdx.x;
    int h = hb / NL, i = hb % NL;
    int mode = blockIdx.y;     // 0: row-sums (col vec), 1: col-sums (row vec)
    const float* base = A2 + (long)h*NL*NL;
    float s = 0.f;
    if (mode == 0) { for (int j = threadIdx.x; j < NL; j += blockDim.x) s += fabsf(base[(long)i*NL + j]); }
    else           { for (int j = threadIdx.x; j < NL; j += blockDim.x) s += fabsf(base[(long)j*NL + i]); }
    __shared__ float red[256];
    red[threadIdx.x] = s; __syncthreads();
    for (int st = blockDim.x/2; st > 0; st >>= 1) {
        if (threadIdx.x < st) red[threadIdx.x] += red[threadIdx.x+st];
        __syncthreads();
    }
    if (threadIdx.x == 0) atomicMaxFloatPos(&scal[mode], red[0]);
}

__global__ void zinit(const float* __restrict__ A2, float* __restrict__ Z,
                      const float* __restrict__ scal)
{
    int idx = blockIdx.x * blockDim.x + threadIdx.x;
    if (idx >= HEADS*NL*NL) return;
    int h = idx / (NL*NL);
    int r = (idx / NL) % NL;
    int c = idx % NL;
    float denom = scal[0] * scal[1];
    Z[idx] = A2[(long)h*NL*NL + (long)c*NL + r] / denom;
}

// depthwise 1D conv (kernel 33) over sequence, per head, added into attn out
__global__ void res_conv_add(float* __restrict__ attn, const float* __restrict__ V,
                             const float* __restrict__ w)
{
    int t = blockIdx.x;
    int c = threadIdx.x;         // 512
    int h = c >> 6, d = c & 63;
    float s = 0.f;
    #pragma unroll
    for (int k = 0; k < 33; k++) {
        int tt = t + k - 16;
        if (tt >= 0 && tt < NPAD)
            s += w[h*33 + k] * V[((long)h*NPAD + tt)*DH + d];
    }
    attn[(long)t*DIM + c] += s;
}

__global__ void add_tail(float* __restrict__ h, const float* __restrict__ y) {
    int i = blockIdx.x * blockDim.x + threadIdx.x;
    if (i >= NTOK*DIM) return;
    int t = i / DIM, c = i % DIM;
    h[i] += y[(long)(PADR + t)*DIM + c];
}

// PPEG: conv7 + identity + conv5 + conv3, depthwise per channel, on 123x123 image
__global__ void ppeg_kernel(const float* __restrict__ h, float* __restrict__ out,
                            const float* __restrict__ w7, const float* __restrict__ b7,
                            const float* __restrict__ w5, const float* __restrict__ b5,
                            const float* __restrict__ w3, const float* __restrict__ b3)
{
    int p = blockIdx.x;          // pixel 0..15128
    int ch = threadIdx.x;        // 512
    int r = p / IMGH, c = p % IMGH;
    float acc = h[(long)(1 + p)*DIM + ch] + b7[ch] + b5[ch] + b3[ch];
    #pragma unroll
    for (int dy = -3; dy <= 3; dy++) {
        int rr = r + dy;
        if (rr < 0 || rr >= IMGH) continue;
        #pragma unroll
        for (int dx = -3; dx <= 3; dx++) {
            int cc = c + dx;
            if (cc < 0 || cc >= IMGH) continue;
            float v = h[(long)(1 + rr*IMGH + cc)*DIM + ch];
            acc += v * w7[(long)ch*49 + (dy+3)*7 + (dx+3)];
            if (dy >= -2 && dy <= 2 && dx >= -2 && dx <= 2)
                acc += v * w5[(long)ch*25 + (dy+2)*5 + (dx+2)];
            if (dy >= -1 && dy <= 1 && dx >= -1 && dx <= 1)
                acc += v * w3[(long)ch*9 + (dy+1)*3 + (dx+1)];
        }
    }
    out[(long)p*DIM + ch] = acc;
}

__global__ void ppeg_copyback(float* __restrict__ h, const float* __restrict__ y) {
    long i = (long)blockIdx.x * blockDim.x + threadIdx.x;
    if (i < (long)NPIX*DIM) h[DIM + i] = y[i];
}

// final LN(token0) -> 5 logits -> softmax -> argmax
__global__ void final_head(const float* __restrict__ h, const float* __restrict__ g,
                           const float* __restrict__ b, const float* __restrict__ W,
                           const float* __restrict__ bias, float* __restrict__ out,
                           int out_size)
{
    __shared__ float red[512];
    __shared__ float xn[512];
    int tid = threadIdx.x;       // 512
    float x = h[tid];
    red[tid] = x; __syncthreads();
    for (int st = 256; st > 0; st >>= 1) {
        if (tid < st) red[tid] += red[tid+st];
        __syncthreads();
    }
    float mu = red[0] / DIM; __syncthreads();
    float d = x - mu;
    red[tid] = d*d; __syncthreads();
    for (int st = 256; st > 0; st >>= 1) {
        if (tid < st) red[tid] += red[tid+st];
        __syncthreads();
    }
    float rstd = rsqrtf(red[0]/DIM + 1e-5f); __syncthreads();
    xn[tid] = d*rstd*g[tid] + b[tid];
    __syncthreads();
    if (tid < 5) {
        float s = bias[tid];
        for (int c = 0; c < DIM; c++) s += xn[c] * W[c*5 + tid];
        red[tid] = s;
    }
    __syncthreads();
    if (tid == 0) {
        float lg[5], mx = -1e30f;
        for (int j = 0; j < 5; j++) { lg[j] = red[j]; mx = fmaxf(mx, lg[j]); }
        float se = 0.f, pr[5];
        for (int j = 0; j < 5; j++) { pr[j] = expf(lg[j]-mx); se += pr[j]; }
        int am = 0;
        for (int j = 1; j < 5; j++) if (lg[j] > lg[am]) am = j;
        for (int j = 0; j < 5; j++) {
            if (j < out_size)     out[j]     = lg[j];
            if (5 + j < out_size) out[5 + j] = pr[j]/se;
        }
        if (10 < out_size) out[10] = (float)am;
        for (int j = 11; j < out_size; j++) out[j] = 0.f;
    }
}

// ---------------- host orchestration ----------------
struct Ptrs {
    float *h, *xln, *qkv, *Q, *K, *V, *QL, *KL, *A1, *A3;
    float *S2, *XZ, *T1, *T2, *Z, *Z2, *T, *U, *attn, *y, *scal;
};

static void get_ptrs(Ptrs& P) {
    cudaGetSymbolAddress((void**)&P.h,    g_h);
    cudaGetSymbolAddress((void**)&P.xln,  g_xln);
    cudaGetSymbolAddress((void**)&P.qkv,  g_qkv);
    cudaGetSymbolAddress((void**)&P.Q,    g_Qh);
    cudaGetSymbolAddress((void**)&P.K,    g_Kh);
    cudaGetSymbolAddress((void**)&P.V,    g_Vh);
    cudaGetSymbolAddress((void**)&P.QL,   g_QL);
    cudaGetSymbolAddress((void**)&P.KL,   g_KL);
    cudaGetSymbolAddress((void**)&P.A1,   g_A1);
    cudaGetSymbolAddress((void**)&P.A3,   g_A3);
    cudaGetSymbolAddress((void**)&P.S2,   g_S2);
    cudaGetSymbolAddress((void**)&P.XZ,   g_XZ);
    cudaGetSymbolAddress((void**)&P.T1,   g_T1);
    cudaGetSymbolAddress((void**)&P.T2,   g_T2);
    cudaGetSymbolAddress((void**)&P.Z,    g_Zb);
    cudaGetSymbolAddress((void**)&P.Z2,   g_Z2b);
    cudaGetSymbolAddress((void**)&P.T,    g_Tb);
    cudaGetSymbolAddress((void**)&P.U,    g_Ub);
    cudaGetSymbolAddress((void**)&P.attn, g_attn);
    cudaGetSymbolAddress((void**)&P.y,    g_y);
    cudaGetSymbolAddress((void**)&P.scal, g_scal);
}

// template aliases via function wrappers
#define MMA_BIG_NN  gemm_mma<128,128,64,32,false,false>
#define MMA_BIG_NT  gemm_mma<128,128,64,32,true ,false>
#define MMA_SM_NN   gemm_mma<64,64,32,32,false,false>
#define MMA_SM_NT   gemm_mma<64,64,32,32,true ,false>
#define MMA_SM_SPK  gemm_mma<64,64,32,32,false,true >

static inline dim3 grid128(int M, int N, int batch) {
    return dim3(N / 128, (M + 127) / 128, batch);
}
static inline dim3 grid64(int M, int N, int batch) {
    return dim3(N / 64, (M + 63) / 64, batch);
}

static void run_attention(const Ptrs& P, const float* lng, const float* lnb,
                          const float* Wqkv, const float* Wout, const float* bout,
                          const float* resw)
{
    const long sQhead = (long)NPAD*DH;
    const long sLnd   = (long)NL*DH;
    const long sQ     = (long)NL*NL;

    // 1. LN + front pad
    ln_pad<<<NPAD, 256>>>(P.h, P.xln, lng, lnb);
    // 2. qkv = x_ln @ Wqkv  (15360 x 1536 x 512)
    MMA_BIG_NN<<<grid128(NPAD, 3*DIM, 1), 256>>>(
        P.xln, Wqkv, P.qkv, NPAD, 3*DIM, DIM, DIM, 3*DIM, 3*DIM,
        0, 0, 0, 1.f, 0.f, 0.f, nullptr, 0);
    // 3. split heads (+ q scaling)
    split_qkv<<<(NPAD*DIM + 255)/256, 256>>>(P.qkv, P.Q, P.K, P.V);
    // 4. landmarks
    landmarks_k<<<(HEADS*NL*DH + 255)/256, 256>>>(P.Q, P.K, P.QL, P.KL);
    // 5. sim2 = QL @ KL^T, softmax  (256 x 256 x 64 x8)
    MMA_SM_NT<<<grid64(NL, NL, HEADS), 128>>>(
        P.QL, P.KL, P.S2, NL, NL, DH, DH, DH, NL,
        sLnd, sLnd, sQ, 1.f, 0.f, 0.f, nullptr, 0);
    softmax_rows<<<HEADS*NL, 256>>>(P.S2, NL);
    // 6. Moore-Penrose pinv
    zero_kernel<<<1, 32>>>(P.scal, 2);
    pinv_scalars<<<dim3(HEADS*NL, 2, 1), 256>>>(P.S2, P.scal);
    zinit<<<(HEADS*NL*NL + 255)/256, 256>>>(P.S2, P.Z, P.scal);
    for (int it = 0; it < 6; it++) {
        float* zin  = (it % 2 == 0) ? P.Z  : P.Z2;
        float* zout = (it % 2 == 0) ? P.Z2 : P.Z;
        // XZ = S2 @ zin
        MMA_SM_NN<<<grid64(NL, NL, HEADS), 128>>>(
            P.S2, zin, P.XZ, NL, NL, NL, NL, NL, NL, sQ, sQ, sQ,
            1.f, 0.f, 0.f, nullptr, 0);
        // T2 = XZ@XZ - 7*XZ + 15I
        MMA_SM_NN<<<grid64(NL, NL, HEADS), 128>>>(
            P.XZ, P.XZ, P.T2, NL, NL, NL, NL, NL, NL, sQ, sQ, sQ,
            1.f, 15.f, -7.f, nullptr, 0);
        // T1 = 13I - XZ @ T2
        MMA_SM_NN<<<grid64(NL, NL, HEADS), 128>>>(
            P.XZ, P.T2, P.T1, NL, NL, NL, NL, NL, NL, sQ, sQ, sQ,
            -1.f, 13.f, 0.f, nullptr, 0);
        // zout = 0.25 * zin @ T1
        MMA_SM_NN<<<grid64(NL, NL, HEADS), 128>>>(
            zin, P.T1, zout, NL, NL, NL, NL, NL, NL, sQ, sQ, sQ,
            0.25f, 0.f, 0.f, nullptr, 0);
    }
    // result in P.Z after 6 iterations
    // 7. a1 = softmax(Q @ KL^T)  (15360 x 256 x 64, x8)
    MMA_BIG_NT<<<grid128(NPAD, NL, HEADS), 256>>>(
        P.Q, P.KL, P.A1, NPAD, NL, DH, DH, DH, NL,
        sQhead, sLnd, (long)NPAD*NL, 1.f, 0.f, 0.f, nullptr, 0);
    softmax_rows<<<HEADS*NPAD, 128>>>(P.A1, NL);
    // 8. a3 = softmax(QL @ K^T)  (256 x 15360 x 64, x8)
    MMA_BIG_NT<<<grid128(NL, NPAD, HEADS), 256>>>(
        P.QL, P.K, P.A3, NL, NPAD, DH, DH, DH, NPAD,
        sLnd, sQhead, (long)NL*NPAD, 1.f, 0.f, 0.f, nullptr, 0);
    softmax_rows<<<HEADS*NL, 256>>>(P.A3, NPAD);
    // 9. T = a3 @ V  (split-K mma)
    zero_kernel<<<(HEADS*NL*DH + 255)/256, 256>>>(P.T, (long)HEADS*NL*DH);
    MMA_SM_SPK<<<grid64(NL, DH, HEADS*NSPLIT), 128>>>(
        P.A3, P.V, P.T, NL, DH, NPAD, NPAD, DH, DH,
        (long)NL*NPAD, sQhead, sLnd, 1.f, 0.f, 0.f, nullptr, 0);
    // 10. U = a2_inv @ T  (256 x 64 x 256, x8)
    MMA_SM_NN<<<grid64(NL, DH, HEADS), 128>>>(
        P.Z, P.T, P.U, NL, DH, NL, NL, DH, DH,
        sQ, sLnd, sLnd, 1.f, 0.f, 0.f, nullptr, 0);
    // 11. attn = a1 @ U  (15360 x 64 x 256, x8, head-interleaved out)
    MMA_SM_NN<<<grid64(NPAD, DH, HEADS), 128>>>(
        P.A1, P.U, P.attn, NPAD, DH, NL, NL, DH, DIM,
        (long)NPAD*NL, sLnd, (long)DH, 1.f, 0.f, 0.f, nullptr, 0);
    // 12. residual depthwise conv (k=33) on V, added in
    res_conv_add<<<NPAD, DIM>>>(P.attn, P.V, resw);
    // 13. out projection + bias  (15360 x 512 x 512)
    MMA_BIG_NN<<<grid128(NPAD, DIM, 1), 256>>>(
        P.attn, Wout, P.y, NPAD, DIM, DIM, DIM, DIM, DIM,
        0, 0, 0, 1.f, 0.f, 0.f, bout, 0);
    // 14. h += y[last NTOK rows]
    add_tail<<<(NTOK*DIM + 255)/256, 256>>>(P.h, P.y);
}

extern "C" void kernel_launch(void* const* d_in, const int* in_sizes, int n_in,
                              void* d_out, int out_size)
{
    const float* data      = (const float*)d_in[0];
    const float* W_fc1     = (const float*)d_in[1];
    const float* b_fc1     = (const float*)d_in[2];
    const float* cls_token = (const float*)d_in[3];
    const float* ln1_g     = (const float*)d_in[4];
    const float* ln1_b     = (const float*)d_in[5];
    const float* qkv1      = (const float*)d_in[6];
    const float* out1_w    = (const float*)d_in[7];
    const float* out1_b    = (const float*)d_in[8];
    const float* res1      = (const float*)d_in[9];
    const float* w7        = (const float*)d_in[10];
    const float* b7        = (const float*)d_in[11];
    const float* w5        = (const float*)d_in[12];
    const float* b5        = (const float*)d_in[13];
    const float* w3        = (const float*)d_in[14];
    const float* b3        = (const float*)d_in[15];
    const float* ln2_g     = (const float*)d_in[16];
    const float* ln2_b     = (const float*)d_in[17];
    const float* qkv2      = (const float*)d_in[18];
    const float* out2_w    = (const float*)d_in[19];
    const float* out2_b    = (const float*)d_in[20];
    const float* res2      = (const float*)d_in[21];
    const float* norm_g    = (const float*)d_in[22];
    const float* norm_b    = (const float*)d_in[23];
    const float* W_fc2     = (const float*)d_in[24];
    const float* b_fc2     = (const float*)d_in[25];

    Ptrs P;
    get_ptrs(P);

    // stage A: token assembly
    set_cls<<<1, DIM>>>(P.h, cls_token);
    // fc1: 15000 x 512 x 1024, bias + relu
    MMA_BIG_NN<<<grid128(15000, DIM, 1), 256>>>(
        data, W_fc1, P.h + DIM, 15000, DIM, 1024, 1024, DIM, DIM,
        0, 0, 0, 1.f, 0.f, 0.f, b_fc1, 1);
    dup_rows<<<(129*DIM + 255)/256, 256>>>(P.h);

    // block 1
    run_attention(P, ln1_g, ln1_b, qkv1, out1_w, out1_b, res1);

    // PPEG
    ppeg_kernel<<<NPIX, DIM>>>(P.h, P.y, w7, b7, w5, b5, w3, b3);
    ppeg_copyback<<<(int)(((long)NPIX*DIM + 255)/256), 256>>>(P.h, P.y);

    // block 2
    run_attention(P, ln2_g, ln2_b, qkv2, out2_w, out2_b, res2);

    // head
    final_head<<<1, DIM>>>(P.h, norm_g, norm_b, W_fc2, b_fc2, (float*)d_out, out_size);
}

// round 4
// speedup vs baseline: 2.5082x; 1.2892x over previous
#include <cuda_runtime.h>
#include <math.h>
#include <stdint.h>

#define HEADS 8
#define DH    64
#define DIM   512
#define QKVD  1536
#define NTOK  15130
#define NPAD  15360
#define PADR  230
#define NL    256
#define LCH   60
#define IMGH  123
#define NPIX  15129
#define NSPLIT 16

// ---------------- static scratch (allocation-free rule) ----------------
__device__ __align__(16) float g_h   [NTOK*DIM];
__device__ __align__(16) float g_xln [NPAD*DIM];
__device__ __align__(16) float g_qkv [NPAD*3*DIM];
__device__ __align__(16) float g_QL  [HEADS*NL*DH];
__device__ __align__(16) float g_KL  [HEADS*NL*DH];
__device__ __align__(16) float g_A1  [HEADS*NPAD*NL];
__device__ __align__(16) float g_A3  [HEADS*NL*NPAD];
__device__ __align__(16) float g_S2  [HEADS*NL*NL];
__device__ __align__(16) float g_XZ  [HEADS*NL*NL];
__device__ __align__(16) float g_T1  [HEADS*NL*NL];
__device__ __align__(16) float g_T2  [HEADS*NL*NL];
__device__ __align__(16) float g_Zb  [HEADS*NL*NL];
__device__ __align__(16) float g_Z2b [HEADS*NL*NL];
__device__ __align__(16) float g_Tb  [HEADS*NL*DH];
__device__ __align__(16) float g_Ub  [HEADS*NL*DH];
__device__ __align__(16) float g_attn[NPAD*DIM];
__device__ __align__(16) float g_y   [NPAD*DIM];
__device__ float g_scal[2];

// ================= tf32 split-precision MMA GEMM =================
__device__ __forceinline__ uint32_t f2tf(float x) {
    uint32_t r;
    asm("cvt.rna.tf32.f32 %0, %1;" : "=r"(r) : "f"(x));
    return r;
}
__device__ __forceinline__ void mma8(float* d,
    uint32_t a0, uint32_t a1, uint32_t a2, uint32_t a3,
    uint32_t b0, uint32_t b1)
{
    asm volatile("mma.sync.aligned.m16n8k8.row.col.f32.tf32.tf32.f32 "
        "{%0,%1,%2,%3},{%4,%5,%6,%7},{%8,%9},{%0,%1,%2,%3};"
        : "+f"(d[0]), "+f"(d[1]), "+f"(d[2]), "+f"(d[3])
        : "r"(a0), "r"(a1), "r"(a2), "r"(a3), "r"(b0), "r"(b1));
}

#define PADS 4

template<int BM, int BN, int WM, int WN, bool NT, bool SPLITK>
__global__ void __launch_bounds__((BM/WM)*(BN/WN)*32)
gemm_mma(const float* __restrict__ A, const float* __restrict__ B,
         float* __restrict__ C,
         int M, int N, int K, int lda, int ldb, int ldc,
         long sA, long sB, long sC,
         float alpha, float beta_diag, float gammaA,
         const float* __restrict__ bias, int relu)
{
    constexpr int NWARP = (BM/WM)*(BN/WN);
    constexpr int T = NWARP * 32;
    constexpr int NWN = BN / WN;
    constexpr int MT = WM / 16, NTL = WN / 8;

    int z = blockIdx.z;
    int kbeg = 0, kend = K;
    if (SPLITK) {
        int batch = z / NSPLIT, split = z % NSPLIT;
        A += (long)batch * sA; B += (long)batch * sB; C += (long)batch * sC;
        int chunk = K / NSPLIT;
        kbeg = split * chunk; kend = kbeg + chunk;
    } else {
        A += (long)z * sA; B += (long)z * sB; C += (long)z * sC;
    }

    __shared__ float As[2][16][BM + PADS];
    __shared__ float Bs[2][16][BN + PADS];

    const int tid = threadIdx.x;
    const int wid = tid >> 5, lane = tid & 31;
    const int g = lane >> 2, t = lane & 3;
    const int row0 = blockIdx.y * BM;
    const int col0 = blockIdx.x * BN;
    const int wm0 = (wid / NWN) * WM;
    const int wn0 = (wid % NWN) * WN;

    float4 ra[2], rb[2];

    auto load_g = [&](int k0) {
        #pragma unroll
        for (int it = 0; it < 2; it++) {
            int i = tid + it * T;
            {
                int m = i >> 2, kq = (i & 3) * 4;
                int gm = row0 + m;
                ra[it] = make_float4(0.f, 0.f, 0.f, 0.f);
                if (gm < M) ra[it] = *(const float4*)&A[(long)gm * lda + k0 + kq];
            }
            if (!NT) {
                int kk = i / (BN / 4), nq = (i % (BN / 4)) * 4;
                rb[it] = *(const float4*)&B[(long)(k0 + kk) * ldb + col0 + nq];
            } else {
                int n = i >> 2, kq = (i & 3) * 4;
                rb[it] = *(const float4*)&B[(long)(col0 + n) * ldb + k0 + kq];
            }
        }
    };
    auto store_s = [&](int buf) {
        #pragma unroll
        for (int it = 0; it < 2; it++) {
            int i = tid + it * T;
            {
                int m = i >> 2, kq = (i & 3) * 4;
                As[buf][kq + 0][m] = ra[it].x;
                As[buf][kq + 1][m] = ra[it].y;
                As[buf][kq + 2][m] = ra[it].z;
                As[buf][kq + 3][m] = ra[it].w;
            }
            if (!NT) {
                int kk = i / (BN / 4), nq = (i % (BN / 4)) * 4;
                *(float4*)&Bs[buf][kk][nq] = rb[it];
            } else {
                int n = i >> 2, kq = (i & 3) * 4;
                Bs[buf][kq + 0][n] = rb[it].x;
                Bs[buf][kq + 1][n] = rb[it].y;
                Bs[buf][kq + 2][n] = rb[it].z;
                Bs[buf][kq + 3][n] = rb[it].w;
            }
        }
    };

    float acc[MT][NTL][4];
    #pragma unroll
    for (int i = 0; i < MT; i++)
        #pragma unroll
        for (int j = 0; j < NTL; j++)
            #pragma unroll
            for (int q = 0; q < 4; q++) acc[i][j][q] = 0.f;

    const int ntiles = (kend - kbeg) / 16;
    load_g(kbeg);
    store_s(0);
    __syncthreads();

    for (int kt = 0; kt < ntiles; kt++) {
        if (kt + 1 < ntiles) load_g(kbeg + (kt + 1) * 16);
        int buf = kt & 1;
        #pragma unroll
        for (int k8 = 0; k8 < 16; k8 += 8) {
            uint32_t Ah[MT][4], Al[MT][4], Bh[NTL][2], Bl[NTL][2];
            #pragma unroll
            for (int mt = 0; mt < MT; mt++) {
                int mb = wm0 + mt * 16 + g;
                float x0 = As[buf][k8 + t    ][mb];
                float x1 = As[buf][k8 + t    ][mb + 8];
                float x2 = As[buf][k8 + t + 4][mb];
                float x3 = As[buf][k8 + t + 4][mb + 8];
                Ah[mt][0] = f2tf(x0); Al[mt][0] = __float_as_uint(x0 - __uint_as_float(Ah[mt][0]));
                Ah[mt][1] = f2tf(x1); Al[mt][1] = __float_as_uint(x1 - __uint_as_float(Ah[mt][1]));
                Ah[mt][2] = f2tf(x2); Al[mt][2] = __float_as_uint(x2 - __uint_as_float(Ah[mt][2]));
                Ah[mt][3] = f2tf(x3); Al[mt][3] = __float_as_uint(x3 - __uint_as_float(Ah[mt][3]));
            }
            #pragma unroll
            for (int nt = 0; nt < NTL; nt++) {
                int nb = wn0 + nt * 8 + g;
                float y0 = Bs[buf][k8 + t    ][nb];
                float y1 = Bs[buf][k8 + t + 4][nb];
                Bh[nt][0] = f2tf(y0); Bl[nt][0] = __float_as_uint(y0 - __uint_as_float(Bh[nt][0]));
                Bh[nt][1] = f2tf(y1); Bl[nt][1] = __float_as_uint(y1 - __uint_as_float(Bh[nt][1]));
            }
            #pragma unroll
            for (int mt = 0; mt < MT; mt++)
                #pragma unroll
                for (int nt = 0; nt < NTL; nt++) {
                    mma8(acc[mt][nt], Ah[mt][0], Ah[mt][1], Ah[mt][2], Ah[mt][3],
                         Bh[nt][0], Bh[nt][1]);
                    mma8(acc[mt][nt], Ah[mt][0], Ah[mt][1], Ah[mt][2], Ah[mt][3],
                         Bl[nt][0], Bl[nt][1]);
                    mma8(acc[mt][nt], Al[mt][0], Al[mt][1], Al[mt][2], Al[mt][3],
                         Bh[nt][0], Bh[nt][1]);
                }
        }
        if (kt + 1 < ntiles) {
            store_s((kt + 1) & 1);
            __syncthreads();
        }
    }

    auto emit = [&](int r, int c, float v0, float v1) {
        if (r >= M) return;
        v0 *= alpha; v1 *= alpha;
        if (bias) { v0 += bias[c]; v1 += bias[c + 1]; }
        if (beta_diag != 0.f) {
            if (r == c)     v0 += beta_diag;
            if (r == c + 1) v1 += beta_diag;
        }
        if (gammaA != 0.f) {
            v0 += gammaA * A[(long)r * lda + c];
            v1 += gammaA * A[(long)r * lda + c + 1];
        }
        if (relu) { v0 = fmaxf(v0, 0.f); v1 = fmaxf(v1, 0.f); }
        if (SPLITK) {
            atomicAdd(&C[(long)r * ldc + c], v0);
            atomicAdd(&C[(long)r * ldc + c + 1], v1);
        } else {
            *(float2*)&C[(long)r * ldc + c] = make_float2(v0, v1);
        }
    };
    #pragma unroll
    for (int mt = 0; mt < MT; mt++)
        #pragma unroll
        for (int nt = 0; nt < NTL; nt++) {
            int r = row0 + wm0 + mt * 16 + g;
            int c = col0 + wn0 + nt * 8 + 2 * t;
            emit(r,     c, acc[mt][nt][0], acc[mt][nt][1]);
            emit(r + 8, c, acc[mt][nt][2], acc[mt][nt][3]);
        }
}

// ---------------- misc kernels ----------------
__global__ void zero_kernel(float* p, long n) {
    long i = (long)blockIdx.x * blockDim.x + threadIdx.x;
    if (i < n) p[i] = 0.f;
}

__global__ void set_cls(float* h, const float* __restrict__ cls) {
    h[threadIdx.x] = cls[threadIdx.x];   // 512 threads
}

__global__ void dup_rows(float* h) {
    int i = blockIdx.x * blockDim.x + threadIdx.x;
    if (i < 129*DIM) {
        int t = i / DIM, c = i % DIM;
        h[(long)(15001 + t)*DIM + c] = h[(long)(1 + t)*DIM + c];
    }
}

// layernorm, single global read (register-cached), warp-shuffle reductions.
// rows [0,PADR) zeroed; row p>=PADR = LN(h[p-PADR]). 256 threads, float2 each.
__global__ void __launch_bounds__(256) ln_pad(
    const float* __restrict__ h, float* __restrict__ xo,
    const float* __restrict__ g, const float* __restrict__ b)
{
    int row = blockIdx.x, tid = threadIdx.x;
    float2* out2 = (float2*)(xo + (long)row * DIM);
    if (row < PADR) { out2[tid] = make_float2(0.f, 0.f); return; }
    const float2 xv = ((const float2*)(h + (long)(row - PADR) * DIM))[tid];
    __shared__ float sm1[8], sm2[8];
    float s = xv.x + xv.y;
    #pragma unroll
    for (int o = 16; o; o >>= 1) s += __shfl_xor_sync(~0u, s, o);
    if ((tid & 31) == 0) sm1[tid >> 5] = s;
    __syncthreads();
    float mu = (sm1[0]+sm1[1]+sm1[2]+sm1[3]+sm1[4]+sm1[5]+sm1[6]+sm1[7]) * (1.f/DIM);
    float d0 = xv.x - mu, d1 = xv.y - mu;
    float v = d0*d0 + d1*d1;
    #pragma unroll
    for (int o = 16; o; o >>= 1) v += __shfl_xor_sync(~0u, v, o);
    if ((tid & 31) == 0) sm2[tid >> 5] = v;
    __syncthreads();
    float var = (sm2[0]+sm2[1]+sm2[2]+sm2[3]+sm2[4]+sm2[5]+sm2[6]+sm2[7]) * (1.f/DIM);
    float rstd = rsqrtf(var + 1e-5f);
    float2 gg = ((const float2*)g)[tid];
    float2 bb = ((const float2*)b)[tid];
    out2[tid] = make_float2(d0*rstd*gg.x + bb.x, d1*rstd*gg.y + bb.y);
}

// landmarks from strided qkv views (q unscaled; scaling folded into GEMM alpha)
__global__ void landmarks_k(const float* __restrict__ qkv,
                            float* __restrict__ QL, float* __restrict__ KL)
{
    int idx = blockIdx.x * blockDim.x + threadIdx.x;
    if (idx >= HEADS*NL*DH) return;
    int h = idx / (NL*DH);
    int j = (idx / DH) % NL;
    int d = idx % DH;
    const float* qb = qkv + (long)(j*LCH)*QKVD + h*DH + d;
    const float* kb = qb + DIM;
    float sq = 0.f, sk = 0.f;
    for (int i = 0; i < LCH; i++) { sq += qb[(long)i*QKVD]; sk += kb[(long)i*QKVD]; }
    QL[idx] = sq * (1.f/LCH);
    KL[idx] = sk * (1.f/LCH);
}

// softmax over 256 cols, register-resident: 128 threads x float2
__global__ void __launch_bounds__(128) softmax256(float* __restrict__ X) {
    long r = blockIdx.x;
    float2* x = (float2*)(X + r * (long)NL);
    int tid = threadIdx.x;
    float2 v = x[tid];
    __shared__ float sm[4];
    float m = fmaxf(v.x, v.y);
    #pragma unroll
    for (int o = 16; o; o >>= 1) m = fmaxf(m, __shfl_xor_sync(~0u, m, o));
    if ((tid & 31) == 0) sm[tid >> 5] = m;
    __syncthreads();
    m = fmaxf(fmaxf(sm[0], sm[1]), fmaxf(sm[2], sm[3]));
    __syncthreads();
    v.x = expf(v.x - m); v.y = expf(v.y - m);
    float s = v.x + v.y;
    #pragma unroll
    for (int o = 16; o; o >>= 1) s += __shfl_xor_sync(~0u, s, o);
    if ((tid & 31) == 0) sm[tid >> 5] = s;
    __syncthreads();
    float inv = 1.f / (sm[0]+sm[1]+sm[2]+sm[3]);
    x[tid] = make_float2(v.x * inv, v.y * inv);
}

// softmax over 15360 cols, register-resident: 256 threads x 15 float4
__global__ void __launch_bounds__(256) softmax_wide(float* __restrict__ X) {
    long r = blockIdx.x;
    float* x = X + r * (long)NPAD;
    int tid = threadIdx.x;
    float4 v[15];
    #pragma unroll
    for (int i = 0; i < 15; i++) v[i] = *(float4*)&x[tid*4 + i*1024];
    __shared__ float sm[8];
    float m = -1e30f;
    #pragma unroll
    for (int i = 0; i < 15; i++)
        m = fmaxf(m, fmaxf(fmaxf(v[i].x, v[i].y), fmaxf(v[i].z, v[i].w)));
    #pragma unroll
    for (int o = 16; o; o >>= 1) m = fmaxf(m, __shfl_xor_sync(~0u, m, o));
    if ((tid & 31) == 0) sm[tid >> 5] = m;
    __syncthreads();
    m = fmaxf(fmaxf(fmaxf(sm[0],sm[1]),fmaxf(sm[2],sm[3])),
              fmaxf(fmaxf(sm[4],sm[5]),fmaxf(sm[6],sm[7])));
    __syncthreads();
    float s = 0.f;
    #pragma unroll
    for (int i = 0; i < 15; i++) {
        v[i].x = expf(v[i].x - m); v[i].y = expf(v[i].y - m);
        v[i].z = expf(v[i].z - m); v[i].w = expf(v[i].w - m);
        s += v[i].x + v[i].y + v[i].z + v[i].w;
    }
    #pragma unroll
    for (int o = 16; o; o >>= 1) s += __shfl_xor_sync(~0u, s, o);
    if ((tid & 31) == 0) sm[tid >> 5] = s;
    __syncthreads();
    float inv = 1.f / (sm[0]+sm[1]+sm[2]+sm[3]+sm[4]+sm[5]+sm[6]+sm[7]);
    #pragma unroll
    for (int i = 0; i < 15; i++) {
        v[i].x *= inv; v[i].y *= inv; v[i].z *= inv; v[i].w *= inv;
        *(float4*)&x[tid*4 + i*1024] = v[i];
    }
}

__device__ __forceinline__ void atomicMaxFloatPos(float* addr, float v) {
    atomicMax((int*)addr, __float_as_int(v));
}

__global__ void pinv_scalars(const float* __restrict__ A2, float* __restrict__ scal) {
    int hb = blockIdx.x;
    int h = hb / NL, i = hb % NL;
    int mode = blockIdx.y;
    const float* base = A2 + (long)h*NL*NL;
    float s = 0.f;
    if (mode == 0) { for (int j = threadIdx.x; j < NL; j += blockDim.x) s += fabsf(base[(long)i*NL + j]); }
    else           { for (int j = threadIdx.x; j < NL; j += blockDim.x) s += fabsf(base[(long)j*NL + i]); }
    __shared__ float red[256];
    red[threadIdx.x] = s; __syncthreads();
    for (int st = blockDim.x/2; st > 0; st >>= 1) {
        if (threadIdx.x < st) red[threadIdx.x] += red[threadIdx.x+st];
        __syncthreads();
    }
    if (threadIdx.x == 0) atomicMaxFloatPos(&scal[mode], red[0]);
}

__global__ void zinit(const float* __restrict__ A2, float* __restrict__ Z,
                      const float* __restrict__ scal)
{
    int idx = blockIdx.x * blockDim.x + threadIdx.x;
    if (idx >= HEADS*NL*NL) return;
    int h = idx / (NL*NL);
    int r = (idx / NL) % NL;
    int c = idx % NL;
    float denom = scal[0] * scal[1];
    Z[idx] = A2[(long)h*NL*NL + (long)c*NL + r] / denom;
}

// depthwise 1D conv (k=33) on strided V view, register-sliding window, 8 t/thread
__global__ void __launch_bounds__(512) res_conv2(
    float* __restrict__ attn, const float* __restrict__ qkv,
    const float* __restrict__ w)
{
    int t0 = blockIdx.x * 8;
    int ch = threadIdx.x;
    int h = ch >> 6;
    float wk[33];
    #pragma unroll
    for (int k = 0; k < 33; k++) wk[k] = w[h*33 + k];
    float v[40];
    #pragma unroll
    for (int j = 0; j < 40; j++) {
        int tt = t0 + j - 16;
        v[j] = (tt >= 0 && tt < NPAD) ? qkv[(long)tt*QKVD + 2*DIM + ch] : 0.f;
    }
    #pragma unroll
    for (int j = 0; j < 8; j++) {
        float s = 0.f;
        #pragma unroll
        for (int k = 0; k < 33; k++) s += wk[k] * v[j + k];
        attn[(long)(t0 + j)*DIM + ch] += s;
    }
}

__global__ void add_tail(float* __restrict__ h, const float* __restrict__ y) {
    int i = blockIdx.x * blockDim.x + threadIdx.x;
    if (i >= NTOK*DIM) return;
    int t = i / DIM, c = i % DIM;
    h[i] += y[(long)(PADR + t)*DIM + c];
}

// PPEG v2: combined 49-tap weight (w7 + padded w5 + padded w3 + identity) per
// channel in smem; 128-ch slab per block, 16 pixels per block.
#define PPP 16
__global__ void __launch_bounds__(128) ppeg2(
    const float* __restrict__ h, float* __restrict__ out,
    const float* __restrict__ w7, const float* __restrict__ b7,
    const float* __restrict__ w5, const float* __restrict__ b5,
    const float* __restrict__ w3, const float* __restrict__ b3)
{
    __shared__ float wc[49][128];
    int tid = threadIdx.x;
    int ch = blockIdx.y * 128 + tid;
    #pragma unroll
    for (int k = 0; k < 49; k++) {
        int dy = k / 7 - 3, dx = k % 7 - 3;
        float wv = w7[(long)ch*49 + k];
        if (dy >= -2 && dy <= 2 && dx >= -2 && dx <= 2)
            wv += w5[(long)ch*25 + (dy+2)*5 + (dx+2)];
        if (dy >= -1 && dy <= 1 && dx >= -1 && dx <= 1)
            wv += w3[(long)ch*9 + (dy+1)*3 + (dx+1)];
        if (k == 24) wv += 1.f;   // identity
        wc[k][tid] = wv;
    }
    float bias_c = b7[ch] + b5[ch] + b3[ch];
    __syncthreads();

    int p0 = blockIdx.x * PPP;
    #pragma unroll 1
    for (int pp = 0; pp < PPP; pp++) {
        int p = p0 + pp;
        if (p >= NPIX) break;
        int r = p / IMGH, c = p % IMGH;
        float acc = bias_c;
        if (r >= 3 && r < IMGH-3 && c >= 3 && c < IMGH-3) {
            #pragma unroll
            for (int k = 0; k < 49; k++) {
                int dy = k / 7 - 3, dx = k % 7 - 3;
                acc += h[(long)(1 + (r+dy)*IMGH + (c+dx))*DIM + ch] * wc[k][tid];
            }
        } else {
            #pragma unroll
            for (int k = 0; k < 49; k++) {
                int dy = k / 7 - 3, dx = k % 7 - 3;
                int rr = r + dy, cc = c + dx;
                if (rr >= 0 && rr < IMGH && cc >= 0 && cc < IMGH)
                    acc += h[(long)(1 + rr*IMGH + cc)*DIM + ch] * wc[k][tid];
            }
        }
        out[(long)p*DIM + ch] = acc;
    }
}

__global__ void ppeg_copyback(float* __restrict__ h, const float* __restrict__ y) {
    long i = (long)blockIdx.x * blockDim.x + threadIdx.x;
    if (i < (long)NPIX*DIM) h[DIM + i] = y[i];
}

// final LN(token0) -> 5 logits -> softmax -> argmax
__global__ void final_head(const float* __restrict__ h, const float* __restrict__ g,
                           const float* __restrict__ b, const float* __restrict__ W,
                           const float* __restrict__ bias, float* __restrict__ out,
                           int out_size)
{
    __shared__ float red[512];
    __shared__ float xn[512];
    int tid = threadIdx.x;
    float x = h[tid];
    red[tid] = x; __syncthreads();
    for (int st = 256; st > 0; st >>= 1) {
        if (tid < st) red[tid] += red[tid+st];
        __syncthreads();
    }
    float mu = red[0] / DIM; __syncthreads();
    float d = x - mu;
    red[tid] = d*d; __syncthreads();
    for (int st = 256; st > 0; st >>= 1) {
        if (tid < st) red[tid] += red[tid+st];
        __syncthreads();
    }
    float rstd = rsqrtf(red[0]/DIM + 1e-5f); __syncthreads();
    xn[tid] = d*rstd*g[tid] + b[tid];
    __syncthreads();
    if (tid < 5) {
        float s = bias[tid];
        for (int c = 0; c < DIM; c++) s += xn[c] * W[c*5 + tid];
        red[tid] = s;
    }
    __syncthreads();
    if (tid == 0) {
        float lg[5], mx = -1e30f;
        for (int j = 0; j < 5; j++) { lg[j] = red[j]; mx = fmaxf(mx, lg[j]); }
        float se = 0.f, pr[5];
        for (int j = 0; j < 5; j++) { pr[j] = expf(lg[j]-mx); se += pr[j]; }
        int am = 0;
        for (int j = 1; j < 5; j++) if (lg[j] > lg[am]) am = j;
        for (int j = 0; j < 5; j++) {
            if (j < out_size)     out[j]     = lg[j];
            if (5 + j < out_size) out[5 + j] = pr[j]/se;
        }
        if (10 < out_size) out[10] = (float)am;
        for (int j = 11; j < out_size; j++) out[j] = 0.f;
    }
}

// ---------------- host orchestration ----------------
struct Ptrs {
    float *h, *xln, *qkv, *QL, *KL, *A1, *A3;
    float *S2, *XZ, *T1, *T2, *Z, *Z2, *T, *U, *attn, *y, *scal;
};

static void get_ptrs(Ptrs& P) {
    cudaGetSymbolAddress((void**)&P.h,    g_h);
    cudaGetSymbolAddress((void**)&P.xln,  g_xln);
    cudaGetSymbolAddress((void**)&P.qkv,  g_qkv);
    cudaGetSymbolAddress((void**)&P.QL,   g_QL);
    cudaGetSymbolAddress((void**)&P.KL,   g_KL);
    cudaGetSymbolAddress((void**)&P.A1,   g_A1);
    cudaGetSymbolAddress((void**)&P.A3,   g_A3);
    cudaGetSymbolAddress((void**)&P.S2,   g_S2);
    cudaGetSymbolAddress((void**)&P.XZ,   g_XZ);
    cudaGetSymbolAddress((void**)&P.T1,   g_T1);
    cudaGetSymbolAddress((void**)&P.T2,   g_T2);
    cudaGetSymbolAddress((void**)&P.Z,    g_Zb);
    cudaGetSymbolAddress((void**)&P.Z2,   g_Z2b);
    cudaGetSymbolAddress((void**)&P.T,    g_Tb);
    cudaGetSymbolAddress((void**)&P.U,    g_Ub);
    cudaGetSymbolAddress((void**)&P.attn, g_attn);
    cudaGetSymbolAddress((void**)&P.y,    g_y);
    cudaGetSymbolAddress((void**)&P.scal, g_scal);
}

#define MMA_BIG_NN  gemm_mma<128,128,64,32,false,false>
#define MMA_BIG_NT  gemm_mma<128,128,64,32,true ,false>
#define MMA_SM_NN   gemm_mma<64,64,32,32,false,false>
#define MMA_SM_NT   gemm_mma<64,64,32,32,true ,false>
#define MMA_SM_SPK  gemm_mma<64,64,32,32,false,true >

static inline dim3 grid128(int M, int N, int batch) {
    return dim3(N / 128, (M + 127) / 128, batch);
}
static inline dim3 grid64(int M, int N, int batch) {
    return dim3(N / 64, (M + 63) / 64, batch);
}

static void run_attention(const Ptrs& P, const float* lng, const float* lnb,
                          const float* Wqkv, const float* Wout, const float* bout,
                          const float* resw)
{
    const long sLnd = (long)NL*DH;
    const long sQ   = (long)NL*NL;
    const float QS = 0.125f;   // DIM_HEAD^-0.5

    // strided head views of qkv: Q at +0, K at +512, V at +1024; head h at +h*64
    const float* Qv = P.qkv;
    const float* Kv = P.qkv + DIM;
    const float* Vv = P.qkv + 2*DIM;

    // 1. LN + front pad
    ln_pad<<<NPAD, 256>>>(P.h, P.xln, lng, lnb);
    // 2. qkv = x_ln @ Wqkv
    MMA_BIG_NN<<<grid128(NPAD, 3*DIM, 1), 256>>>(
        P.xln, Wqkv, P.qkv, NPAD, 3*DIM, DIM, DIM, 3*DIM, 3*DIM,
        0, 0, 0, 1.f, 0.f, 0.f, nullptr, 0);
    // 3. landmarks (from strided views, unscaled q)
    landmarks_k<<<(HEADS*NL*DH + 255)/256, 256>>>(P.qkv, P.QL, P.KL);
    // 4. sim2 = 0.125 * QL @ KL^T, softmax
    MMA_SM_NT<<<grid64(NL, NL, HEADS), 128>>>(
        P.QL, P.KL, P.S2, NL, NL, DH, DH, DH, NL,
        sLnd, sLnd, sQ, QS, 0.f, 0.f, nullptr, 0);
    softmax256<<<HEADS*NL, 128>>>(P.S2);
    // 5. Moore-Penrose pinv
    zero_kernel<<<1, 32>>>(P.scal, 2);
    pinv_scalars<<<dim3(HEADS*NL, 2, 1), 256>>>(P.S2, P.scal);
    zinit<<<(HEADS*NL*NL + 255)/256, 256>>>(P.S2, P.Z, P.scal);
    for (int it = 0; it < 6; it++) {
        float* zin  = (it % 2 == 0) ? P.Z  : P.Z2;
        float* zout = (it % 2 == 0) ? P.Z2 : P.Z;
        MMA_SM_NN<<<grid64(NL, NL, HEADS), 128>>>(
            P.S2, zin, P.XZ, NL, NL, NL, NL, NL, NL, sQ, sQ, sQ,
            1.f, 0.f, 0.f, nullptr, 0);
        MMA_SM_NN<<<grid64(NL, NL, HEADS), 128>>>(
            P.XZ, P.XZ, P.T2, NL, NL, NL, NL, NL, NL, sQ, sQ, sQ,
            1.f, 15.f, -7.f, nullptr, 0);
        MMA_SM_NN<<<grid64(NL, NL, HEADS), 128>>>(
            P.XZ, P.T2, P.T1, NL, NL, NL, NL, NL, NL, sQ, sQ, sQ,
            -1.f, 13.f, 0.f, nullptr, 0);
        MMA_SM_NN<<<grid64(NL, NL, HEADS), 128>>>(
            zin, P.T1, zout, NL, NL, NL, NL, NL, NL, sQ, sQ, sQ,
            0.25f, 0.f, 0.f, nullptr, 0);
    }
    // 6. a1 = softmax(0.125 * Q @ KL^T)   A strided (lda=1536, head stride 64)
    MMA_BIG_NT<<<grid128(NPAD, NL, HEADS), 256>>>(
        Qv, P.KL, P.A1, NPAD, NL, DH, QKVD, DH, NL,
        (long)DH, sLnd, (long)NPAD*NL, QS, 0.f, 0.f, nullptr, 0);
    softmax256<<<HEADS*NPAD, 128>>>(P.A1);
    // 7. a3 = softmax(0.125 * QL @ K^T)   B strided
    MMA_BIG_NT<<<grid128(NL, NPAD, HEADS), 256>>>(
        P.QL, Kv, P.A3, NL, NPAD, DH, DH, QKVD, NPAD,
        sLnd, (long)DH, (long)NL*NPAD, QS, 0.f, 0.f, nullptr, 0);
    softmax_wide<<<HEADS*NL, 256>>>(P.A3);
    // 8. T = a3 @ V  (split-K, V strided)
    zero_kernel<<<(HEADS*NL*DH + 255)/256, 256>>>(P.T, (long)HEADS*NL*DH);
    MMA_SM_SPK<<<grid64(NL, DH, HEADS*NSPLIT), 128>>>(
        P.A3, Vv, P.T, NL, DH, NPAD, NPAD, QKVD, DH,
        (long)NL*NPAD, (long)DH, sLnd, 1.f, 0.f, 0.f, nullptr, 0);
    // 9. U = a2_inv @ T
    MMA_SM_NN<<<grid64(NL, DH, HEADS), 128>>>(
        P.Z, P.T, P.U, NL, DH, NL, NL, DH, DH,
        sQ, sLnd, sLnd, 1.f, 0.f, 0.f, nullptr, 0);
    // 10. attn = a1 @ U  (head-interleaved out [NPAD][512])
    MMA_SM_NN<<<grid64(NPAD, DH, HEADS), 128>>>(
        P.A1, P.U, P.attn, NPAD, DH, NL, NL, DH, DIM,
        (long)NPAD*NL, sLnd, (long)DH, 1.f, 0.f, 0.f, nullptr, 0);
    // 11. residual depthwise conv (k=33) on V, added in
    res_conv2<<<NPAD/8, 512>>>(P.attn, P.qkv, resw);
    // 12. out projection + bias
    MMA_BIG_NN<<<grid128(NPAD, DIM, 1), 256>>>(
        P.attn, Wout, P.y, NPAD, DIM, DIM, DIM, DIM, DIM,
        0, 0, 0, 1.f, 0.f, 0.f, bout, 0);
    // 13. h += y[last NTOK rows]
    add_tail<<<(NTOK*DIM + 255)/256, 256>>>(P.h, P.y);
}

extern "C" void kernel_launch(void* const* d_in, const int* in_sizes, int n_in,
                              void* d_out, int out_size)
{
    const float* data      = (const float*)d_in[0];
    const float* W_fc1     = (const float*)d_in[1];
    const float* b_fc1     = (const float*)d_in[2];
    const float* cls_token = (const float*)d_in[3];
    const float* ln1_g     = (const float*)d_in[4];
    const float* ln1_b     = (const float*)d_in[5];
    const float* qkv1      = (const float*)d_in[6];
    const float* out1_w    = (const float*)d_in[7];
    const float* out1_b    = (const float*)d_in[8];
    const float* res1      = (const float*)d_in[9];
    const float* w7        = (const float*)d_in[10];
    const float* b7        = (const float*)d_in[11];
    const float* w5        = (const float*)d_in[12];
    const float* b5        = (const float*)d_in[13];
    const float* w3        = (const float*)d_in[14];
    const float* b3        = (const float*)d_in[15];
    const float* ln2_g     = (const float*)d_in[16];
    const float* ln2_b     = (const float*)d_in[17];
    const float* qkv2      = (const float*)d_in[18];
    const float* out2_w    = (const float*)d_in[19];
    const float* out2_b    = (const float*)d_in[20];
    const float* res2      = (const float*)d_in[21];
    const float* norm_g    = (const float*)d_in[22];
    const float* norm_b    = (const float*)d_in[23];
    const float* W_fc2     = (const float*)d_in[24];
    const float* b_fc2     = (const float*)d_in[25];

    Ptrs P;
    get_ptrs(P);

    // stage A: token assembly
    set_cls<<<1, DIM>>>(P.h, cls_token);
    MMA_BIG_NN<<<grid128(15000, DIM, 1), 256>>>(
        data, W_fc1, P.h + DIM, 15000, DIM, 1024, 1024, DIM, DIM,
        0, 0, 0, 1.f, 0.f, 0.f, b_fc1, 1);
    dup_rows<<<(129*DIM + 255)/256, 256>>>(P.h);

    // block 1
    run_attention(P, ln1_g, ln1_b, qkv1, out1_w, out1_b, res1);

    // PPEG
    ppeg2<<<dim3((NPIX + PPP - 1)/PPP, DIM/128), 128>>>(
        P.h, P.y, w7, b7, w5, b5, w3, b3);
    ppeg_copyback<<<(int)(((long)NPIX*DIM + 255)/256), 256>>>(P.h, P.y);

    // block 2
    run_attention(P, ln2_g, ln2_b, qkv2, out2_w, out2_b, res2);

    // head
    final_head<<<1, DIM>>>(P.h, norm_g, norm_b, W_fc2, b_fc2, (float*)d_out, out_size);
}

// round 5
// speedup vs baseline: 2.5412x; 1.0132x over previous
#include <cuda_runtime.h>
#include <math.h>
#include <stdint.h>

#define HEADS 8
#define DH    64
#define DIM   512
#define QKVD  1536
#define NTOK  15130
#define NPAD  15360
#define PADR  230
#define NL    256
#define LCH   60
#define IMGH  123
#define NPIX  15129
#define NSPLIT 16
#define PBLOCKS 128

// ---------------- static scratch (allocation-free rule) ----------------
__device__ __align__(16) float g_h   [NTOK*DIM];
__device__ __align__(16) float g_xln [NPAD*DIM];
__device__ __align__(16) float g_qkv [NPAD*3*DIM];
__device__ __align__(16) float g_QL  [HEADS*NL*DH];
__device__ __align__(16) float g_KL  [HEADS*NL*DH];
__device__ __align__(16) float g_A3  [HEADS*NL*NPAD];
__device__ __align__(16) float g_S2  [HEADS*NL*NL];
__device__ __align__(16) float g_XZ  [HEADS*NL*NL];
__device__ __align__(16) float g_T1  [HEADS*NL*NL];
__device__ __align__(16) float g_T2  [HEADS*NL*NL];
__device__ __align__(16) float g_Zb  [HEADS*NL*NL];
__device__ __align__(16) float g_Z2b [HEADS*NL*NL];
__device__ __align__(16) float g_Tb  [HEADS*NL*DH];
__device__ __align__(16) float g_Ub  [HEADS*NL*DH];
__device__ __align__(16) float g_attn[NPAD*DIM];
__device__ __align__(16) float g_y   [NPAD*DIM];
__device__ float g_scal[2];
__device__ unsigned g_bar_cnt = 0;
__device__ volatile unsigned g_bar_gen = 0;

// ================= tf32 split-precision MMA primitives =================
__device__ __forceinline__ uint32_t f2tf(float x) {
    uint32_t r;
    asm("cvt.rna.tf32.f32 %0, %1;" : "=r"(r) : "f"(x));
    return r;
}
__device__ __forceinline__ void mma8(float* d,
    uint32_t a0, uint32_t a1, uint32_t a2, uint32_t a3,
    uint32_t b0, uint32_t b1)
{
    asm volatile("mma.sync.aligned.m16n8k8.row.col.f32.tf32.tf32.f32 "
        "{%0,%1,%2,%3},{%4,%5,%6,%7},{%8,%9},{%0,%1,%2,%3};"
        : "+f"(d[0]), "+f"(d[1]), "+f"(d[2]), "+f"(d[3])
        : "r"(a0), "r"(a1), "r"(a2), "r"(a3), "r"(b0), "r"(b1));
}
// full split product: acc += a*b with hi/lo compensation (3 MMAs)
__device__ __forceinline__ void mma_split(float* acc,
    const uint32_t* Ah, const uint32_t* Al, const uint32_t* Bh, const uint32_t* Bl)
{
    mma8(acc, Ah[0],Ah[1],Ah[2],Ah[3], Bh[0],Bh[1]);
    mma8(acc, Ah[0],Ah[1],Ah[2],Ah[3], Bl[0],Bl[1]);
    mma8(acc, Al[0],Al[1],Al[2],Al[3], Bh[0],Bh[1]);
}
__device__ __forceinline__ void splitA(float x, uint32_t& h, uint32_t& l) {
    h = f2tf(x); l = __float_as_uint(x - __uint_as_float(h));
}

#define PADS 4

// ================= generic GEMM kernel (batched, NN/NT, split-K) =================
template<int BM, int BN, int WM, int WN, bool NT, bool SPLITK>
__global__ void __launch_bounds__((BM/WM)*(BN/WN)*32)
gemm_mma(const float* __restrict__ A, const float* __restrict__ B,
         float* __restrict__ C,
         int M, int N, int K, int lda, int ldb, int ldc,
         long sA, long sB, long sC,
         float alpha, float beta_diag, float gammaA,
         const float* __restrict__ bias, int relu)
{
    constexpr int NWARP = (BM/WM)*(BN/WN);
    constexpr int T = NWARP * 32;
    constexpr int NWN = BN / WN;
    constexpr int MT = WM / 16, NTL = WN / 8;

    int z = blockIdx.z;
    int kbeg = 0, kend = K;
    if (SPLITK) {
        int batch = z / NSPLIT, split = z % NSPLIT;
        A += (long)batch * sA; B += (long)batch * sB; C += (long)batch * sC;
        int chunk = K / NSPLIT;
        kbeg = split * chunk; kend = kbeg + chunk;
    } else {
        A += (long)z * sA; B += (long)z * sB; C += (long)z * sC;
    }

    __shared__ float As[2][16][BM + PADS];
    __shared__ float Bs[2][16][BN + PADS];

    const int tid = threadIdx.x;
    const int wid = tid >> 5, lane = tid & 31;
    const int g = lane >> 2, t = lane & 3;
    const int row0 = blockIdx.y * BM;
    const int col0 = blockIdx.x * BN;
    const int wm0 = (wid / NWN) * WM;
    const int wn0 = (wid % NWN) * WN;

    float4 ra[2], rb[2];

    auto load_g = [&](int k0) {
        #pragma unroll
        for (int it = 0; it < 2; it++) {
            int i = tid + it * T;
            {
                int m = i >> 2, kq = (i & 3) * 4;
                int gm = row0 + m;
                ra[it] = make_float4(0.f, 0.f, 0.f, 0.f);
                if (gm < M) ra[it] = *(const float4*)&A[(long)gm * lda + k0 + kq];
            }
            if (!NT) {
                int kk = i / (BN / 4), nq = (i % (BN / 4)) * 4;
                rb[it] = *(const float4*)&B[(long)(k0 + kk) * ldb + col0 + nq];
            } else {
                int n = i >> 2, kq = (i & 3) * 4;
                rb[it] = *(const float4*)&B[(long)(col0 + n) * ldb + k0 + kq];
            }
        }
    };
    auto store_s = [&](int buf) {
        #pragma unroll
        for (int it = 0; it < 2; it++) {
            int i = tid + it * T;
            {
                int m = i >> 2, kq = (i & 3) * 4;
                As[buf][kq + 0][m] = ra[it].x;
                As[buf][kq + 1][m] = ra[it].y;
                As[buf][kq + 2][m] = ra[it].z;
                As[buf][kq + 3][m] = ra[it].w;
            }
            if (!NT) {
                int kk = i / (BN / 4), nq = (i % (BN / 4)) * 4;
                *(float4*)&Bs[buf][kk][nq] = rb[it];
            } else {
                int n = i >> 2, kq = (i & 3) * 4;
                Bs[buf][kq + 0][n] = rb[it].x;
                Bs[buf][kq + 1][n] = rb[it].y;
                Bs[buf][kq + 2][n] = rb[it].z;
                Bs[buf][kq + 3][n] = rb[it].w;
            }
        }
    };

    float acc[MT][NTL][4];
    #pragma unroll
    for (int i = 0; i < MT; i++)
        #pragma unroll
        for (int j = 0; j < NTL; j++)
            #pragma unroll
            for (int q = 0; q < 4; q++) acc[i][j][q] = 0.f;

    const int ntiles = (kend - kbeg) / 16;
    load_g(kbeg);
    store_s(0);
    __syncthreads();

    for (int kt = 0; kt < ntiles; kt++) {
        if (kt + 1 < ntiles) load_g(kbeg + (kt + 1) * 16);
        int buf = kt & 1;
        #pragma unroll
        for (int k8 = 0; k8 < 16; k8 += 8) {
            uint32_t Ah[MT][4], Al[MT][4], Bh[NTL][2], Bl[NTL][2];
            #pragma unroll
            for (int mt = 0; mt < MT; mt++) {
                int mb = wm0 + mt * 16 + g;
                splitA(As[buf][k8 + t    ][mb],     Ah[mt][0], Al[mt][0]);
                splitA(As[buf][k8 + t    ][mb + 8], Ah[mt][1], Al[mt][1]);
                splitA(As[buf][k8 + t + 4][mb],     Ah[mt][2], Al[mt][2]);
                splitA(As[buf][k8 + t + 4][mb + 8], Ah[mt][3], Al[mt][3]);
            }
            #pragma unroll
            for (int nt = 0; nt < NTL; nt++) {
                int nb = wn0 + nt * 8 + g;
                splitA(Bs[buf][k8 + t    ][nb], Bh[nt][0], Bl[nt][0]);
                splitA(Bs[buf][k8 + t + 4][nb], Bh[nt][1], Bl[nt][1]);
            }
            #pragma unroll
            for (int mt = 0; mt < MT; mt++)
                #pragma unroll
                for (int nt = 0; nt < NTL; nt++)
                    mma_split(acc[mt][nt], Ah[mt], Al[mt], Bh[nt], Bl[nt]);
        }
        if (kt + 1 < ntiles) {
            store_s((kt + 1) & 1);
            __syncthreads();
        }
    }

    auto emit = [&](int r, int c, float v0, float v1) {
        if (r >= M) return;
        v0 *= alpha; v1 *= alpha;
        if (bias) { v0 += bias[c]; v1 += bias[c + 1]; }
        if (beta_diag != 0.f) {
            if (r == c)     v0 += beta_diag;
            if (r == c + 1) v1 += beta_diag;
        }
        if (gammaA != 0.f) {
            v0 += gammaA * A[(long)r * lda + c];
            v1 += gammaA * A[(long)r * lda + c + 1];
        }
        if (relu) { v0 = fmaxf(v0, 0.f); v1 = fmaxf(v1, 0.f); }
        if (SPLITK) {
            atomicAdd(&C[(long)r * ldc + c], v0);
            atomicAdd(&C[(long)r * ldc + c + 1], v1);
        } else {
            *(float2*)&C[(long)r * ldc + c] = make_float2(v0, v1);
        }
    };
    #pragma unroll
    for (int mt = 0; mt < MT; mt++)
        #pragma unroll
        for (int nt = 0; nt < NTL; nt++) {
            int r = row0 + wm0 + mt * 16 + g;
            int c = col0 + wn0 + nt * 8 + 2 * t;
            emit(r,     c, acc[mt][nt][0], acc[mt][nt][1]);
            emit(r + 8, c, acc[mt][nt][2], acc[mt][nt][3]);
        }
}

// ================= persistent pinv kernel =================
__device__ __forceinline__ void atomicMaxFloatPos(float* addr, float v) {
    atomicMax((int*)addr, __float_as_int(v));
}

__device__ __forceinline__ void gridbar() {
    __syncthreads();
    if (threadIdx.x == 0) {
        unsigned gen = g_bar_gen;
        __threadfence();
        if (atomicAdd(&g_bar_cnt, 1u) == PBLOCKS - 1) {
            g_bar_cnt = 0;
            __threadfence();
            g_bar_gen = gen + 1;
        } else {
            while (g_bar_gen == gen) { __nanosleep(64); }
        }
        __threadfence();
    }
    __syncthreads();
}

typedef float smtile[16][68];

// 64x64 tile of C = alpha*A@B + beta_diag*I + gammaA*A, A/B/C 256x256 row-major.
// 128 threads. Uses the same proven fragment mapping as gemm_mma.
__device__ __noinline__ void gemm64_dev(
    const float* __restrict__ A, const float* __restrict__ B, float* __restrict__ C,
    int row0, int col0, float alpha, float beta_diag, float gammaA,
    smtile* As, smtile* Bs)
{
    const int tid = threadIdx.x;
    const int wid = tid >> 5, lane = tid & 31;
    const int g = lane >> 2, t = lane & 3;
    const int wm0 = (wid >> 1) * 32, wn0 = (wid & 1) * 32;

    float4 ra[2], rb[2];
    auto load_g = [&](int k0) {
        #pragma unroll
        for (int it = 0; it < 2; it++) {
            int i = tid + it * 128;
            int m = i >> 2, kq = (i & 3) * 4;
            ra[it] = *(const float4*)&A[(long)(row0 + m) * 256 + k0 + kq];
            int kk = i >> 4, nq = (i & 15) * 4;
            rb[it] = *(const float4*)&B[(long)(k0 + kk) * 256 + col0 + nq];
        }
    };
    auto store_s = [&](int buf) {
        #pragma unroll
        for (int it = 0; it < 2; it++) {
            int i = tid + it * 128;
            int m = i >> 2, kq = (i & 3) * 4;
            As[buf][kq + 0][m] = ra[it].x;
            As[buf][kq + 1][m] = ra[it].y;
            As[buf][kq + 2][m] = ra[it].z;
            As[buf][kq + 3][m] = ra[it].w;
            int kk = i >> 4, nq = (i & 15) * 4;
            *(float4*)&Bs[buf][kk][nq] = rb[it];
        }
    };

    float acc[2][4][4] = {};
    load_g(0);
    store_s(0);
    __syncthreads();
    for (int kt = 0; kt < 16; kt++) {
        if (kt + 1 < 16) load_g((kt + 1) * 16);
        int buf = kt & 1;
        #pragma unroll
        for (int k8 = 0; k8 < 16; k8 += 8) {
            uint32_t Ah[2][4], Al[2][4], Bh[4][2], Bl[4][2];
            #pragma unroll
            for (int mt = 0; mt < 2; mt++) {
                int mb = wm0 + mt * 16 + g;
                splitA(As[buf][k8 + t    ][mb],     Ah[mt][0], Al[mt][0]);
                splitA(As[buf][k8 + t    ][mb + 8], Ah[mt][1], Al[mt][1]);
                splitA(As[buf][k8 + t + 4][mb],     Ah[mt][2], Al[mt][2]);
                splitA(As[buf][k8 + t + 4][mb + 8], Ah[mt][3], Al[mt][3]);
            }
            #pragma unroll
            for (int nt = 0; nt < 4; nt++) {
                int nb = wn0 + nt * 8 + g;
                splitA(Bs[buf][k8 + t    ][nb], Bh[nt][0], Bl[nt][0]);
                splitA(Bs[buf][k8 + t + 4][nb], Bh[nt][1], Bl[nt][1]);
            }
            #pragma unroll
            for (int mt = 0; mt < 2; mt++)
                #pragma unroll
                for (int nt = 0; nt < 4; nt++)
                    mma_split(acc[mt][nt], Ah[mt], Al[mt], Bh[nt], Bl[nt]);
        }
        if (kt + 1 < 16) {
            store_s((kt + 1) & 1);
            __syncthreads();
        }
    }
    #pragma unroll
    for (int mt = 0; mt < 2; mt++)
        #pragma unroll
        for (int nt = 0; nt < 4; nt++) {
            int r0 = row0 + wm0 + mt * 16 + g;
            int c = col0 + wn0 + nt * 8 + 2 * t;
            #pragma unroll
            for (int half = 0; half < 2; half++) {
                int r = r0 + half * 8;
                float v0 = alpha * acc[mt][nt][half*2 + 0];
                float v1 = alpha * acc[mt][nt][half*2 + 1];
                if (beta_diag != 0.f) {
                    if (r == c)     v0 += beta_diag;
                    if (r == c + 1) v1 += beta_diag;
                }
                if (gammaA != 0.f) {
                    v0 += gammaA * A[(long)r * 256 + c];
                    v1 += gammaA * A[(long)r * 256 + c + 1];
                }
                *(float2*)&C[(long)r * 256 + c] = make_float2(v0, v1);
            }
        }
    __syncthreads();
}

__global__ void __launch_bounds__(128) pinv_persist(
    const float* __restrict__ S2, float* __restrict__ Z, float* __restrict__ Z2,
    float* __restrict__ XZ, float* __restrict__ T1, float* __restrict__ T2,
    float* __restrict__ scal)
{
    __shared__ float As[2][16][68], Bs[2][16][68];
    const int b = blockIdx.x, tid = threadIdx.x;
    const int wid = tid >> 5, lane = tid & 31;

    if (b == 0 && tid < 2) scal[tid] = 0.f;
    gridbar();

    // scalars: 4096 reductions (2 modes x 8 heads x 256), 32 per block
    for (int q = 0; q < 8; q++) {
        int idx = b * 32 + wid * 8 + q;
        int mode = idx >> 11, rem = idx & 2047;
        int h = rem >> 8, i = rem & 255;
        const float* base = S2 + (long)h * 65536;
        float s = 0.f;
        if (mode == 0) { for (int j = lane; j < 256; j += 32) s += fabsf(base[i * 256 + j]); }
        else           { for (int j = lane; j < 256; j += 32) s += fabsf(base[j * 256 + i]); }
        #pragma unroll
        for (int o = 16; o; o >>= 1) s += __shfl_xor_sync(~0u, s, o);
        if (lane == 0) atomicMaxFloatPos(&scal[mode], s);
    }
    gridbar();

    float denom = scal[0] * scal[1];
    // zinit: Z = S2^T / denom
    for (int l = 0; l < 32; l++) {
        int idx = b * 4096 + l * 128 + tid;
        int h = idx >> 16, rc = idx & 65535, r = rc >> 8, c = rc & 255;
        Z[idx] = S2[(long)h * 65536 + (long)c * 256 + r] / denom;
    }
    gridbar();

    const int head = b >> 4, tt = b & 15;
    const int row0 = (tt >> 2) * 64, col0 = (tt & 3) * 64;
    const long ho = (long)head * 65536;

    for (int it = 0; it < 6; it++) {
        float* zin  = (it & 1) ? Z2 : Z;
        float* zout = (it & 1) ? Z  : Z2;
        gemm64_dev(S2 + ho, zin + ho, XZ + ho, row0, col0, 1.f, 0.f, 0.f, As, Bs);
        gridbar();
        gemm64_dev(XZ + ho, XZ + ho, T2 + ho, row0, col0, 1.f, 15.f, -7.f, As, Bs);
        gridbar();
        gemm64_dev(XZ + ho, T2 + ho, T1 + ho, row0, col0, -1.f, 13.f, 0.f, As, Bs);
        gridbar();
        gemm64_dev(zin + ho, T1 + ho, zout + ho, row0, col0, 0.25f, 0.f, 0.f, As, Bs);
        gridbar();
    }
}

// ================= fused a1 attention: attn = softmax(0.125 Q@KL^T) @ U =================
// grid (NPAD/64, HEADS), 128 threads, 220KB dynamic smem.
#define A1_AS1   0
#define A1_BS1   (64*68)
#define A1_ST    (A1_BS1 + 64*260)
#define A1_US    (A1_ST + 256*65)
#define A1_RINV  (A1_US + 256*68)
#define A1_SMEMF (A1_RINV + 64)
#define A1_SMEMB (A1_SMEMF*4)

__global__ void __launch_bounds__(128) attn1_fused(
    const float* __restrict__ qkv, const float* __restrict__ KL,
    const float* __restrict__ U, float* __restrict__ attn)
{
    extern __shared__ float sm[];
    float* As1 = sm + A1_AS1;    // [64][68]  (k-major Q)
    float* Bs1 = sm + A1_BS1;    // [64][260] (k-major KL^T)
    float* ST  = sm + A1_ST;     // [256][65] (landmark-major scores)
    float* Us  = sm + A1_US;     // [256][68]
    float* rinv= sm + A1_RINV;   // [64]

    const int tid = threadIdx.x;
    const int wid = tid >> 5, lane = tid & 31;
    const int g = lane >> 2, t = lane & 3;
    const int h = blockIdx.y;
    const int row0 = blockIdx.x * 64;
    const float* Qg  = qkv + h * DH;             // row stride QKVD
    const float* KLh = KL + (long)h * NL * DH;
    const float* Uh  = U  + (long)h * NL * DH;

    // loads
    #pragma unroll
    for (int l = 0; l < 8; l++) {
        int i = tid + l * 128;
        int m = i >> 4, kq = (i & 15) * 4;
        float4 v = *(const float4*)&Qg[(long)(row0 + m) * QKVD + kq];
        As1[(kq+0)*68+m] = v.x; As1[(kq+1)*68+m] = v.y;
        As1[(kq+2)*68+m] = v.z; As1[(kq+3)*68+m] = v.w;
    }
    #pragma unroll
    for (int l = 0; l < 32; l++) {
        int i = tid + l * 128;
        int n = i >> 4, kq = (i & 15) * 4;
        float4 v = *(const float4*)&KLh[n * 64 + kq];
        Bs1[(kq+0)*260+n] = v.x; Bs1[(kq+1)*260+n] = v.y;
        Bs1[(kq+2)*260+n] = v.z; Bs1[(kq+3)*260+n] = v.w;
        int k = i >> 4, nq = (i & 15) * 4;
        *(float4*)&Us[k * 68 + nq] = *(const float4*)&Uh[k * 64 + nq];
    }
    __syncthreads();

    // MMA1: S = Q@KL^T, M=64 N=256 K=64; warps 2x2: warp tile 32x128
    const int wm0 = (wid >> 1) * 32;
    const int wn1 = (wid & 1) * 128;
    {
        float acc1[2][16][4] = {};
        #pragma unroll
        for (int k8 = 0; k8 < 64; k8 += 8) {
            uint32_t Ah[2][4], Al[2][4];
            #pragma unroll
            for (int mt = 0; mt < 2; mt++) {
                int mb = wm0 + mt * 16 + g;
                splitA(As1[(k8+t  )*68 + mb],   Ah[mt][0], Al[mt][0]);
                splitA(As1[(k8+t  )*68 + mb+8], Ah[mt][1], Al[mt][1]);
                splitA(As1[(k8+t+4)*68 + mb],   Ah[mt][2], Al[mt][2]);
                splitA(As1[(k8+t+4)*68 + mb+8], Ah[mt][3], Al[mt][3]);
            }
            #pragma unroll
            for (int nt = 0; nt < 16; nt++) {
                int nb = wn1 + nt * 8 + g;
                uint32_t Bh[2], Bl[2];
                splitA(Bs1[(k8+t  )*260 + nb], Bh[0], Bl[0]);
                splitA(Bs1[(k8+t+4)*260 + nb], Bh[1], Bl[1]);
                mma_split(acc1[0][nt], Ah[0], Al[0], Bh, Bl);
                mma_split(acc1[1][nt], Ah[1], Al[1], Bh, Bl);
            }
        }
        __syncthreads();   // As1/Bs1 no longer needed (ST aliases nothing)
        #pragma unroll
        for (int mt = 0; mt < 2; mt++)
            #pragma unroll
            for (int nt = 0; nt < 16; nt++) {
                int r = wm0 + mt * 16 + g;
                int c = wn1 + nt * 8 + 2 * t;
                ST[c*65 + r]       = 0.125f * acc1[mt][nt][0];
                ST[(c+1)*65 + r]   = 0.125f * acc1[mt][nt][1];
                ST[c*65 + r+8]     = 0.125f * acc1[mt][nt][2];
                ST[(c+1)*65 + r+8] = 0.125f * acc1[mt][nt][3];
            }
    }
    __syncthreads();

    // softmax over 256 landmarks per row; normalization deferred to epilogue
    {
        int r = tid >> 1, half = tid & 1;
        int j0 = half * 128;
        float m = -1e30f;
        #pragma unroll 8
        for (int j = j0; j < j0 + 128; j++) m = fmaxf(m, ST[j*65 + r]);
        m = fmaxf(m, __shfl_xor_sync(~0u, m, 1));
        float s = 0.f;
        #pragma unroll 8
        for (int j = j0; j < j0 + 128; j++) {
            float e = expf(ST[j*65 + r] - m);
            ST[j*65 + r] = e;
            s += e;
        }
        s += __shfl_xor_sync(~0u, s, 1);
        if (half == 0) rinv[r] = 1.f / s;
    }
    __syncthreads();

    // MMA2: out = P@U, M=64 N=64 K=256; warps 2x2: warp tile 32x32
    {
        const int wn2 = (wid & 1) * 32;
        float acc2[2][4][4] = {};
        #pragma unroll 8
        for (int k8 = 0; k8 < 256; k8 += 8) {
            uint32_t Ah[2][4], Al[2][4], Bh[4][2], Bl[4][2];
            #pragma unroll
            for (int mt = 0; mt < 2; mt++) {
                int mb = wm0 + mt * 16 + g;
                splitA(ST[(k8+t  )*65 + mb],   Ah[mt][0], Al[mt][0]);
                splitA(ST[(k8+t  )*65 + mb+8], Ah[mt][1], Al[mt][1]);
                splitA(ST[(k8+t+4)*65 + mb],   Ah[mt][2], Al[mt][2]);
                splitA(ST[(k8+t+4)*65 + mb+8], Ah[mt][3], Al[mt][3]);
            }
            #pragma unroll
            for (int nt = 0; nt < 4; nt++) {
                int nb = wn2 + nt * 8 + g;
                splitA(Us[(k8+t  )*68 + nb], Bh[nt][0], Bl[nt][0]);
                splitA(Us[(k8+t+4)*68 + nb], Bh[nt][1], Bl[nt][1]);
            }
            #pragma unroll
            for (int mt = 0; mt < 2; mt++)
                #pragma unroll
                for (int nt = 0; nt < 4; nt++)
                    mma_split(acc2[mt][nt], Ah[mt], Al[mt], Bh[nt], Bl[nt]);
        }
        #pragma unroll
        for (int mt = 0; mt < 2; mt++)
            #pragma unroll
            for (int nt = 0; nt < 4; nt++) {
                int rl = wm0 + mt * 16 + g;
                int c = h * DH + wn2 + nt * 8 + 2 * t;
                float i0 = rinv[rl], i1 = rinv[rl + 8];
                *(float2*)&attn[(long)(row0 + rl) * DIM + c] =
                    make_float2(acc2[mt][nt][0] * i0, acc2[mt][nt][1] * i0);
                *(float2*)&attn[(long)(row0 + rl + 8) * DIM + c] =
                    make_float2(acc2[mt][nt][2] * i1, acc2[mt][nt][3] * i1);
            }
    }
}

// ---------------- misc kernels ----------------
__global__ void zero_kernel(float* p, long n) {
    long i = (long)blockIdx.x * blockDim.x + threadIdx.x;
    if (i < n) p[i] = 0.f;
}

__global__ void set_cls(float* h, const float* __restrict__ cls) {
    h[threadIdx.x] = cls[threadIdx.x];
}

__global__ void dup_rows(float* h) {
    int i = blockIdx.x * blockDim.x + threadIdx.x;
    if (i < 129*DIM) {
        int t = i / DIM, c = i % DIM;
        h[(long)(15001 + t)*DIM + c] = h[(long)(1 + t)*DIM + c];
    }
}

__global__ void __launch_bounds__(256) ln_pad(
    const float* __restrict__ h, float* __restrict__ xo,
    const float* __restrict__ g, const float* __restrict__ b)
{
    int row = blockIdx.x, tid = threadIdx.x;
    float2* out2 = (float2*)(xo + (long)row * DIM);
    if (row < PADR) { out2[tid] = make_float2(0.f, 0.f); return; }
    const float2 xv = ((const float2*)(h + (long)(row - PADR) * DIM))[tid];
    __shared__ float sm1[8], sm2[8];
    float s = xv.x + xv.y;
    #pragma unroll
    for (int o = 16; o; o >>= 1) s += __shfl_xor_sync(~0u, s, o);
    if ((tid & 31) == 0) sm1[tid >> 5] = s;
    __syncthreads();
    float mu = (sm1[0]+sm1[1]+sm1[2]+sm1[3]+sm1[4]+sm1[5]+sm1[6]+sm1[7]) * (1.f/DIM);
    float d0 = xv.x - mu, d1 = xv.y - mu;
    float v = d0*d0 + d1*d1;
    #pragma unroll
    for (int o = 16; o; o >>= 1) v += __shfl_xor_sync(~0u, v, o);
    if ((tid & 31) == 0) sm2[tid >> 5] = v;
    __syncthreads();
    float var = (sm2[0]+sm2[1]+sm2[2]+sm2[3]+sm2[4]+sm2[5]+sm2[6]+sm2[7]) * (1.f/DIM);
    float rstd = rsqrtf(var + 1e-5f);
    float2 gg = ((const float2*)g)[tid];
    float2 bb = ((const float2*)b)[tid];
    out2[tid] = make_float2(d0*rstd*gg.x + bb.x, d1*rstd*gg.y + bb.y);
}

__global__ void landmarks_k(const float* __restrict__ qkv,
                            float* __restrict__ QL, float* __restrict__ KL)
{
    int idx = blockIdx.x * blockDim.x + threadIdx.x;
    if (idx >= HEADS*NL*DH) return;
    int h = idx / (NL*DH);
    int j = (idx / DH) % NL;
    int d = idx % DH;
    const float* qb = qkv + (long)(j*LCH)*QKVD + h*DH + d;
    const float* kb = qb + DIM;
    float sq = 0.f, sk = 0.f;
    for (int i = 0; i < LCH; i++) { sq += qb[(long)i*QKVD]; sk += kb[(long)i*QKVD]; }
    QL[idx] = sq * (1.f/LCH);
    KL[idx] = sk * (1.f/LCH);
}

__global__ void __launch_bounds__(128) softmax256(float* __restrict__ X) {
    long r = blockIdx.x;
    float2* x = (float2*)(X + r * (long)NL);
    int tid = threadIdx.x;
    float2 v = x[tid];
    __shared__ float sm[4];
    float m = fmaxf(v.x, v.y);
    #pragma unroll
    for (int o = 16; o; o >>= 1) m = fmaxf(m, __shfl_xor_sync(~0u, m, o));
    if ((tid & 31) == 0) sm[tid >> 5] = m;
    __syncthreads();
    m = fmaxf(fmaxf(sm[0], sm[1]), fmaxf(sm[2], sm[3]));
    __syncthreads();
    v.x = expf(v.x - m); v.y = expf(v.y - m);
    float s = v.x + v.y;
    #pragma unroll
    for (int o = 16; o; o >>= 1) s += __shfl_xor_sync(~0u, s, o);
    if ((tid & 31) == 0) sm[tid >> 5] = s;
    __syncthreads();
    float inv = 1.f / (sm[0]+sm[1]+sm[2]+sm[3]);
    x[tid] = make_float2(v.x * inv, v.y * inv);
}

__global__ void __launch_bounds__(256) softmax_wide(float* __restrict__ X) {
    long r = blockIdx.x;
    float* x = X + r * (long)NPAD;
    int tid = threadIdx.x;
    float4 v[15];
    #pragma unroll
    for (int i = 0; i < 15; i++) v[i] = *(float4*)&x[tid*4 + i*1024];
    __shared__ float sm[8];
    float m = -1e30f;
    #pragma unroll
    for (int i = 0; i < 15; i++)
        m = fmaxf(m, fmaxf(fmaxf(v[i].x, v[i].y), fmaxf(v[i].z, v[i].w)));
    #pragma unroll
    for (int o = 16; o; o >>= 1) m = fmaxf(m, __shfl_xor_sync(~0u, m, o));
    if ((tid & 31) == 0) sm[tid >> 5] = m;
    __syncthreads();
    m = fmaxf(fmaxf(fmaxf(sm[0],sm[1]),fmaxf(sm[2],sm[3])),
              fmaxf(fmaxf(sm[4],sm[5]),fmaxf(sm[6],sm[7])));
    __syncthreads();
    float s = 0.f;
    #pragma unroll
    for (int i = 0; i < 15; i++) {
        v[i].x = expf(v[i].x - m); v[i].y = expf(v[i].y - m);
        v[i].z = expf(v[i].z - m); v[i].w = expf(v[i].w - m);
        s += v[i].x + v[i].y + v[i].z + v[i].w;
    }
    #pragma unroll
    for (int o = 16; o; o >>= 1) s += __shfl_xor_sync(~0u, s, o);
    if ((tid & 31) == 0) sm[tid >> 5] = s;
    __syncthreads();
    float inv = 1.f / (sm[0]+sm[1]+sm[2]+sm[3]+sm[4]+sm[5]+sm[6]+sm[7]);
    #pragma unroll
    for (int i = 0; i < 15; i++) {
        v[i].x *= inv; v[i].y *= inv; v[i].z *= inv; v[i].w *= inv;
        *(float4*)&x[tid*4 + i*1024] = v[i];
    }
}

__global__ void __launch_bounds__(512) res_conv2(
    float* __restrict__ attn, const float* __restrict__ qkv,
    const float* __restrict__ w)
{
    int t0 = blockIdx.x * 8;
    int ch = threadIdx.x;
    int h = ch >> 6;
    float wk[33];
    #pragma unroll
    for (int k = 0; k < 33; k++) wk[k] = w[h*33 + k];
    float v[40];
    #pragma unroll
    for (int j = 0; j < 40; j++) {
        int tt = t0 + j - 16;
        v[j] = (tt >= 0 && tt < NPAD) ? qkv[(long)tt*QKVD + 2*DIM + ch] : 0.f;
    }
    #pragma unroll
    for (int j = 0; j < 8; j++) {
        float s = 0.f;
        #pragma unroll
        for (int k = 0; k < 33; k++) s += wk[k] * v[j + k];
        attn[(long)(t0 + j)*DIM + ch] += s;
    }
}

__global__ void add_tail(float* __restrict__ h, const float* __restrict__ y) {
    int i = blockIdx.x * blockDim.x + threadIdx.x;
    if (i >= NTOK*DIM) return;
    int t = i / DIM, c = i % DIM;
    h[i] += y[(long)(PADR + t)*DIM + c];
}

#define PPP 16
__global__ void __launch_bounds__(128) ppeg2(
    const float* __restrict__ h, float* __restrict__ out,
    const float* __restrict__ w7, const float* __restrict__ b7,
    const float* __restrict__ w5, const float* __restrict__ b5,
    const float* __restrict__ w3, const float* __restrict__ b3)
{
    __shared__ float wc[49][128];
    int tid = threadIdx.x;
    int ch = blockIdx.y * 128 + tid;
    #pragma unroll
    for (int k = 0; k < 49; k++) {
        int dy = k / 7 - 3, dx = k % 7 - 3;
        float wv = w7[(long)ch*49 + k];
        if (dy >= -2 && dy <= 2 && dx >= -2 && dx <= 2)
            wv += w5[(long)ch*25 + (dy+2)*5 + (dx+2)];
        if (dy >= -1 && dy <= 1 && dx >= -1 && dx <= 1)
            wv += w3[(long)ch*9 + (dy+1)*3 + (dx+1)];
        if (k == 24) wv += 1.f;
        wc[k][tid] = wv;
    }
    float bias_c = b7[ch] + b5[ch] + b3[ch];
    __syncthreads();

    int p0 = blockIdx.x * PPP;
    #pragma unroll 1
    for (int pp = 0; pp < PPP; pp++) {
        int p = p0 + pp;
        if (p >= NPIX) break;
        int r = p / IMGH, c = p % IMGH;
        float acc = bias_c;
        if (r >= 3 && r < IMGH-3 && c >= 3 && c < IMGH-3) {
            #pragma unroll
            for (int k = 0; k < 49; k++) {
                int dy = k / 7 - 3, dx = k % 7 - 3;
                acc += h[(long)(1 + (r+dy)*IMGH + (c+dx))*DIM + ch] * wc[k][tid];
            }
        } else {
            #pragma unroll
            for (int k = 0; k < 49; k++) {
                int dy = k / 7 - 3, dx = k % 7 - 3;
                int rr = r + dy, cc = c + dx;
                if (rr >= 0 && rr < IMGH && cc >= 0 && cc < IMGH)
                    acc += h[(long)(1 + rr*IMGH + cc)*DIM + ch] * wc[k][tid];
            }
        }
        out[(long)p*DIM + ch] = acc;
    }
}

__global__ void ppeg_copyback(float* __restrict__ h, const float* __restrict__ y) {
    long i = (long)blockIdx.x * blockDim.x + threadIdx.x;
    if (i < (long)NPIX*DIM) h[DIM + i] = y[i];
}

__global__ void final_head(const float* __restrict__ h, const float* __restrict__ g,
                           const float* __restrict__ b, const float* __restrict__ W,
                           const float* __restrict__ bias, float* __restrict__ out,
                           int out_size)
{
    __shared__ float red[512];
    __shared__ float xn[512];
    int tid = threadIdx.x;
    float x = h[tid];
    red[tid] = x; __syncthreads();
    for (int st = 256; st > 0; st >>= 1) {
        if (tid < st) red[tid] += red[tid+st];
        __syncthreads();
    }
    float mu = red[0] / DIM; __syncthreads();
    float d = x - mu;
    red[tid] = d*d; __syncthreads();
    for (int st = 256; st > 0; st >>= 1) {
        if (tid < st) red[tid] += red[tid+st];
        __syncthreads();
    }
    float rstd = rsqrtf(red[0]/DIM + 1e-5f); __syncthreads();
    xn[tid] = d*rstd*g[tid] + b[tid];
    __syncthreads();
    if (tid < 5) {
        float s = bias[tid];
        for (int c = 0; c < DIM; c++) s += xn[c] * W[c*5 + tid];
        red[tid] = s;
    }
    __syncthreads();
    if (tid == 0) {
        float lg[5], mx = -1e30f;
        for (int j = 0; j < 5; j++) { lg[j] = red[j]; mx = fmaxf(mx, lg[j]); }
        float se = 0.f, pr[5];
        for (int j = 0; j < 5; j++) { pr[j] = expf(lg[j]-mx); se += pr[j]; }
        int am = 0;
        for (int j = 1; j < 5; j++) if (lg[j] > lg[am]) am = j;
        for (int j = 0; j < 5; j++) {
            if (j < out_size)     out[j]     = lg[j];
            if (5 + j < out_size) out[5 + j] = pr[j]/se;
        }
        if (10 < out_size) out[10] = (float)am;
        for (int j = 11; j < out_size; j++) out[j] = 0.f;
    }
}

// ---------------- host orchestration ----------------
struct Ptrs {
    float *h, *xln, *qkv, *QL, *KL, *A3;
    float *S2, *XZ, *T1, *T2, *Z, *Z2, *T, *U, *attn, *y, *scal;
};

static void get_ptrs(Ptrs& P) {
    cudaGetSymbolAddress((void**)&P.h,    g_h);
    cudaGetSymbolAddress((void**)&P.xln,  g_xln);
    cudaGetSymbolAddress((void**)&P.qkv,  g_qkv);
    cudaGetSymbolAddress((void**)&P.QL,   g_QL);
    cudaGetSymbolAddress((void**)&P.KL,   g_KL);
    cudaGetSymbolAddress((void**)&P.A3,   g_A3);
    cudaGetSymbolAddress((void**)&P.S2,   g_S2);
    cudaGetSymbolAddress((void**)&P.XZ,   g_XZ);
    cudaGetSymbolAddress((void**)&P.T1,   g_T1);
    cudaGetSymbolAddress((void**)&P.T2,   g_T2);
    cudaGetSymbolAddress((void**)&P.Z,    g_Zb);
    cudaGetSymbolAddress((void**)&P.Z2,   g_Z2b);
    cudaGetSymbolAddress((void**)&P.T,    g_Tb);
    cudaGetSymbolAddress((void**)&P.U,    g_Ub);
    cudaGetSymbolAddress((void**)&P.attn, g_attn);
    cudaGetSymbolAddress((void**)&P.y,    g_y);
    cudaGetSymbolAddress((void**)&P.scal, g_scal);
}

#define MMA_BIG_NN  gemm_mma<128,128,64,32,false,false>
#define MMA_BIG_NT  gemm_mma<128,128,64,32,true ,false>
#define MMA_SM_NN   gemm_mma<64,64,32,32,false,false>
#define MMA_SM_NT   gemm_mma<64,64,32,32,true ,false>
#define MMA_SM_SPK  gemm_mma<64,64,32,32,false,true >

static inline dim3 grid128(int M, int N, int batch) {
    return dim3(N / 128, (M + 127) / 128, batch);
}
static inline dim3 grid64(int M, int N, int batch) {
    return dim3(N / 64, (M + 63) / 64, batch);
}

static void run_attention(const Ptrs& P, const float* lng, const float* lnb,
                          const float* Wqkv, const float* Wout, const float* bout,
                          const float* resw)
{
    const long sLnd = (long)NL*DH;
    const long sQ   = (long)NL*NL;
    const float QS = 0.125f;

    const float* Kv = P.qkv + DIM;
    const float* Vv = P.qkv + 2*DIM;

    ln_pad<<<NPAD, 256>>>(P.h, P.xln, lng, lnb);
    MMA_BIG_NN<<<grid128(NPAD, 3*DIM, 1), 256>>>(
        P.xln, Wqkv, P.qkv, NPAD, 3*DIM, DIM, DIM, 3*DIM, 3*DIM,
        0, 0, 0, 1.f, 0.f, 0.f, nullptr, 0);
    landmarks_k<<<(HEADS*NL*DH + 255)/256, 256>>>(P.qkv, P.QL, P.KL);
    // sim2 + softmax
    MMA_SM_NT<<<grid64(NL, NL, HEADS), 128>>>(
        P.QL, P.KL, P.S2, NL, NL, DH, DH, DH, NL,
        sLnd, sLnd, sQ, QS, 0.f, 0.f, nullptr, 0);
    softmax256<<<HEADS*NL, 128>>>(P.S2);
    // pinv: one persistent launch
    pinv_persist<<<PBLOCKS, 128>>>(P.S2, P.Z, P.Z2, P.XZ, P.T1, P.T2, P.scal);
    // a3 = softmax(QL @ K^T)
    MMA_BIG_NT<<<grid128(NL, NPAD, HEADS), 256>>>(
        P.QL, Kv, P.A3, NL, NPAD, DH, DH, QKVD, NPAD,
        sLnd, (long)DH, (long)NL*NPAD, QS, 0.f, 0.f, nullptr, 0);
    softmax_wide<<<HEADS*NL, 256>>>(P.A3);
    // T = a3 @ V (split-K)
    zero_kernel<<<(HEADS*NL*DH + 255)/256, 256>>>(P.T, (long)HEADS*NL*DH);
    MMA_SM_SPK<<<grid64(NL, DH, HEADS*NSPLIT), 128>>>(
        P.A3, Vv, P.T, NL, DH, NPAD, NPAD, QKVD, DH,
        (long)NL*NPAD, (long)DH, sLnd, 1.f, 0.f, 0.f, nullptr, 0);
    // U = a2_inv @ T
    MMA_SM_NN<<<grid64(NL, DH, HEADS), 128>>>(
        P.Z, P.T, P.U, NL, DH, NL, NL, DH, DH,
        sQ, sLnd, sLnd, 1.f, 0.f, 0.f, nullptr, 0);
    // fused a1 path: attn = softmax(0.125 Q@KL^T) @ U
    attn1_fused<<<dim3(NPAD/64, HEADS), 128, A1_SMEMB>>>(P.qkv, P.KL, P.U, P.attn);
    // residual depthwise conv
    res_conv2<<<NPAD/8, 512>>>(P.attn, P.qkv, resw);
    // out projection
    MMA_BIG_NN<<<grid128(NPAD, DIM, 1), 256>>>(
        P.attn, Wout, P.y, NPAD, DIM, DIM, DIM, DIM, DIM,
        0, 0, 0, 1.f, 0.f, 0.f, bout, 0);
    add_tail<<<(NTOK*DIM + 255)/256, 256>>>(P.h, P.y);
}

extern "C" void kernel_launch(void* const* d_in, const int* in_sizes, int n_in,
                              void* d_out, int out_size)
{
    const float* data      = (const float*)d_in[0];
    const float* W_fc1     = (const float*)d_in[1];
    const float* b_fc1     = (const float*)d_in[2];
    const float* cls_token = (const float*)d_in[3];
    const float* ln1_g     = (const float*)d_in[4];
    const float* ln1_b     = (const float*)d_in[5];
    const float* qkv1      = (const float*)d_in[6];
    const float* out1_w    = (const float*)d_in[7];
    const float* out1_b    = (const float*)d_in[8];
    const float* res1      = (const float*)d_in[9];
    const float* w7        = (const float*)d_in[10];
    const float* b7        = (const float*)d_in[11];
    const float* w5        = (const float*)d_in[12];
    const float* b5        = (const float*)d_in[13];
    const float* w3        = (const float*)d_in[14];
    const float* b3        = (const float*)d_in[15];
    const float* ln2_g     = (const float*)d_in[16];
    const float* ln2_b     = (const float*)d_in[17];
    const float* qkv2      = (const float*)d_in[18];
    const float* out2_w    = (const float*)d_in[19];
    const float* out2_b    = (const float*)d_in[20];
    const float* res2      = (const float*)d_in[21];
    const float* norm_g    = (const float*)d_in[22];
    const float* norm_b    = (const float*)d_in[23];
    const float* W_fc2     = (const float*)d_in[24];
    const float* b_fc2     = (const float*)d_in[25];

    Ptrs P;
    get_ptrs(P);

    cudaFuncSetAttribute(attn1_fused,
        cudaFuncAttributeMaxDynamicSharedMemorySize, A1_SMEMB);

    set_cls<<<1, DIM>>>(P.h, cls_token);
    MMA_BIG_NN<<<grid128(15000, DIM, 1), 256>>>(
        data, W_fc1, P.h + DIM, 15000, DIM, 1024, 1024, DIM, DIM,
        0, 0, 0, 1.f, 0.f, 0.f, b_fc1, 1);
    dup_rows<<<(129*DIM + 255)/256, 256>>>(P.h);

    run_attention(P, ln1_g, ln1_b, qkv1, out1_w, out1_b, res1);

    ppeg2<<<dim3((NPIX + PPP - 1)/PPP, DIM/128), 128>>>(
        P.h, P.y, w7, b7, w5, b5, w3, b3);
    ppeg_copyback<<<(int)(((long)NPIX*DIM + 255)/256), 256>>>(P.h, P.y);

    run_attention(P, ln2_g, ln2_b, qkv2, out2_w, out2_b, res2);

    final_head<<<1, DIM>>>(P.h, norm_g, norm_b, W_fc2, b_fc2, (float*)d_out, out_size);
}

// round 8
// speedup vs baseline: 3.2008x; 1.2596x over previous
#include <cuda_runtime.h>
#include <math.h>
#include <stdint.h>

#define HEADS 8
#define DH    64
#define DIM   512
#define QKVD  1536
#define NTOK  15130
#define NPAD  15360
#define PADR  230
#define NL    256
#define LCH   60
#define IMGH  123
#define NPIX  15129
#define NSPLIT 16
#define PBLOCKS 128

// ---------------- static scratch (allocation-free rule) ----------------
__device__ __align__(16) float g_h   [NTOK*DIM];
__device__ __align__(16) float g_xln [NPAD*DIM];
__device__ __align__(16) float g_qkv [NPAD*3*DIM];
__device__ __align__(16) float g_QL  [HEADS*NL*DH];
__device__ __align__(16) float g_KL  [HEADS*NL*DH];
__device__ __align__(16) float g_A3  [HEADS*NL*NPAD];
__device__ __align__(16) float g_S2  [HEADS*NL*NL];
__device__ __align__(16) float g_XZ  [HEADS*NL*NL];
__device__ __align__(16) float g_T1  [HEADS*NL*NL];
__device__ __align__(16) float g_T2  [HEADS*NL*NL];
__device__ __align__(16) float g_Zb  [HEADS*NL*NL];
__device__ __align__(16) float g_Z2b [HEADS*NL*NL];
__device__ __align__(16) float g_Tb  [HEADS*NL*DH];
__device__ __align__(16) float g_Ub  [HEADS*NL*DH];
__device__ __align__(16) float g_attn[NPAD*DIM];
__device__ __align__(16) float g_y   [NPAD*DIM];
__device__ float g_scal[2];
__device__ unsigned g_bar_cnt = 0;
__device__ volatile unsigned g_bar_gen = 0;

// ================= tf32 split primitives (pinv + attn1_fused) =================
__device__ __forceinline__ uint32_t f2tf(float x) {
    uint32_t r;
    asm("cvt.rna.tf32.f32 %0, %1;" : "=r"(r) : "f"(x));
    return r;
}
__device__ __forceinline__ void mma8(float* d,
    uint32_t a0, uint32_t a1, uint32_t a2, uint32_t a3,
    uint32_t b0, uint32_t b1)
{
    asm volatile("mma.sync.aligned.m16n8k8.row.col.f32.tf32.tf32.f32 "
        "{%0,%1,%2,%3},{%4,%5,%6,%7},{%8,%9},{%0,%1,%2,%3};"
        : "+f"(d[0]), "+f"(d[1]), "+f"(d[2]), "+f"(d[3])
        : "r"(a0), "r"(a1), "r"(a2), "r"(a3), "r"(b0), "r"(b1));
}
__device__ __forceinline__ void mma_split(float* acc,
    const uint32_t* Ah, const uint32_t* Al, const uint32_t* Bh, const uint32_t* Bl)
{
    mma8(acc, Ah[0],Ah[1],Ah[2],Ah[3], Bh[0],Bh[1]);
    mma8(acc, Ah[0],Ah[1],Ah[2],Ah[3], Bl[0],Bl[1]);
    mma8(acc, Al[0],Al[1],Al[2],Al[3], Bh[0],Bh[1]);
}
__device__ __forceinline__ void splitA(float x, uint32_t& h, uint32_t& l) {
    h = f2tf(x); l = __float_as_uint(x - __uint_as_float(h));
}

// ================= bf16 split primitives (generic GEMM) =================
// pack two floats into bf16x2: x0 -> low half (lower k index), x1 -> high half
__device__ __forceinline__ uint32_t pkbf(float x0, float x1) {
    uint32_t r;
    asm("cvt.rn.bf16x2.f32 %0, %1, %2;" : "=r"(r) : "f"(x1), "f"(x0));
    return r;
}
__device__ __forceinline__ float unlo(uint32_t p) {
    return __uint_as_float(p << 16);
}
__device__ __forceinline__ float unhi(uint32_t p) {
    return __uint_as_float(p & 0xFFFF0000u);
}
// split float4 (4 consecutive k values) -> 2 packed hi + 2 packed lo
__device__ __forceinline__ void bsplit4(float4 v,
    uint32_t& h0, uint32_t& h1, uint32_t& l0, uint32_t& l1)
{
    h0 = pkbf(v.x, v.y);
    h1 = pkbf(v.z, v.w);
    l0 = pkbf(v.x - unlo(h0), v.y - unhi(h0));
    l1 = pkbf(v.z - unlo(h1), v.w - unhi(h1));
}
__device__ __forceinline__ void mma16(float* d,
    uint32_t a0, uint32_t a1, uint32_t a2, uint32_t a3,
    uint32_t b0, uint32_t b1)
{
    asm volatile("mma.sync.aligned.m16n8k16.row.col.f32.bf16.bf16.f32 "
        "{%0,%1,%2,%3},{%4,%5,%6,%7},{%8,%9},{%0,%1,%2,%3};"
        : "+f"(d[0]), "+f"(d[1]), "+f"(d[2]), "+f"(d[3])
        : "r"(a0), "r"(a1), "r"(a2), "r"(a3), "r"(b0), "r"(b1));
}
__device__ __forceinline__ void mma16_split(float* acc,
    const uint32_t* Ah, const uint32_t* Al, const uint32_t* Bh, const uint32_t* Bl)
{
    mma16(acc, Ah[0],Ah[1],Ah[2],Ah[3], Bh[0],Bh[1]);
    mma16(acc, Ah[0],Ah[1],Ah[2],Ah[3], Bl[0],Bl[1]);
    mma16(acc, Al[0],Al[1],Al[2],Al[3], Bh[0],Bh[1]);
}

#define PADS 4

// ================= generic bf16-split GEMM (batched, NN/NT, split-K) ============
// K-tile = 16. Smem holds PRE-SPLIT packed bf16x2 hi/lo (k-pairs): inner loop is
// pure LDS + HMMA. mode: 0 plain, 1 bias+relu, 2 residual add into C[r-PADR].
template<int BM, int BN, int WM, int WN, bool NT, bool SPLITK>
__global__ void __launch_bounds__((BM/WM)*(BN/WN)*32)
gemm_mma(const float* __restrict__ A, const float* __restrict__ B,
         float* __restrict__ C,
         int M, int N, int K, int lda, int ldb, int ldc,
         long sA, long sB, long sC,
         float alpha, float beta_diag, float gammaA,
         const float* __restrict__ bias, int mode)
{
    constexpr int NWARP = (BM/WM)*(BN/WN);
    constexpr int T = NWARP * 32;
    constexpr int NWN = BN / WN;
    constexpr int MT = WM / 16, NTL = WN / 8;
    static_assert(T == 8 * (BN / 4), "B-NN loader mapping requires T == 2*BN");

    int z = blockIdx.z;
    int kbeg = 0, kend = K;
    if (SPLITK) {
        int batch = z / NSPLIT, split = z % NSPLIT;
        A += (long)batch * sA; B += (long)batch * sB; C += (long)batch * sC;
        int chunk = K / NSPLIT;
        kbeg = split * chunk; kend = kbeg + chunk;
    } else {
        A += (long)z * sA; B += (long)z * sB; C += (long)z * sC;
    }

    // packed bf16x2 hi/lo tiles, k-pair-major: [8 k-pairs][BM or BN]
    __shared__ __align__(16) uint32_t sAh[2][8][BM + PADS];
    __shared__ __align__(16) uint32_t sAl[2][8][BM + PADS];
    __shared__ __align__(16) uint32_t sBh[2][8][BN + PADS];
    __shared__ __align__(16) uint32_t sBl[2][8][BN + PADS];

    const int tid = threadIdx.x;
    const int wid = tid >> 5, lane = tid & 31;
    const int g = lane >> 2, t = lane & 3;
    const int row0 = blockIdx.y * BM;
    const int col0 = blockIdx.x * BN;
    const int wm0 = (wid / NWN) * WM;
    const int wn0 = (wid % NWN) * WN;

    float4 ra[2], rb[2];   // for NT, rb = 2 float4 over k; for NN, rb = rows k,k+1

    auto load_g = [&](int k0) {
        #pragma unroll
        for (int it = 0; it < 2; it++) {
            int i = tid + it * T;
            int m = i >> 2, kq = (i & 3) * 4;
            int gm = row0 + m;
            ra[it] = make_float4(0.f, 0.f, 0.f, 0.f);
            if (gm < M) ra[it] = *(const float4*)&A[(long)gm * lda + k0 + kq];
        }
        if (!NT) {
            int k2 = tid / (BN / 4), ng = (tid % (BN / 4)) * 4;
            rb[0] = *(const float4*)&B[(long)(k0 + 2*k2)     * ldb + col0 + ng];
            rb[1] = *(const float4*)&B[(long)(k0 + 2*k2 + 1) * ldb + col0 + ng];
        } else {
            #pragma unroll
            for (int it = 0; it < 2; it++) {
                int i = tid + it * T;
                int n = i >> 2, kq = (i & 3) * 4;
                rb[it] = make_float4(0.f, 0.f, 0.f, 0.f);
                if (col0 + n < N)
                    rb[it] = *(const float4*)&B[(long)(col0 + n) * ldb + k0 + kq];
            }
        }
    };
    auto store_s = [&](int buf) {
        #pragma unroll
        for (int it = 0; it < 2; it++) {
            int i = tid + it * T;
            int m = i >> 2, kp = (i & 3) * 2;
            uint32_t h0, h1, l0, l1;
            bsplit4(ra[it], h0, h1, l0, l1);
            sAh[buf][kp][m]     = h0;
            sAh[buf][kp + 1][m] = h1;
            sAl[buf][kp][m]     = l0;
            sAl[buf][kp + 1][m] = l1;
        }
        if (!NT) {
            int k2 = tid / (BN / 4), ng = (tid % (BN / 4)) * 4;
            const float* v0 = &rb[0].x;
            const float* v1 = &rb[1].x;
            uint32_t hh[4], ll[4];
            #pragma unroll
            for (int q = 0; q < 4; q++) {
                uint32_t h = pkbf(v0[q], v1[q]);
                hh[q] = h;
                ll[q] = pkbf(v0[q] - unlo(h), v1[q] - unhi(h));
            }
            *(uint4*)&sBh[buf][k2][ng] = *(uint4*)hh;
            *(uint4*)&sBl[buf][k2][ng] = *(uint4*)ll;
        } else {
            #pragma unroll
            for (int it = 0; it < 2; it++) {
                int i = tid + it * T;
                int n = i >> 2, kp = (i & 3) * 2;
                uint32_t h0, h1, l0, l1;
                bsplit4(rb[it], h0, h1, l0, l1);
                sBh[buf][kp][n]     = h0;
                sBh[buf][kp + 1][n] = h1;
                sBl[buf][kp][n]     = l0;
                sBl[buf][kp + 1][n] = l1;
            }
        }
    };

    float acc[MT][NTL][4];
    #pragma unroll
    for (int i = 0; i < MT; i++)
        #pragma unroll
        for (int j = 0; j < NTL; j++)
            #pragma unroll
            for (int q = 0; q < 4; q++) acc[i][j][q] = 0.f;

    const int ntiles = (kend - kbeg) / 16;
    load_g(kbeg);
    store_s(0);
    __syncthreads();

    for (int kt = 0; kt < ntiles; kt++) {
        if (kt + 1 < ntiles) load_g(kbeg + (kt + 1) * 16);
        int buf = kt & 1;
        {
            uint32_t Ahf[MT][4], Alf[MT][4], Bhf[NTL][2], Blf[NTL][2];
            #pragma unroll
            for (int mt = 0; mt < MT; mt++) {
                int mb = wm0 + mt * 16 + g;
                Ahf[mt][0] = sAh[buf][t    ][mb];
                Ahf[mt][1] = sAh[buf][t    ][mb + 8];
                Ahf[mt][2] = sAh[buf][t + 4][mb];
                Ahf[mt][3] = sAh[buf][t + 4][mb + 8];
                Alf[mt][0] = sAl[buf][t    ][mb];
                Alf[mt][1] = sAl[buf][t    ][mb + 8];
                Alf[mt][2] = sAl[buf][t + 4][mb];
                Alf[mt][3] = sAl[buf][t + 4][mb + 8];
            }
            #pragma unroll
            for (int nt = 0; nt < NTL; nt++) {
                int nb = wn0 + nt * 8 + g;
                Bhf[nt][0] = sBh[buf][t    ][nb];
                Bhf[nt][1] = sBh[buf][t + 4][nb];
                Blf[nt][0] = sBl[buf][t    ][nb];
                Blf[nt][1] = sBl[buf][t + 4][nb];
            }
            #pragma unroll
            for (int mt = 0; mt < MT; mt++)
                #pragma unroll
                for (int nt = 0; nt < NTL; nt++)
                    mma16_split(acc[mt][nt], Ahf[mt], Alf[mt], Bhf[nt], Blf[nt]);
        }
        if (kt + 1 < ntiles) {
            store_s((kt + 1) & 1);
            __syncthreads();
        }
    }

    auto emit = [&](int r, int c, float v0, float v1) {
        if (r >= M) return;
        v0 *= alpha; v1 *= alpha;
        if (bias) { v0 += bias[c]; v1 += bias[c + 1]; }
        if (beta_diag != 0.f) {
            if (r == c)     v0 += beta_diag;
            if (r == c + 1) v1 += beta_diag;
        }
        if (gammaA != 0.f) {
            v0 += gammaA * A[(long)r * lda + c];
            v1 += gammaA * A[(long)r * lda + c + 1];
        }
        if (mode == 1) { v0 = fmaxf(v0, 0.f); v1 = fmaxf(v1, 0.f); }
        if (SPLITK) {
            atomicAdd(&C[(long)r * ldc + c], v0);
            atomicAdd(&C[(long)r * ldc + c + 1], v1);
        } else if (mode == 2) {
            if (r >= PADR) {
                float2* dst = (float2*)&C[(long)(r - PADR) * ldc + c];
                float2 o = *dst;
                o.x += v0; o.y += v1;
                *dst = o;
            }
        } else {
            *(float2*)&C[(long)r * ldc + c] = make_float2(v0, v1);
        }
    };
    #pragma unroll
    for (int mt = 0; mt < MT; mt++)
        #pragma unroll
        for (int nt = 0; nt < NTL; nt++) {
            int r = row0 + wm0 + mt * 16 + g;
            int c = col0 + wn0 + nt * 8 + 2 * t;
            emit(r,     c, acc[mt][nt][0], acc[mt][nt][1]);
            emit(r + 8, c, acc[mt][nt][2], acc[mt][nt][3]);
        }
}

// ================= persistent pinv kernel (tf32 split, unchanged) ==============
__device__ __forceinline__ void atomicMaxFloatPos(float* addr, float v) {
    atomicMax((int*)addr, __float_as_int(v));
}

__device__ __forceinline__ void gridbar() {
    __syncthreads();
    if (threadIdx.x == 0) {
        unsigned gen = g_bar_gen;
        __threadfence();
        if (atomicAdd(&g_bar_cnt, 1u) == PBLOCKS - 1) {
            g_bar_cnt = 0;
            __threadfence();
            g_bar_gen = gen + 1;
        } else {
            while (g_bar_gen == gen) { __nanosleep(64); }
        }
        __threadfence();
    }
    __syncthreads();
}

typedef float smtile[16][68];

__device__ __noinline__ void gemm64_dev(
    const float* __restrict__ A, const float* __restrict__ B, float* __restrict__ C,
    int row0, int col0, float alpha, float beta_diag, float gammaA,
    smtile* As, smtile* Bs)
{
    const int tid = threadIdx.x;
    const int wid = tid >> 5, lane = tid & 31;
    const int g = lane >> 2, t = lane & 3;
    const int wm0 = (wid >> 1) * 32, wn0 = (wid & 1) * 32;

    float4 ra[2], rb[2];
    auto load_g = [&](int k0) {
        #pragma unroll
        for (int it = 0; it < 2; it++) {
            int i = tid + it * 128;
            int m = i >> 2, kq = (i & 3) * 4;
            ra[it] = *(const float4*)&A[(long)(row0 + m) * 256 + k0 + kq];
            int kk = i >> 4, nq = (i & 15) * 4;
            rb[it] = *(const float4*)&B[(long)(k0 + kk) * 256 + col0 + nq];
        }
    };
    auto store_s = [&](int buf) {
        #pragma unroll
        for (int it = 0; it < 2; it++) {
            int i = tid + it * 128;
            int m = i >> 2, kq = (i & 3) * 4;
            As[buf][kq + 0][m] = ra[it].x;
            As[buf][kq + 1][m] = ra[it].y;
            As[buf][kq + 2][m] = ra[it].z;
            As[buf][kq + 3][m] = ra[it].w;
            int kk = i >> 4, nq = (i & 15) * 4;
            *(float4*)&Bs[buf][kk][nq] = rb[it];
        }
    };

    float acc[2][4][4] = {};
    load_g(0);
    store_s(0);
    __syncthreads();
    for (int kt = 0; kt < 16; kt++) {
        if (kt + 1 < 16) load_g((kt + 1) * 16);
        int buf = kt & 1;
        #pragma unroll
        for (int k8 = 0; k8 < 16; k8 += 8) {
            uint32_t Ah[2][4], Al[2][4], Bh[4][2], Bl[4][2];
            #pragma unroll
            for (int mt = 0; mt < 2; mt++) {
                int mb = wm0 + mt * 16 + g;
                splitA(As[buf][k8 + t    ][mb],     Ah[mt][0], Al[mt][0]);
                splitA(As[buf][k8 + t    ][mb + 8], Ah[mt][1], Al[mt][1]);
                splitA(As[buf][k8 + t + 4][mb],     Ah[mt][2], Al[mt][2]);
                splitA(As[buf][k8 + t + 4][mb + 8], Ah[mt][3], Al[mt][3]);
            }
            #pragma unroll
            for (int nt = 0; nt < 4; nt++) {
                int nb = wn0 + nt * 8 + g;
                splitA(Bs[buf][k8 + t    ][nb], Bh[nt][0], Bl[nt][0]);
                splitA(Bs[buf][k8 + t + 4][nb], Bh[nt][1], Bl[nt][1]);
            }
            #pragma unroll
            for (int mt = 0; mt < 2; mt++)
                #pragma unroll
                for (int nt = 0; nt < 4; nt++)
                    mma_split(acc[mt][nt], Ah[mt], Al[mt], Bh[nt], Bl[nt]);
        }
        if (kt + 1 < 16) {
            store_s((kt + 1) & 1);
            __syncthreads();
        }
    }
    #pragma unroll
    for (int mt = 0; mt < 2; mt++)
        #pragma unroll
        for (int nt = 0; nt < 4; nt++) {
            int r0 = row0 + wm0 + mt * 16 + g;
            int c = col0 + wn0 + nt * 8 + 2 * t;
            #pragma unroll
            for (int half = 0; half < 2; half++) {
                int r = r0 + half * 8;
                float v0 = alpha * acc[mt][nt][half*2 + 0];
                float v1 = alpha * acc[mt][nt][half*2 + 1];
                if (beta_diag != 0.f) {
                    if (r == c)     v0 += beta_diag;
                    if (r == c + 1) v1 += beta_diag;
                }
                if (gammaA != 0.f) {
                    v0 += gammaA * A[(long)r * 256 + c];
                    v1 += gammaA * A[(long)r * 256 + c + 1];
                }
                *(float2*)&C[(long)r * 256 + c] = make_float2(v0, v1);
            }
        }
    __syncthreads();
}

__global__ void __launch_bounds__(128) pinv_persist(
    const float* __restrict__ S2, float* __restrict__ Z, float* __restrict__ Z2,
    float* __restrict__ XZ, float* __restrict__ T1, float* __restrict__ T2,
    float* __restrict__ scal)
{
    __shared__ float As[2][16][68], Bs[2][16][68];
    const int b = blockIdx.x, tid = threadIdx.x;
    const int wid = tid >> 5, lane = tid & 31;

    if (b == 0 && tid < 2) scal[tid] = 0.f;
    gridbar();

    for (int q = 0; q < 8; q++) {
        int idx = b * 32 + wid * 8 + q;
        int mode = idx >> 11, rem = idx & 2047;
        int h = rem >> 8, i = rem & 255;
        const float* base = S2 + (long)h * 65536;
        float s = 0.f;
        if (mode == 0) { for (int j = lane; j < 256; j += 32) s += fabsf(base[i * 256 + j]); }
        else           { for (int j = lane; j < 256; j += 32) s += fabsf(base[j * 256 + i]); }
        #pragma unroll
        for (int o = 16; o; o >>= 1) s += __shfl_xor_sync(~0u, s, o);
        if (lane == 0) atomicMaxFloatPos(&scal[mode], s);
    }
    gridbar();

    float denom = scal[0] * scal[1];
    for (int l = 0; l < 32; l++) {
        int idx = b * 4096 + l * 128 + tid;
        int h = idx >> 16, rc = idx & 65535, r = rc >> 8, c = rc & 255;
        Z[idx] = S2[(long)h * 65536 + (long)c * 256 + r] / denom;
    }
    gridbar();

    const int head = b >> 4, tt = b & 15;
    const int row0 = (tt >> 2) * 64, col0 = (tt & 3) * 64;
    const long ho = (long)head * 65536;

    for (int it = 0; it < 6; it++) {
        float* zin  = (it & 1) ? Z2 : Z;
        float* zout = (it & 1) ? Z  : Z2;
        gemm64_dev(S2 + ho, zin + ho, XZ + ho, row0, col0, 1.f, 0.f, 0.f, As, Bs);
        gridbar();
        gemm64_dev(XZ + ho, XZ + ho, T2 + ho, row0, col0, 1.f, 15.f, -7.f, As, Bs);
        gridbar();
        gemm64_dev(XZ + ho, T2 + ho, T1 + ho, row0, col0, -1.f, 13.f, 0.f, As, Bs);
        gridbar();
        gemm64_dev(zin + ho, T1 + ho, zout + ho, row0, col0, 0.25f, 0.f, 0.f, As, Bs);
        gridbar();
    }
}

// ================= fused a1 attention: attn += softmax(0.125 Q@KL^T) @ U =========
#define A1_AS1   0
#define A1_BS1   (64*68)
#define A1_ST    (A1_BS1 + 64*260)
#define A1_US    (A1_ST + 256*65)
#define A1_RINV  (A1_US + 256*68)
#define A1_SMEMF (A1_RINV + 64)
#define A1_SMEMB (A1_SMEMF*4)

__global__ void __launch_bounds__(128) attn1_fused(
    const float* __restrict__ qkv, const float* __restrict__ KL,
    const float* __restrict__ U, float* __restrict__ attn)
{
    extern __shared__ float sm[];
    float* As1 = sm + A1_AS1;
    float* Bs1 = sm + A1_BS1;
    float* ST  = sm + A1_ST;
    float* Us  = sm + A1_US;
    float* rinv= sm + A1_RINV;

    const int tid = threadIdx.x;
    const int wid = tid >> 5, lane = tid & 31;
    const int g = lane >> 2, t = lane & 3;
    const int h = blockIdx.y;
    const int row0 = blockIdx.x * 64;
    const float* Qg  = qkv + h * DH;
    const float* KLh = KL + (long)h * NL * DH;
    const float* Uh  = U  + (long)h * NL * DH;

    #pragma unroll
    for (int l = 0; l < 8; l++) {
        int i = tid + l * 128;
        int m = i >> 4, kq = (i & 15) * 4;
        float4 v = *(const float4*)&Qg[(long)(row0 + m) * QKVD + kq];
        As1[(kq+0)*68+m] = v.x; As1[(kq+1)*68+m] = v.y;
        As1[(kq+2)*68+m] = v.z; As1[(kq+3)*68+m] = v.w;
    }
    #pragma unroll
    for (int l = 0; l < 32; l++) {
        int i = tid + l * 128;
        int n = i >> 4, kq = (i & 15) * 4;
        float4 v = *(const float4*)&KLh[n * 64 + kq];
        Bs1[(kq+0)*260+n] = v.x; Bs1[(kq+1)*260+n] = v.y;
        Bs1[(kq+2)*260+n] = v.z; Bs1[(kq+3)*260+n] = v.w;
        int k = i >> 4, nq = (i & 15) * 4;
        *(float4*)&Us[k * 68 + nq] = *(const float4*)&Uh[k * 64 + nq];
    }
    __syncthreads();

    const int wm0 = (wid >> 1) * 32;
    const int wn1 = (wid & 1) * 128;
    {
        float acc1[2][16][4] = {};
        #pragma unroll
        for (int k8 = 0; k8 < 64; k8 += 8) {
            uint32_t Ah[2][4], Al[2][4];
            #pragma unroll
            for (int mt = 0; mt < 2; mt++) {
                int mb = wm0 + mt * 16 + g;
                splitA(As1[(k8+t  )*68 + mb],   Ah[mt][0], Al[mt][0]);
                splitA(As1[(k8+t  )*68 + mb+8], Ah[mt][1], Al[mt][1]);
                splitA(As1[(k8+t+4)*68 + mb],   Ah[mt][2], Al[mt][2]);
                splitA(As1[(k8+t+4)*68 + mb+8], Ah[mt][3], Al[mt][3]);
            }
            #pragma unroll
            for (int nt = 0; nt < 16; nt++) {
                int nb = wn1 + nt * 8 + g;
                uint32_t Bh[2], Bl[2];
                splitA(Bs1[(k8+t  )*260 + nb], Bh[0], Bl[0]);
                splitA(Bs1[(k8+t+4)*260 + nb], Bh[1], Bl[1]);
                mma_split(acc1[0][nt], Ah[0], Al[0], Bh, Bl);
                mma_split(acc1[1][nt], Ah[1], Al[1], Bh, Bl);
            }
        }
        __syncthreads();
        #pragma unroll
        for (int mt = 0; mt < 2; mt++)
            #pragma unroll
            for (int nt = 0; nt < 16; nt++) {
                int r = wm0 + mt * 16 + g;
                int c = wn1 + nt * 8 + 2 * t;
                ST[c*65 + r]       = 0.125f * acc1[mt][nt][0];
                ST[(c+1)*65 + r]   = 0.125f * acc1[mt][nt][1];
                ST[c*65 + r+8]     = 0.125f * acc1[mt][nt][2];
                ST[(c+1)*65 + r+8] = 0.125f * acc1[mt][nt][3];
            }
    }
    __syncthreads();

    {
        int r = tid >> 1, half = tid & 1;
        int j0 = half * 128;
        float m = -1e30f;
        #pragma unroll 8
        for (int j = j0; j < j0 + 128; j++) m = fmaxf(m, ST[j*65 + r]);
        m = fmaxf(m, __shfl_xor_sync(~0u, m, 1));
        float s = 0.f;
        #pragma unroll 8
        for (int j = j0; j < j0 + 128; j++) {
            float e = expf(ST[j*65 + r] - m);
            ST[j*65 + r] = e;
            s += e;
        }
        s += __shfl_xor_sync(~0u, s, 1);
        if (half == 0) rinv[r] = 1.f / s;
    }
    __syncthreads();

    {
        const int wn2 = (wid & 1) * 32;
        float acc2[2][4][4] = {};
        #pragma unroll 8
        for (int k8 = 0; k8 < 256; k8 += 8) {
            uint32_t Ah[2][4], Al[2][4], Bh[4][2], Bl[4][2];
            #pragma unroll
            for (int mt = 0; mt < 2; mt++) {
                int mb = wm0 + mt * 16 + g;
                splitA(ST[(k8+t  )*65 + mb],   Ah[mt][0], Al[mt][0]);
                splitA(ST[(k8+t  )*65 + mb+8], Ah[mt][1], Al[mt][1]);
                splitA(ST[(k8+t+4)*65 + mb],   Ah[mt][2], Al[mt][2]);
                splitA(ST[(k8+t+4)*65 + mb+8], Ah[mt][3], Al[mt][3]);
            }
            #pragma unroll
            for (int nt = 0; nt < 4; nt++) {
                int nb = wn2 + nt * 8 + g;
                splitA(Us[(k8+t  )*68 + nb], Bh[nt][0], Bl[nt][0]);
                splitA(Us[(k8+t+4)*68 + nb], Bh[nt][1], Bl[nt][1]);
            }
            #pragma unroll
            for (int mt = 0; mt < 2; mt++)
                #pragma unroll
                for (int nt = 0; nt < 4; nt++)
                    mma_split(acc2[mt][nt], Ah[mt], Al[mt], Bh[nt], Bl[nt]);
        }
        #pragma unroll
        for (int mt = 0; mt < 2; mt++)
            #pragma unroll
            for (int nt = 0; nt < 4; nt++) {
                int rl = wm0 + mt * 16 + g;
                int c = h * DH + wn2 + nt * 8 + 2 * t;
                float i0 = rinv[rl], i1 = rinv[rl + 8];
                float2* d0 = (float2*)&attn[(long)(row0 + rl) * DIM + c];
                float2 o0 = *d0;
                o0.x += acc2[mt][nt][0] * i0;
                o0.y += acc2[mt][nt][1] * i0;
                *d0 = o0;
                float2* d1 = (float2*)&attn[(long)(row0 + rl + 8) * DIM + c];
                float2 o1 = *d1;
                o1.x += acc2[mt][nt][2] * i1;
                o1.y += acc2[mt][nt][3] * i1;
                *d1 = o1;
            }
    }
}

// ---------------- misc kernels ----------------
__global__ void zero_kernel(float* p, long n) {
    long i = (long)blockIdx.x * blockDim.x + threadIdx.x;
    if (i < n) p[i] = 0.f;
}

__global__ void set_cls(float* h, const float* __restrict__ cls) {
    h[threadIdx.x] = cls[threadIdx.x];
}

__global__ void dup_rows(float* h) {
    int i = blockIdx.x * blockDim.x + threadIdx.x;
    if (i < 129*DIM) {
        int t = i / DIM, c = i % DIM;
        h[(long)(15001 + t)*DIM + c] = h[(long)(1 + t)*DIM + c];
    }
}

__global__ void __launch_bounds__(256) ln_pad(
    const float* __restrict__ h, float* __restrict__ xo,
    const float* __restrict__ g, const float* __restrict__ b)
{
    int row = blockIdx.x, tid = threadIdx.x;
    float2* out2 = (float2*)(xo + (long)row * DIM);
    if (row < PADR) { out2[tid] = make_float2(0.f, 0.f); return; }
    const float2 xv = ((const float2*)(h + (long)(row - PADR) * DIM))[tid];
    __shared__ float sm1[8], sm2[8];
    float s = xv.x + xv.y;
    #pragma unroll
    for (int o = 16; o; o >>= 1) s += __shfl_xor_sync(~0u, s, o);
    if ((tid & 31) == 0) sm1[tid >> 5] = s;
    __syncthreads();
    float mu = (sm1[0]+sm1[1]+sm1[2]+sm1[3]+sm1[4]+sm1[5]+sm1[6]+sm1[7]) * (1.f/DIM);
    float d0 = xv.x - mu, d1 = xv.y - mu;
    float v = d0*d0 + d1*d1;
    #pragma unroll
    for (int o = 16; o; o >>= 1) v += __shfl_xor_sync(~0u, v, o);
    if ((tid & 31) == 0) sm2[tid >> 5] = v;
    __syncthreads();
    float var = (sm2[0]+sm2[1]+sm2[2]+sm2[3]+sm2[4]+sm2[5]+sm2[6]+sm2[7]) * (1.f/DIM);
    float rstd = rsqrtf(var + 1e-5f);
    float2 gg = ((const float2*)g)[tid];
    float2 bb = ((const float2*)b)[tid];
    out2[tid] = make_float2(d0*rstd*gg.x + bb.x, d1*rstd*gg.y + bb.y);
}

__global__ void landmarks_k(const float* __restrict__ qkv,
                            float* __restrict__ QL, float* __restrict__ KL)
{
    int idx = blockIdx.x * blockDim.x + threadIdx.x;
    if (idx >= HEADS*NL*DH) return;
    int h = idx / (NL*DH);
    int j = (idx / DH) % NL;
    int d = idx % DH;
    const float* qb = qkv + (long)(j*LCH)*QKVD + h*DH + d;
    const float* kb = qb + DIM;
    float sq = 0.f, sk = 0.f;
    for (int i = 0; i < LCH; i++) { sq += qb[(long)i*QKVD]; sk += kb[(long)i*QKVD]; }
    QL[idx] = sq * (1.f/LCH);
    KL[idx] = sk * (1.f/LCH);
}

__global__ void __launch_bounds__(128) softmax256(float* __restrict__ X) {
    long r = blockIdx.x;
    float2* x = (float2*)(X + r * (long)NL);
    int tid = threadIdx.x;
    float2 v = x[tid];
    __shared__ float sm[4];
    float m = fmaxf(v.x, v.y);
    #pragma unroll
    for (int o = 16; o; o >>= 1) m = fmaxf(m, __shfl_xor_sync(~0u, m, o));
    if ((tid & 31) == 0) sm[tid >> 5] = m;
    __syncthreads();
    m = fmaxf(fmaxf(sm[0], sm[1]), fmaxf(sm[2], sm[3]));
    __syncthreads();
    v.x = expf(v.x - m); v.y = expf(v.y - m);
    float s = v.x + v.y;
    #pragma unroll
    for (int o = 16; o; o >>= 1) s += __shfl_xor_sync(~0u, s, o);
    if ((tid & 31) == 0) sm[tid >> 5] = s;
    __syncthreads();
    float inv = 1.f / (sm[0]+sm[1]+sm[2]+sm[3]);
    x[tid] = make_float2(v.x * inv, v.y * inv);
}

__global__ void __launch_bounds__(256) softmax_wide(float* __restrict__ X) {
    long r = blockIdx.x;
    float* x = X + r * (long)NPAD;
    int tid = threadIdx.x;
    float4 v[15];
    #pragma unroll
    for (int i = 0; i < 15; i++) v[i] = *(float4*)&x[tid*4 + i*1024];
    __shared__ float sm[8];
    float m = -1e30f;
    #pragma unroll
    for (int i = 0; i < 15; i++)
        m = fmaxf(m, fmaxf(fmaxf(v[i].x, v[i].y), fmaxf(v[i].z, v[i].w)));
    #pragma unroll
    for (int o = 16; o; o >>= 1) m = fmaxf(m, __shfl_xor_sync(~0u, m, o));
    if ((tid & 31) == 0) sm[tid >> 5] = m;
    __syncthreads();
    m = fmaxf(fmaxf(fmaxf(sm[0],sm[1]),fmaxf(sm[2],sm[3])),
              fmaxf(fmaxf(sm[4],sm[5]),fmaxf(sm[6],sm[7])));
    __syncthreads();
    float s = 0.f;
    #pragma unroll
    for (int i = 0; i < 15; i++) {
        v[i].x = expf(v[i].x - m); v[i].y = expf(v[i].y - m);
        v[i].z = expf(v[i].z - m); v[i].w = expf(v[i].w - m);
        s += v[i].x + v[i].y + v[i].z + v[i].w;
    }
    #pragma unroll
    for (int o = 16; o; o >>= 1) s += __shfl_xor_sync(~0u, s, o);
    if ((tid & 31) == 0) sm[tid >> 5] = s;
    __syncthreads();
    float inv = 1.f / (sm[0]+sm[1]+sm[2]+sm[3]+sm[4]+sm[5]+sm[6]+sm[7]);
    #pragma unroll
    for (int i = 0; i < 15; i++) {
        v[i].x *= inv; v[i].y *= inv; v[i].z *= inv; v[i].w *= inv;
        *(float4*)&x[tid*4 + i*1024] = v[i];
    }
}

// depthwise conv(k=33) on V view; WRITES attn (attn1_fused accumulates after)
__global__ void __launch_bounds__(512) res_conv2(
    float* __restrict__ attn, const float* __restrict__ qkv,
    const float* __restrict__ w)
{
    int t0 = blockIdx.x * 8;
    int ch = threadIdx.x;
    int h = ch >> 6;
    float wk[33];
    #pragma unroll
    for (int k = 0; k < 33; k++) wk[k] = w[h*33 + k];
    float v[40];
    #pragma unroll
    for (int j = 0; j < 40; j++) {
        int tt = t0 + j - 16;
        v[j] = (tt >= 0 && tt < NPAD) ? qkv[(long)tt*QKVD + 2*DIM + ch] : 0.f;
    }
    #pragma unroll
    for (int j = 0; j < 8; j++) {
        float s = 0.f;
        #pragma unroll
        for (int k = 0; k < 33; k++) s += wk[k] * v[j + k];
        attn[(long)(t0 + j)*DIM + ch] = s;
    }
}

#define PPP 16
__global__ void __launch_bounds__(128) ppeg2(
    const float* __restrict__ h, float* __restrict__ out,
    const float* __restrict__ w7, const float* __restrict__ b7,
    const float* __restrict__ w5, const float* __restrict__ b5,
    const float* __restrict__ w3, const float* __restrict__ b3)
{
    __shared__ float wc[49][128];
    int tid = threadIdx.x;
    int ch = blockIdx.y * 128 + tid;
    #pragma unroll
    for (int k = 0; k < 49; k++) {
        int dy = k / 7 - 3, dx = k % 7 - 3;
        float wv = w7[(long)ch*49 + k];
        if (dy >= -2 && dy <= 2 && dx >= -2 && dx <= 2)
            wv += w5[(long)ch*25 + (dy+2)*5 + (dx+2)];
        if (dy >= -1 && dy <= 1 && dx >= -1 && dx <= 1)
            wv += w3[(long)ch*9 + (dy+1)*3 + (dx+1)];
        if (k == 24) wv += 1.f;
        wc[k][tid] = wv;
    }
    float bias_c = b7[ch] + b5[ch] + b3[ch];
    __syncthreads();

    int p0 = blockIdx.x * PPP;
    #pragma unroll 1
    for (int pp = 0; pp < PPP; pp++) {
        int p = p0 + pp;
        if (p >= NPIX) break;
        int r = p / IMGH, c = p % IMGH;
        float acc = bias_c;
        if (r >= 3 && r < IMGH-3 && c >= 3 && c < IMGH-3) {
            #pragma unroll
            for (int k = 0; k < 49; k++) {
                int dy = k / 7 - 3, dx = k % 7 - 3;
                acc += h[(long)(1 + (r+dy)*IMGH + (c+dx))*DIM + ch] * wc[k][tid];
            }
        } else {
            #pragma unroll
            for (int k = 0; k < 49; k++) {
                int dy = k / 7 - 3, dx = k % 7 - 3;
                int rr = r + dy, cc = c + dx;
                if (rr >= 0 && rr < IMGH && cc >= 0 && cc < IMGH)
                    acc += h[(long)(1 + rr*IMGH + cc)*DIM + ch] * wc[k][tid];
            }
        }
        out[(long)p*DIM + ch] = acc;
    }
}

__global__ void ppeg_copyback(float* __restrict__ h, const float* __restrict__ y) {
    long i = (long)blockIdx.x * blockDim.x + threadIdx.x;
    if (i < (long)NPIX*DIM) h[DIM + i] = y[i];
}

__global__ void final_head(const float* __restrict__ h, const float* __restrict__ g,
                           const float* __restrict__ b, const float* __restrict__ W,
                           const float* __restrict__ bias, float* __restrict__ out,
                           int out_size)
{
    __shared__ float red[512];
    __shared__ float xn[512];
    int tid = threadIdx.x;
    float x = h[tid];
    red[tid] = x; __syncthreads();
    for (int st = 256; st > 0; st >>= 1) {
        if (tid < st) red[tid] += red[tid+st];
        __syncthreads();
    }
    float mu = red[0] / DIM; __syncthreads();
    float d = x - mu;
    red[tid] = d*d; __syncthreads();
    for (int st = 256; st > 0; st >>= 1) {
        if (tid < st) red[tid] += red[tid+st];
        __syncthreads();
    }
    float rstd = rsqrtf(red[0]/DIM + 1e-5f); __syncthreads();
    xn[tid] = d*rstd*g[tid] + b[tid];
    __syncthreads();
    if (tid < 5) {
        float s = bias[tid];
        for (int c = 0; c < DIM; c++) s += xn[c] * W[c*5 + tid];
        red[tid] = s;
    }
    __syncthreads();
    if (tid == 0) {
        float lg[5], mx = -1e30f;
        for (int j = 0; j < 5; j++) { lg[j] = red[j]; mx = fmaxf(mx, lg[j]); }
        float se = 0.f, pr[5];
        for (int j = 0; j < 5; j++) { pr[j] = expf(lg[j]-mx); se += pr[j]; }
        int am = 0;
        for (int j = 1; j < 5; j++) if (lg[j] > lg[am]) am = j;
        for (int j = 0; j < 5; j++) {
            if (j < out_size)     out[j]     = lg[j];
            if (5 + j < out_size) out[5 + j] = pr[j]/se;
        }
        if (10 < out_size) out[10] = (float)am;
        for (int j = 11; j < out_size; j++) out[j] = 0.f;
    }
}

// ---------------- host orchestration ----------------
struct Ptrs {
    float *h, *xln, *qkv, *QL, *KL, *A3;
    float *S2, *XZ, *T1, *T2, *Z, *Z2, *T, *U, *attn, *y, *scal;
};

static void get_ptrs(Ptrs& P) {
    cudaGetSymbolAddress((void**)&P.h,    g_h);
    cudaGetSymbolAddress((void**)&P.xln,  g_xln);
    cudaGetSymbolAddress((void**)&P.qkv,  g_qkv);
    cudaGetSymbolAddress((void**)&P.QL,   g_QL);
    cudaGetSymbolAddress((void**)&P.KL,   g_KL);
    cudaGetSymbolAddress((void**)&P.A3,   g_A3);
    cudaGetSymbolAddress((void**)&P.S2,   g_S2);
    cudaGetSymbolAddress((void**)&P.XZ,   g_XZ);
    cudaGetSymbolAddress((void**)&P.T1,   g_T1);
    cudaGetSymbolAddress((void**)&P.T2,   g_T2);
    cudaGetSymbolAddress((void**)&P.Z,    g_Zb);
    cudaGetSymbolAddress((void**)&P.Z2,   g_Z2b);
    cudaGetSymbolAddress((void**)&P.T,    g_Tb);
    cudaGetSymbolAddress((void**)&P.U,    g_Ub);
    cudaGetSymbolAddress((void**)&P.attn, g_attn);
    cudaGetSymbolAddress((void**)&P.y,    g_y);
    cudaGetSymbolAddress((void**)&P.scal, g_scal);
}

#define MMA_BIG_NN  gemm_mma<128,128,64,32,false,false>
#define MMA_BIG_NT  gemm_mma<128,128,64,32,true ,false>
#define MMA_SM_NN   gemm_mma<64,64,32,32,false,false>
#define MMA_SM_NT   gemm_mma<64,64,32,32,true ,false>
#define MMA_SM_SPK  gemm_mma<64,64,32,32,false,true >

static inline dim3 grid128(int M, int N, int batch) {
    return dim3(N / 128, (M + 127) / 128, batch);
}
static inline dim3 grid64(int M, int N, int batch) {
    return dim3(N / 64, (M + 63) / 64, batch);
}

static void run_attention(const Ptrs& P, const float* lng, const float* lnb,
                          const float* Wqkv, const float* Wout, const float* bout,
                          const float* resw)
{
    const long sLnd = (long)NL*DH;
    const long sQ   = (long)NL*NL;
    const float QS = 0.125f;

    const float* Kv = P.qkv + DIM;
    const float* Vv = P.qkv + 2*DIM;

    ln_pad<<<NPAD, 256>>>(P.h, P.xln, lng, lnb);
    MMA_BIG_NN<<<grid128(NPAD, 3*DIM, 1), 256>>>(
        P.xln, Wqkv, P.qkv, NPAD, 3*DIM, DIM, DIM, 3*DIM, 3*DIM,
        0, 0, 0, 1.f, 0.f, 0.f, nullptr, 0);
    // residual conv writes attn (=); attn1_fused accumulates later
    res_conv2<<<NPAD/8, 512>>>(P.attn, P.qkv, resw);
    landmarks_k<<<(HEADS*NL*DH + 255)/256, 256>>>(P.qkv, P.QL, P.KL);
    // sim2 + softmax + pinv
    MMA_SM_NT<<<grid64(NL, NL, HEADS), 128>>>(
        P.QL, P.KL, P.S2, NL, NL, DH, DH, DH, NL,
        sLnd, sLnd, sQ, QS, 0.f, 0.f, nullptr, 0);
    softmax256<<<HEADS*NL, 128>>>(P.S2);
    pinv_persist<<<PBLOCKS, 128>>>(P.S2, P.Z, P.Z2, P.XZ, P.T1, P.T2, P.scal);
    // a3 = softmax(QL @ K^T)
    MMA_BIG_NT<<<grid128(NL, NPAD, HEADS), 256>>>(
        P.QL, Kv, P.A3, NL, NPAD, DH, DH, QKVD, NPAD,
        sLnd, (long)DH, (long)NL*NPAD, QS, 0.f, 0.f, nullptr, 0);
    softmax_wide<<<HEADS*NL, 256>>>(P.A3);
    // T = a3 @ V (split-K)
    zero_kernel<<<(HEADS*NL*DH + 255)/256, 256>>>(P.T, (long)HEADS*NL*DH);
    MMA_SM_SPK<<<grid64(NL, DH, HEADS*NSPLIT), 128>>>(
        P.A3, Vv, P.T, NL, DH, NPAD, NPAD, QKVD, DH,
        (long)NL*NPAD, (long)DH, sLnd, 1.f, 0.f, 0.f, nullptr, 0);
    // U = a2_inv @ T
    MMA_SM_NN<<<grid64(NL, DH, HEADS), 128>>>(
        P.Z, P.T, P.U, NL, DH, NL, NL, DH, DH,
        sQ, sLnd, sLnd, 1.f, 0.f, 0.f, nullptr, 0);
    // fused a1: attn += softmax(0.125 Q@KL^T) @ U
    attn1_fused<<<dim3(NPAD/64, HEADS), 128, A1_SMEMB>>>(P.qkv, P.KL, P.U, P.attn);
    // out projection with fused residual add into h (mode 2)
    MMA_BIG_NN<<<grid128(NPAD, DIM, 1), 256>>>(
        P.attn, Wout, P.h, NPAD, DIM, DIM, DIM, DIM, DIM,
        0, 0, 0, 1.f, 0.f, 0.f, bout, 2);
}

extern "C" void kernel_launch(void* const* d_in, const int* in_sizes, int n_in,
                              void* d_out, int out_size)
{
    const float* data      = (const float*)d_in[0];
    const float* W_fc1     = (const float*)d_in[1];
    const float* b_fc1     = (const float*)d_in[2];
    const float* cls_token = (const float*)d_in[3];
    const float* ln1_g     = (const float*)d_in[4];
    const float* ln1_b     = (const float*)d_in[5];
    const float* qkv1      = (const float*)d_in[6];
    const float* out1_w    = (const float*)d_in[7];
    const float* out1_b    = (const float*)d_in[8];
    const float* res1      = (const float*)d_in[9];
    const float* w7        = (const float*)d_in[10];
    const float* b7        = (const float*)d_in[11];
    const float* w5        = (const float*)d_in[12];
    const float* b5        = (const float*)d_in[13];
    const float* w3        = (const float*)d_in[14];
    const float* b3        = (const float*)d_in[15];
    const float* ln2_g     = (const float*)d_in[16];
    const float* ln2_b     = (const float*)d_in[17];
    const float* qkv2      = (const float*)d_in[18];
    const float* out2_w    = (const float*)d_in[19];
    const float* out2_b    = (const float*)d_in[20];
    const float* res2      = (const float*)d_in[21];
    const float* norm_g    = (const float*)d_in[22];
    const float* norm_b    = (const float*)d_in[23];
    const float* W_fc2     = (const float*)d_in[24];
    const float* b_fc2     = (const float*)d_in[25];

    Ptrs P;
    get_ptrs(P);

    cudaFuncSetAttribute(attn1_fused,
        cudaFuncAttributeMaxDynamicSharedMemorySize, A1_SMEMB);

    set_cls<<<1, DIM>>>(P.h, cls_token);
    MMA_BIG_NN<<<grid128(15000, DIM, 1), 256>>>(
        data, W_fc1, P.h + DIM, 15000, DIM, 1024, 1024, DIM, DIM,
        0, 0, 0, 1.f, 0.f, 0.f, b_fc1, 1);
    dup_rows<<<(129*DIM + 255)/256, 256>>>(P.h);

    run_attention(P, ln1_g, ln1_b, qkv1, out1_w, out1_b, res1);

    ppeg2<<<dim3((NPIX + PPP - 1)/PPP, DIM/128), 128>>>(
        P.h, P.y, w7, b7, w5, b5, w3, b3);
    ppeg_copyback<<<(int)(((long)NPIX*DIM + 255)/256), 256>>>(P.h, P.y);

    run_attention(P, ln2_g, ln2_b, qkv2, out2_w, out2_b, res2);

    final_head<<<1, DIM>>>(P.h, norm_g, norm_b, W_fc2, b_fc2, (float*)d_out, out_size);
}

// round 9
// speedup vs baseline: 3.3108x; 1.0344x over previous
#include <cuda_runtime.h>
#include <math.h>
#include <stdint.h>

#define HEADS 8
#define DH    64
#define DIM   512
#define QKVD  1536
#define NTOK  15130
#define NPAD  15360
#define PADR  230
#define NL    256
#define LCH   60
#define IMGH  123
#define NPIX  15129
#define NSPLIT 16
#define PBLOCKS 128

// ---------------- static scratch (allocation-free rule) ----------------
__device__ __align__(16) float g_h   [NTOK*DIM];
__device__ __align__(16) float g_xln [NPAD*DIM];
__device__ __align__(16) float g_qkv [NPAD*3*DIM];
__device__ __align__(16) float g_QL  [HEADS*NL*DH];
__device__ __align__(16) float g_KL  [HEADS*NL*DH];
__device__ __align__(16) float g_A3  [HEADS*NL*NPAD];
__device__ __align__(16) float g_S2  [HEADS*NL*NL];
__device__ __align__(16) float g_XZ  [HEADS*NL*NL];
__device__ __align__(16) float g_T1  [HEADS*NL*NL];
__device__ __align__(16) float g_T2  [HEADS*NL*NL];
__device__ __align__(16) float g_Zb  [HEADS*NL*NL];
__device__ __align__(16) float g_Z2b [HEADS*NL*NL];
__device__ __align__(16) float g_Tb  [HEADS*NL*DH];
__device__ __align__(16) float g_Ub  [HEADS*NL*DH];
__device__ __align__(16) float g_attn[NPAD*DIM];
__device__ __align__(16) float g_y   [NPAD*DIM];
__device__ float g_scal[2];
__device__ unsigned g_bar_cnt = 0;
__device__ volatile unsigned g_bar_gen = 0;

// ================= bf16 split primitives =================
// pack two floats into bf16x2: x0 -> low half (lower k index), x1 -> high half
__device__ __forceinline__ uint32_t pkbf(float x0, float x1) {
    uint32_t r;
    asm("cvt.rn.bf16x2.f32 %0, %1, %2;" : "=r"(r) : "f"(x1), "f"(x0));
    return r;
}
__device__ __forceinline__ float unlo(uint32_t p) {
    return __uint_as_float(p << 16);
}
__device__ __forceinline__ float unhi(uint32_t p) {
    return __uint_as_float(p & 0xFFFF0000u);
}
__device__ __forceinline__ void bsplit4(float4 v,
    uint32_t& h0, uint32_t& h1, uint32_t& l0, uint32_t& l1)
{
    h0 = pkbf(v.x, v.y);
    h1 = pkbf(v.z, v.w);
    l0 = pkbf(v.x - unlo(h0), v.y - unhi(h0));
    l1 = pkbf(v.z - unlo(h1), v.w - unhi(h1));
}
__device__ __forceinline__ void bsplit2(float x0, float x1, uint32_t& h, uint32_t& l) {
    h = pkbf(x0, x1);
    l = pkbf(x0 - unlo(h), x1 - unhi(h));
}
__device__ __forceinline__ void mma16(float* d,
    uint32_t a0, uint32_t a1, uint32_t a2, uint32_t a3,
    uint32_t b0, uint32_t b1)
{
    asm volatile("mma.sync.aligned.m16n8k16.row.col.f32.bf16.bf16.f32 "
        "{%0,%1,%2,%3},{%4,%5,%6,%7},{%8,%9},{%0,%1,%2,%3};"
        : "+f"(d[0]), "+f"(d[1]), "+f"(d[2]), "+f"(d[3])
        : "r"(a0), "r"(a1), "r"(a2), "r"(a3), "r"(b0), "r"(b1));
}
__device__ __forceinline__ void mma16_split(float* acc,
    const uint32_t* Ah, const uint32_t* Al, const uint32_t* Bh, const uint32_t* Bl)
{
    mma16(acc, Ah[0],Ah[1],Ah[2],Ah[3], Bh[0],Bh[1]);
    mma16(acc, Ah[0],Ah[1],Ah[2],Ah[3], Bl[0],Bl[1]);
    mma16(acc, Al[0],Al[1],Al[2],Al[3], Bh[0],Bh[1]);
}

#define PADS 4

// ================= generic bf16-split GEMM (batched, NN/NT, split-K) ============
template<int BM, int BN, int WM, int WN, bool NT, bool SPLITK>
__global__ void __launch_bounds__((BM/WM)*(BN/WN)*32)
gemm_mma(const float* __restrict__ A, const float* __restrict__ B,
         float* __restrict__ C,
         int M, int N, int K, int lda, int ldb, int ldc,
         long sA, long sB, long sC,
         float alpha, float beta_diag, float gammaA,
         const float* __restrict__ bias, int mode)
{
    constexpr int NWARP = (BM/WM)*(BN/WN);
    constexpr int T = NWARP * 32;
    constexpr int NWN = BN / WN;
    constexpr int MT = WM / 16, NTL = WN / 8;
    static_assert(T == 8 * (BN / 4), "B-NN loader mapping requires T == 2*BN");

    int z = blockIdx.z;
    int kbeg = 0, kend = K;
    if (SPLITK) {
        int batch = z / NSPLIT, split = z % NSPLIT;
        A += (long)batch * sA; B += (long)batch * sB; C += (long)batch * sC;
        int chunk = K / NSPLIT;
        kbeg = split * chunk; kend = kbeg + chunk;
    } else {
        A += (long)z * sA; B += (long)z * sB; C += (long)z * sC;
    }

    __shared__ __align__(16) uint32_t sAh[2][8][BM + PADS];
    __shared__ __align__(16) uint32_t sAl[2][8][BM + PADS];
    __shared__ __align__(16) uint32_t sBh[2][8][BN + PADS];
    __shared__ __align__(16) uint32_t sBl[2][8][BN + PADS];

    const int tid = threadIdx.x;
    const int wid = tid >> 5, lane = tid & 31;
    const int g = lane >> 2, t = lane & 3;
    const int row0 = blockIdx.y * BM;
    const int col0 = blockIdx.x * BN;
    const int wm0 = (wid / NWN) * WM;
    const int wn0 = (wid % NWN) * WN;

    float4 ra[2], rb[2];

    auto load_g = [&](int k0) {
        #pragma unroll
        for (int it = 0; it < 2; it++) {
            int i = tid + it * T;
            int m = i >> 2, kq = (i & 3) * 4;
            int gm = row0 + m;
            ra[it] = make_float4(0.f, 0.f, 0.f, 0.f);
            if (gm < M) ra[it] = *(const float4*)&A[(long)gm * lda + k0 + kq];
        }
        if (!NT) {
            int k2 = tid / (BN / 4), ng = (tid % (BN / 4)) * 4;
            rb[0] = *(const float4*)&B[(long)(k0 + 2*k2)     * ldb + col0 + ng];
            rb[1] = *(const float4*)&B[(long)(k0 + 2*k2 + 1) * ldb + col0 + ng];
        } else {
            #pragma unroll
            for (int it = 0; it < 2; it++) {
                int i = tid + it * T;
                int n = i >> 2, kq = (i & 3) * 4;
                rb[it] = make_float4(0.f, 0.f, 0.f, 0.f);
                if (col0 + n < N)
                    rb[it] = *(const float4*)&B[(long)(col0 + n) * ldb + k0 + kq];
            }
        }
    };
    auto store_s = [&](int buf) {
        #pragma unroll
        for (int it = 0; it < 2; it++) {
            int i = tid + it * T;
            int m = i >> 2, kp = (i & 3) * 2;
            uint32_t h0, h1, l0, l1;
            bsplit4(ra[it], h0, h1, l0, l1);
            sAh[buf][kp][m]     = h0;
            sAh[buf][kp + 1][m] = h1;
            sAl[buf][kp][m]     = l0;
            sAl[buf][kp + 1][m] = l1;
        }
        if (!NT) {
            int k2 = tid / (BN / 4), ng = (tid % (BN / 4)) * 4;
            const float* v0 = &rb[0].x;
            const float* v1 = &rb[1].x;
            uint32_t hh[4], ll[4];
            #pragma unroll
            for (int q = 0; q < 4; q++) {
                uint32_t h = pkbf(v0[q], v1[q]);
                hh[q] = h;
                ll[q] = pkbf(v0[q] - unlo(h), v1[q] - unhi(h));
            }
            *(uint4*)&sBh[buf][k2][ng] = *(uint4*)hh;
            *(uint4*)&sBl[buf][k2][ng] = *(uint4*)ll;
        } else {
            #pragma unroll
            for (int it = 0; it < 2; it++) {
                int i = tid + it * T;
                int n = i >> 2, kp = (i & 3) * 2;
                uint32_t h0, h1, l0, l1;
                bsplit4(rb[it], h0, h1, l0, l1);
                sBh[buf][kp][n]     = h0;
                sBh[buf][kp + 1][n] = h1;
                sBl[buf][kp][n]     = l0;
                sBl[buf][kp + 1][n] = l1;
            }
        }
    };

    float acc[MT][NTL][4];
    #pragma unroll
    for (int i = 0; i < MT; i++)
        #pragma unroll
        for (int j = 0; j < NTL; j++)
            #pragma unroll
            for (int q = 0; q < 4; q++) acc[i][j][q] = 0.f;

    const int ntiles = (kend - kbeg) / 16;
    load_g(kbeg);
    store_s(0);
    __syncthreads();

    for (int kt = 0; kt < ntiles; kt++) {
        if (kt + 1 < ntiles) load_g(kbeg + (kt + 1) * 16);
        int buf = kt & 1;
        {
            uint32_t Ahf[MT][4], Alf[MT][4], Bhf[NTL][2], Blf[NTL][2];
            #pragma unroll
            for (int mt = 0; mt < MT; mt++) {
                int mb = wm0 + mt * 16 + g;
                Ahf[mt][0] = sAh[buf][t    ][mb];
                Ahf[mt][1] = sAh[buf][t    ][mb + 8];
                Ahf[mt][2] = sAh[buf][t + 4][mb];
                Ahf[mt][3] = sAh[buf][t + 4][mb + 8];
                Alf[mt][0] = sAl[buf][t    ][mb];
                Alf[mt][1] = sAl[buf][t    ][mb + 8];
                Alf[mt][2] = sAl[buf][t + 4][mb];
                Alf[mt][3] = sAl[buf][t + 4][mb + 8];
            }
            #pragma unroll
            for (int nt = 0; nt < NTL; nt++) {
                int nb = wn0 + nt * 8 + g;
                Bhf[nt][0] = sBh[buf][t    ][nb];
                Bhf[nt][1] = sBh[buf][t + 4][nb];
                Blf[nt][0] = sBl[buf][t    ][nb];
                Blf[nt][1] = sBl[buf][t + 4][nb];
            }
            #pragma unroll
            for (int mt = 0; mt < MT; mt++)
                #pragma unroll
                for (int nt = 0; nt < NTL; nt++)
                    mma16_split(acc[mt][nt], Ahf[mt], Alf[mt], Bhf[nt], Blf[nt]);
        }
        if (kt + 1 < ntiles) {
            store_s((kt + 1) & 1);
            __syncthreads();
        }
    }

    auto emit = [&](int r, int c, float v0, float v1) {
        if (r >= M) return;
        v0 *= alpha; v1 *= alpha;
        if (bias) { v0 += bias[c]; v1 += bias[c + 1]; }
        if (beta_diag != 0.f) {
            if (r == c)     v0 += beta_diag;
            if (r == c + 1) v1 += beta_diag;
        }
        if (gammaA != 0.f) {
            v0 += gammaA * A[(long)r * lda + c];
            v1 += gammaA * A[(long)r * lda + c + 1];
        }
        if (mode == 1) { v0 = fmaxf(v0, 0.f); v1 = fmaxf(v1, 0.f); }
        if (SPLITK) {
            atomicAdd(&C[(long)r * ldc + c], v0);
            atomicAdd(&C[(long)r * ldc + c + 1], v1);
        } else if (mode == 2) {
            if (r >= PADR) {
                float2* dst = (float2*)&C[(long)(r - PADR) * ldc + c];
                float2 o = *dst;
                o.x += v0; o.y += v1;
                *dst = o;
            }
        } else {
            *(float2*)&C[(long)r * ldc + c] = make_float2(v0, v1);
        }
    };
    #pragma unroll
    for (int mt = 0; mt < MT; mt++)
        #pragma unroll
        for (int nt = 0; nt < NTL; nt++) {
            int r = row0 + wm0 + mt * 16 + g;
            int c = col0 + wn0 + nt * 8 + 2 * t;
            emit(r,     c, acc[mt][nt][0], acc[mt][nt][1]);
            emit(r + 8, c, acc[mt][nt][2], acc[mt][nt][3]);
        }
}

// ================= persistent pinv kernel (bf16 split) =================
__device__ __forceinline__ void atomicMaxFloatPos(float* addr, float v) {
    atomicMax((int*)addr, __float_as_int(v));
}

__device__ __forceinline__ void gridbar() {
    __syncthreads();
    if (threadIdx.x == 0) {
        unsigned gen = g_bar_gen;
        __threadfence();
        if (atomicAdd(&g_bar_cnt, 1u) == PBLOCKS - 1) {
            g_bar_cnt = 0;
            __threadfence();
            g_bar_gen = gen + 1;
        } else {
            while (g_bar_gen == gen) { __nanosleep(64); }
        }
        __threadfence();
    }
    __syncthreads();
}

typedef uint32_t pktile[2][8][68];

// 64x64 tile of C = alpha*A@B + beta_diag*I + gammaA*A, A/B/C 256x256 row-major.
// bf16-split packed smem tiles; identical fragment mapping to gemm_mma (NN).
__device__ __noinline__ void gemm64_dev(
    const float* __restrict__ A, const float* __restrict__ B, float* __restrict__ C,
    int row0, int col0, float alpha, float beta_diag, float gammaA,
    pktile& Ah, pktile& Al, pktile& Bh, pktile& Bl)
{
    const int tid = threadIdx.x;
    const int wid = tid >> 5, lane = tid & 31;
    const int g = lane >> 2, t = lane & 3;
    const int wm0 = (wid >> 1) * 32, wn0 = (wid & 1) * 32;

    float4 ra[2], rb0, rb1;
    const int k2 = tid >> 4, ng = (tid & 15) * 4;

    auto load_g = [&](int k0) {
        #pragma unroll
        for (int it = 0; it < 2; it++) {
            int i = tid + it * 128;
            int m = i >> 2, kq = (i & 3) * 4;
            ra[it] = *(const float4*)&A[(long)(row0 + m) * 256 + k0 + kq];
        }
        rb0 = *(const float4*)&B[(long)(k0 + 2*k2)     * 256 + col0 + ng];
        rb1 = *(const float4*)&B[(long)(k0 + 2*k2 + 1) * 256 + col0 + ng];
    };
    auto store_s = [&](int buf) {
        #pragma unroll
        for (int it = 0; it < 2; it++) {
            int i = tid + it * 128;
            int m = i >> 2, kp = (i & 3) * 2;
            uint32_t h0, h1, l0, l1;
            bsplit4(ra[it], h0, h1, l0, l1);
            Ah[buf][kp][m]     = h0;
            Ah[buf][kp + 1][m] = h1;
            Al[buf][kp][m]     = l0;
            Al[buf][kp + 1][m] = l1;
        }
        const float* v0 = &rb0.x;
        const float* v1 = &rb1.x;
        uint32_t hh[4], ll[4];
        #pragma unroll
        for (int q = 0; q < 4; q++) {
            uint32_t h = pkbf(v0[q], v1[q]);
            hh[q] = h;
            ll[q] = pkbf(v0[q] - unlo(h), v1[q] - unhi(h));
        }
        *(uint4*)&Bh[buf][k2][ng] = *(uint4*)hh;
        *(uint4*)&Bl[buf][k2][ng] = *(uint4*)ll;
    };

    float acc[2][4][4] = {};
    load_g(0);
    store_s(0);
    __syncthreads();
    for (int kt = 0; kt < 16; kt++) {
        if (kt + 1 < 16) load_g((kt + 1) * 16);
        int buf = kt & 1;
        {
            uint32_t Ahf[2][4], Alf[2][4], Bhf[4][2], Blf[4][2];
            #pragma unroll
            for (int mt = 0; mt < 2; mt++) {
                int mb = wm0 + mt * 16 + g;
                Ahf[mt][0] = Ah[buf][t    ][mb];
                Ahf[mt][1] = Ah[buf][t    ][mb + 8];
                Ahf[mt][2] = Ah[buf][t + 4][mb];
                Ahf[mt][3] = Ah[buf][t + 4][mb + 8];
                Alf[mt][0] = Al[buf][t    ][mb];
                Alf[mt][1] = Al[buf][t    ][mb + 8];
                Alf[mt][2] = Al[buf][t + 4][mb];
                Alf[mt][3] = Al[buf][t + 4][mb + 8];
            }
            #pragma unroll
            for (int nt = 0; nt < 4; nt++) {
                int nb = wn0 + nt * 8 + g;
                Bhf[nt][0] = Bh[buf][t    ][nb];
                Bhf[nt][1] = Bh[buf][t + 4][nb];
                Blf[nt][0] = Bl[buf][t    ][nb];
                Blf[nt][1] = Bl[buf][t + 4][nb];
            }
            #pragma unroll
            for (int mt = 0; mt < 2; mt++)
                #pragma unroll
                for (int nt = 0; nt < 4; nt++)
                    mma16_split(acc[mt][nt], Ahf[mt], Alf[mt], Bhf[nt], Blf[nt]);
        }
        if (kt + 1 < 16) {
            store_s((kt + 1) & 1);
            __syncthreads();
        }
    }
    #pragma unroll
    for (int mt = 0; mt < 2; mt++)
        #pragma unroll
        for (int nt = 0; nt < 4; nt++) {
            int r0 = row0 + wm0 + mt * 16 + g;
            int c = col0 + wn0 + nt * 8 + 2 * t;
            #pragma unroll
            for (int half = 0; half < 2; half++) {
                int r = r0 + half * 8;
                float v0 = alpha * acc[mt][nt][half*2 + 0];
                float v1 = alpha * acc[mt][nt][half*2 + 1];
                if (beta_diag != 0.f) {
                    if (r == c)     v0 += beta_diag;
                    if (r == c + 1) v1 += beta_diag;
                }
                if (gammaA != 0.f) {
                    v0 += gammaA * A[(long)r * 256 + c];
                    v1 += gammaA * A[(long)r * 256 + c + 1];
                }
                *(float2*)&C[(long)r * 256 + c] = make_float2(v0, v1);
            }
        }
    __syncthreads();
}

__global__ void __launch_bounds__(128) pinv_persist(
    const float* __restrict__ S2, float* __restrict__ Z, float* __restrict__ Z2,
    float* __restrict__ XZ, float* __restrict__ T1, float* __restrict__ T2,
    float* __restrict__ scal)
{
    __shared__ __align__(16) uint32_t Ah[2][8][68], Al[2][8][68];
    __shared__ __align__(16) uint32_t Bh[2][8][68], Bl[2][8][68];
    const int b = blockIdx.x, tid = threadIdx.x;
    const int wid = tid >> 5, lane = tid & 31;

    if (b == 0 && tid < 2) scal[tid] = 0.f;
    gridbar();

    for (int q = 0; q < 8; q++) {
        int idx = b * 32 + wid * 8 + q;
        int mode = idx >> 11, rem = idx & 2047;
        int h = rem >> 8, i = rem & 255;
        const float* base = S2 + (long)h * 65536;
        float s = 0.f;
        if (mode == 0) { for (int j = lane; j < 256; j += 32) s += fabsf(base[i * 256 + j]); }
        else           { for (int j = lane; j < 256; j += 32) s += fabsf(base[j * 256 + i]); }
        #pragma unroll
        for (int o = 16; o; o >>= 1) s += __shfl_xor_sync(~0u, s, o);
        if (lane == 0) atomicMaxFloatPos(&scal[mode], s);
    }
    gridbar();

    float denom = scal[0] * scal[1];
    for (int l = 0; l < 32; l++) {
        int idx = b * 4096 + l * 128 + tid;
        int h = idx >> 16, rc = idx & 65535, r = rc >> 8, c = rc & 255;
        Z[idx] = S2[(long)h * 65536 + (long)c * 256 + r] / denom;
    }
    gridbar();

    const int head = b >> 4, tt = b & 15;
    const int row0 = (tt >> 2) * 64, col0 = (tt & 3) * 64;
    const long ho = (long)head * 65536;

    for (int it = 0; it < 6; it++) {
        float* zin  = (it & 1) ? Z2 : Z;
        float* zout = (it & 1) ? Z  : Z2;
        gemm64_dev(S2 + ho, zin + ho, XZ + ho, row0, col0, 1.f, 0.f, 0.f, Ah, Al, Bh, Bl);
        gridbar();
        gemm64_dev(XZ + ho, XZ + ho, T2 + ho, row0, col0, 1.f, 15.f, -7.f, Ah, Al, Bh, Bl);
        gridbar();
        gemm64_dev(XZ + ho, T2 + ho, T1 + ho, row0, col0, -1.f, 13.f, 0.f, Ah, Al, Bh, Bl);
        gridbar();
        gemm64_dev(zin + ho, T1 + ho, zout + ho, row0, col0, 0.25f, 0.f, 0.f, Ah, Al, Bh, Bl);
        gridbar();
    }
}

// ================= fused a1 attention (bf16 split): attn += softmax(P)@U ========
// smem layout (4B units):
//   region0 (0..20991):   AQh[32*68] AQl[32*68] BKh[32*260] BKl[32*260]
//                         (reused after MMA1 as Ph[128*68], Pl[128*68])
//   ST     (20992..):     float [256][65]
//   Uh/Ul  (37632..):     [128*68] each
//   rinv   (55040..55103)
#define A1_AQH   0
#define A1_AQL   (32*68)
#define A1_BKH   (2*32*68)
#define A1_BKL   (2*32*68 + 32*260)
#define A1_PH    0
#define A1_PL    (128*68)
#define A1_ST    20992
#define A1_UH    37632
#define A1_UL    (37632 + 128*68)
#define A1_RINV  55040
#define A1_SMEMB (55104*4)

__global__ void __launch_bounds__(128) attn1_fused(
    const float* __restrict__ qkv, const float* __restrict__ KL,
    const float* __restrict__ U, float* __restrict__ attn)
{
    extern __shared__ float sm[];
    uint32_t* AQh = (uint32_t*)sm + A1_AQH;   // [32 kp][68]
    uint32_t* AQl = (uint32_t*)sm + A1_AQL;
    uint32_t* BKh = (uint32_t*)sm + A1_BKH;   // [32 kp][260]
    uint32_t* BKl = (uint32_t*)sm + A1_BKL;
    uint32_t* Ph  = (uint32_t*)sm + A1_PH;    // [128 kp][68] (reuse)
    uint32_t* Pl  = (uint32_t*)sm + A1_PL;
    float*    ST  = sm + A1_ST;               // [256][65]
    uint32_t* Uh  = (uint32_t*)sm + A1_UH;    // [128 kp][68]
    uint32_t* Ul  = (uint32_t*)sm + A1_UL;
    float*    rinv= sm + A1_RINV;

    const int tid = threadIdx.x;
    const int wid = tid >> 5, lane = tid & 31;
    const int g = lane >> 2, t = lane & 3;
    const int h = blockIdx.y;
    const int row0 = blockIdx.x * 64;
    const float* Qg  = qkv + h * DH;
    const float* KLh = KL + (long)h * NL * DH;
    const float* Ug  = U  + (long)h * NL * DH;

    // load Q (64 rows x 64 k), pack along k
    #pragma unroll
    for (int l = 0; l < 8; l++) {
        int i = tid + l * 128;
        int m = i >> 4, kq = (i & 15) * 4;
        float4 v = *(const float4*)&Qg[(long)(row0 + m) * QKVD + kq];
        uint32_t h0, h1, l0, l1;
        bsplit4(v, h0, h1, l0, l1);
        int kp = kq >> 1;
        AQh[kp*68 + m] = h0; AQh[(kp+1)*68 + m] = h1;
        AQl[kp*68 + m] = l0; AQl[(kp+1)*68 + m] = l1;
    }
    // load KL (256 rows x 64 k), pack along k
    #pragma unroll
    for (int l = 0; l < 32; l++) {
        int i = tid + l * 128;
        int n = i >> 4, kq = (i & 15) * 4;
        float4 v = *(const float4*)&KLh[n * 64 + kq];
        uint32_t h0, h1, l0, l1;
        bsplit4(v, h0, h1, l0, l1);
        int kp = kq >> 1;
        BKh[kp*260 + n] = h0; BKh[(kp+1)*260 + n] = h1;
        BKl[kp*260 + n] = l0; BKl[(kp+1)*260 + n] = l1;
    }
    // load U (256 k x 64 n), pack across adjacent k rows
    #pragma unroll
    for (int l = 0; l < 16; l++) {
        int i = tid + l * 128;
        int kp = i >> 4, n4 = (i & 15) * 4;
        float4 v0 = *(const float4*)&Ug[(long)(2*kp)     * 64 + n4];
        float4 v1 = *(const float4*)&Ug[(long)(2*kp + 1) * 64 + n4];
        const float* p0 = &v0.x;
        const float* p1 = &v1.x;
        uint32_t hh[4], ll[4];
        #pragma unroll
        for (int q = 0; q < 4; q++) {
            uint32_t hq = pkbf(p0[q], p1[q]);
            hh[q] = hq;
            ll[q] = pkbf(p0[q] - unlo(hq), p1[q] - unhi(hq));
        }
        *(uint4*)&Uh[kp*68 + n4] = *(uint4*)hh;
        *(uint4*)&Ul[kp*68 + n4] = *(uint4*)ll;
    }
    __syncthreads();

    // MMA1: S = Q@KL^T, M=64 N=256 K=64; warps 2x2 (32 x 128 tiles)
    const int wm0 = (wid >> 1) * 32;
    const int wn1 = (wid & 1) * 128;
    {
        float acc1[2][16][4] = {};
        #pragma unroll
        for (int k16 = 0; k16 < 4; k16++) {
            int kb = k16 * 8;
            uint32_t Ahf[2][4], Alf[2][4];
            #pragma unroll
            for (int mt = 0; mt < 2; mt++) {
                int mb = wm0 + mt * 16 + g;
                Ahf[mt][0] = AQh[(kb + t    )*68 + mb];
                Ahf[mt][1] = AQh[(kb + t    )*68 + mb + 8];
                Ahf[mt][2] = AQh[(kb + t + 4)*68 + mb];
                Ahf[mt][3] = AQh[(kb + t + 4)*68 + mb + 8];
                Alf[mt][0] = AQl[(kb + t    )*68 + mb];
                Alf[mt][1] = AQl[(kb + t    )*68 + mb + 8];
                Alf[mt][2] = AQl[(kb + t + 4)*68 + mb];
                Alf[mt][3] = AQl[(kb + t + 4)*68 + mb + 8];
            }
            #pragma unroll
            for (int nt = 0; nt < 16; nt++) {
                int nb = wn1 + nt * 8 + g;
                uint32_t Bhf[2], Blf[2];
                Bhf[0] = BKh[(kb + t    )*260 + nb];
                Bhf[1] = BKh[(kb + t + 4)*260 + nb];
                Blf[0] = BKl[(kb + t    )*260 + nb];
                Blf[1] = BKl[(kb + t + 4)*260 + nb];
                mma16_split(acc1[0][nt], Ahf[0], Alf[0], Bhf, Blf);
                mma16_split(acc1[1][nt], Ahf[1], Alf[1], Bhf, Blf);
            }
        }
        // write scaled scores to ST (landmark-major)
        #pragma unroll
        for (int mt = 0; mt < 2; mt++)
            #pragma unroll
            for (int nt = 0; nt < 16; nt++) {
                int r = wm0 + mt * 16 + g;
                int c = wn1 + nt * 8 + 2 * t;
                ST[c*65 + r]       = 0.125f * acc1[mt][nt][0];
                ST[(c+1)*65 + r]   = 0.125f * acc1[mt][nt][1];
                ST[c*65 + r+8]     = 0.125f * acc1[mt][nt][2];
                ST[(c+1)*65 + r+8] = 0.125f * acc1[mt][nt][3];
            }
    }
    __syncthreads();

    // softmax over 256 landmarks per row; normalization deferred
    {
        int r = tid >> 1, half = tid & 1;
        int j0 = half * 128;
        float m = -1e30f;
        #pragma unroll 8
        for (int j = j0; j < j0 + 128; j++) m = fmaxf(m, ST[j*65 + r]);
        m = fmaxf(m, __shfl_xor_sync(~0u, m, 1));
        float s = 0.f;
        #pragma unroll 8
        for (int j = j0; j < j0 + 128; j++) {
            float e = expf(ST[j*65 + r] - m);
            ST[j*65 + r] = e;
            s += e;
        }
        s += __shfl_xor_sync(~0u, s, 1);
        if (half == 0) rinv[r] = 1.f / s;
    }
    __syncthreads();

    // repack P into packed bf16 hi/lo (overwrites AQ/BK region)
    #pragma unroll
    for (int l = 0; l < 64; l++) {
        int i = tid + l * 128;
        int kp = i >> 6, m = i & 63;
        float x0 = ST[(2*kp)     * 65 + m];
        float x1 = ST[(2*kp + 1) * 65 + m];
        uint32_t hq, lq;
        bsplit2(x0, x1, hq, lq);
        Ph[kp*68 + m] = hq;
        Pl[kp*68 + m] = lq;
    }
    __syncthreads();

    // MMA2: out = P@U, M=64 N=64 K=256
    {
        const int wn2 = (wid & 1) * 32;
        float acc2[2][4][4] = {};
        #pragma unroll 4
        for (int k16 = 0; k16 < 16; k16++) {
            int kb = k16 * 8;
            uint32_t Ahf[2][4], Alf[2][4], Bhf[4][2], Blf[4][2];
            #pragma unroll
            for (int mt = 0; mt < 2; mt++) {
                int mb = wm0 + mt * 16 + g;
                Ahf[mt][0] = Ph[(kb + t    )*68 + mb];
                Ahf[mt][1] = Ph[(kb + t    )*68 + mb + 8];
                Ahf[mt][2] = Ph[(kb + t + 4)*68 + mb];
                Ahf[mt][3] = Ph[(kb + t + 4)*68 + mb + 8];
                Alf[mt][0] = Pl[(kb + t    )*68 + mb];
                Alf[mt][1] = Pl[(kb + t    )*68 + mb + 8];
                Alf[mt][2] = Pl[(kb + t + 4)*68 + mb];
                Alf[mt][3] = Pl[(kb + t + 4)*68 + mb + 8];
            }
            #pragma unroll
            for (int nt = 0; nt < 4; nt++) {
                int nb = wn2 + nt * 8 + g;
                Bhf[nt][0] = Uh[(kb + t    )*68 + nb];
                Bhf[nt][1] = Uh[(kb + t + 4)*68 + nb];
                Blf[nt][0] = Ul[(kb + t    )*68 + nb];
                Blf[nt][1] = Ul[(kb + t + 4)*68 + nb];
            }
            #pragma unroll
            for (int mt = 0; mt < 2; mt++)
                #pragma unroll
                for (int nt = 0; nt < 4; nt++)
                    mma16_split(acc2[mt][nt], Ahf[mt], Alf[mt], Bhf[nt], Blf[nt]);
        }
        // accumulate into attn (res_conv wrote the conv residual there first)
        #pragma unroll
        for (int mt = 0; mt < 2; mt++)
            #pragma unroll
            for (int nt = 0; nt < 4; nt++) {
                int rl = wm0 + mt * 16 + g;
                int c = h * DH + wn2 + nt * 8 + 2 * t;
                float i0 = rinv[rl], i1 = rinv[rl + 8];
                float2* d0 = (float2*)&attn[(long)(row0 + rl) * DIM + c];
                float2 o0 = *d0;
                o0.x += acc2[mt][nt][0] * i0;
                o0.y += acc2[mt][nt][1] * i0;
                *d0 = o0;
                float2* d1 = (float2*)&attn[(long)(row0 + rl + 8) * DIM + c];
                float2 o1 = *d1;
                o1.x += acc2[mt][nt][2] * i1;
                o1.y += acc2[mt][nt][3] * i1;
                *d1 = o1;
            }
    }
}

// ---------------- misc kernels ----------------
__global__ void zero_kernel(float* p, long n) {
    long i = (long)blockIdx.x * blockDim.x + threadIdx.x;
    if (i < n) p[i] = 0.f;
}

__global__ void set_cls(float* h, const float* __restrict__ cls) {
    h[threadIdx.x] = cls[threadIdx.x];
}

__global__ void dup_rows(float* h) {
    int i = blockIdx.x * blockDim.x + threadIdx.x;
    if (i < 129*DIM) {
        int t = i / DIM, c = i % DIM;
        h[(long)(15001 + t)*DIM + c] = h[(long)(1 + t)*DIM + c];
    }
}

__global__ void __launch_bounds__(256) ln_pad(
    const float* __restrict__ h, float* __restrict__ xo,
    const float* __restrict__ g, const float* __restrict__ b)
{
    int row = blockIdx.x, tid = threadIdx.x;
    float2* out2 = (float2*)(xo + (long)row * DIM);
    if (row < PADR) { out2[tid] = make_float2(0.f, 0.f); return; }
    const float2 xv = ((const float2*)(h + (long)(row - PADR) * DIM))[tid];
    __shared__ float sm1[8], sm2[8];
    float s = xv.x + xv.y;
    #pragma unroll
    for (int o = 16; o; o >>= 1) s += __shfl_xor_sync(~0u, s, o);
    if ((tid & 31) == 0) sm1[tid >> 5] = s;
    __syncthreads();
    float mu = (sm1[0]+sm1[1]+sm1[2]+sm1[3]+sm1[4]+sm1[5]+sm1[6]+sm1[7]) * (1.f/DIM);
    float d0 = xv.x - mu, d1 = xv.y - mu;
    float v = d0*d0 + d1*d1;
    #pragma unroll
    for (int o = 16; o; o >>= 1) v += __shfl_xor_sync(~0u, v, o);
    if ((tid & 31) == 0) sm2[tid >> 5] = v;
    __syncthreads();
    float var = (sm2[0]+sm2[1]+sm2[2]+sm2[3]+sm2[4]+sm2[5]+sm2[6]+sm2[7]) * (1.f/DIM);
    float rstd = rsqrtf(var + 1e-5f);
    float2 gg = ((const float2*)g)[tid];
    float2 bb = ((const float2*)b)[tid];
    out2[tid] = make_float2(d0*rstd*gg.x + bb.x, d1*rstd*gg.y + bb.y);
}

__global__ void landmarks_k(const float* __restrict__ qkv,
                            float* __restrict__ QL, float* __restrict__ KL)
{
    int idx = blockIdx.x * blockDim.x + threadIdx.x;
    if (idx >= HEADS*NL*DH) return;
    int h = idx / (NL*DH);
    int j = (idx / DH) % NL;
    int d = idx % DH;
    const float* qb = qkv + (long)(j*LCH)*QKVD + h*DH + d;
    const float* kb = qb + DIM;
    float sq = 0.f, sk = 0.f;
    for (int i = 0; i < LCH; i++) { sq += qb[(long)i*QKVD]; sk += kb[(long)i*QKVD]; }
    QL[idx] = sq * (1.f/LCH);
    KL[idx] = sk * (1.f/LCH);
}

__global__ void __launch_bounds__(128) softmax256(float* __restrict__ X) {
    long r = blockIdx.x;
    float2* x = (float2*)(X + r * (long)NL);
    int tid = threadIdx.x;
    float2 v = x[tid];
    __shared__ float sm[4];
    float m = fmaxf(v.x, v.y);
    #pragma unroll
    for (int o = 16; o; o >>= 1) m = fmaxf(m, __shfl_xor_sync(~0u, m, o));
    if ((tid & 31) == 0) sm[tid >> 5] = m;
    __syncthreads();
    m = fmaxf(fmaxf(sm[0], sm[1]), fmaxf(sm[2], sm[3]));
    __syncthreads();
    v.x = expf(v.x - m); v.y = expf(v.y - m);
    float s = v.x + v.y;
    #pragma unroll
    for (int o = 16; o; o >>= 1) s += __shfl_xor_sync(~0u, s, o);
    if ((tid & 31) == 0) sm[tid >> 5] = s;
    __syncthreads();
    float inv = 1.f / (sm[0]+sm[1]+sm[2]+sm[3]);
    x[tid] = make_float2(v.x * inv, v.y * inv);
}

__global__ void __launch_bounds__(256) softmax_wide(float* __restrict__ X) {
    long r = blockIdx.x;
    float* x = X + r * (long)NPAD;
    int tid = threadIdx.x;
    float4 v[15];
    #pragma unroll
    for (int i = 0; i < 15; i++) v[i] = *(float4*)&x[tid*4 + i*1024];
    __shared__ float sm[8];
    float m = -1e30f;
    #pragma unroll
    for (int i = 0; i < 15; i++)
        m = fmaxf(m, fmaxf(fmaxf(v[i].x, v[i].y), fmaxf(v[i].z, v[i].w)));
    #pragma unroll
    for (int o = 16; o; o >>= 1) m = fmaxf(m, __shfl_xor_sync(~0u, m, o));
    if ((tid & 31) == 0) sm[tid >> 5] = m;
    __syncthreads();
    m = fmaxf(fmaxf(fmaxf(sm[0],sm[1]),fmaxf(sm[2],sm[3])),
              fmaxf(fmaxf(sm[4],sm[5]),fmaxf(sm[6],sm[7])));
    __syncthreads();
    float s = 0.f;
    #pragma unroll
    for (int i = 0; i < 15; i++) {
        v[i].x = expf(v[i].x - m); v[i].y = expf(v[i].y - m);
        v[i].z = expf(v[i].z - m); v[i].w = expf(v[i].w - m);
        s += v[i].x + v[i].y + v[i].z + v[i].w;
    }
    #pragma unroll
    for (int o = 16; o; o >>= 1) s += __shfl_xor_sync(~0u, s, o);
    if ((tid & 31) == 0) sm[tid >> 5] = s;
    __syncthreads();
    float inv = 1.f / (sm[0]+sm[1]+sm[2]+sm[3]+sm[4]+sm[5]+sm[6]+sm[7]);
    #pragma unroll
    for (int i = 0; i < 15; i++) {
        v[i].x *= inv; v[i].y *= inv; v[i].z *= inv; v[i].w *= inv;
        *(float4*)&x[tid*4 + i*1024] = v[i];
    }
}

// depthwise conv(k=33) on V view; WRITES attn (attn1_fused accumulates after)
__global__ void __launch_bounds__(512) res_conv2(
    float* __restrict__ attn, const float* __restrict__ qkv,
    const float* __restrict__ w)
{
    int t0 = blockIdx.x * 8;
    int ch = threadIdx.x;
    int h = ch >> 6;
    float wk[33];
    #pragma unroll
    for (int k = 0; k < 33; k++) wk[k] = w[h*33 + k];
    float v[40];
    #pragma unroll
    for (int j = 0; j < 40; j++) {
        int tt = t0 + j - 16;
        v[j] = (tt >= 0 && tt < NPAD) ? qkv[(long)tt*QKVD + 2*DIM + ch] : 0.f;
    }
    #pragma unroll
    for (int j = 0; j < 8; j++) {
        float s = 0.f;
        #pragma unroll
        for (int k = 0; k < 33; k++) s += wk[k] * v[j + k];
        attn[(long)(t0 + j)*DIM + ch] = s;
    }
}

#define PPP 16
__global__ void __launch_bounds__(128) ppeg2(
    const float* __restrict__ h, float* __restrict__ out,
    const float* __restrict__ w7, const float* __restrict__ b7,
    const float* __restrict__ w5, const float* __restrict__ b5,
    const float* __restrict__ w3, const float* __restrict__ b3)
{
    __shared__ float wc[49][128];
    int tid = threadIdx.x;
    int ch = blockIdx.y * 128 + tid;
    #pragma unroll
    for (int k = 0; k < 49; k++) {
        int dy = k / 7 - 3, dx = k % 7 - 3;
        float wv = w7[(long)ch*49 + k];
        if (dy >= -2 && dy <= 2 && dx >= -2 && dx <= 2)
            wv += w5[(long)ch*25 + (dy+2)*5 + (dx+2)];
        if (dy >= -1 && dy <= 1 && dx >= -1 && dx <= 1)
            wv += w3[(long)ch*9 + (dy+1)*3 + (dx+1)];
        if (k == 24) wv += 1.f;
        wc[k][tid] = wv;
    }
    float bias_c = b7[ch] + b5[ch] + b3[ch];
    __syncthreads();

    int p0 = blockIdx.x * PPP;
    #pragma unroll 1
    for (int pp = 0; pp < PPP; pp++) {
        int p = p0 + pp;
        if (p >= NPIX) break;
        int r = p / IMGH, c = p % IMGH;
        float acc = bias_c;
        if (r >= 3 && r < IMGH-3 && c >= 3 && c < IMGH-3) {
            #pragma unroll
            for (int k = 0; k < 49; k++) {
                int dy = k / 7 - 3, dx = k % 7 - 3;
                acc += h[(long)(1 + (r+dy)*IMGH + (c+dx))*DIM + ch] * wc[k][tid];
            }
        } else {
            #pragma unroll
            for (int k = 0; k < 49; k++) {
                int dy = k / 7 - 3, dx = k % 7 - 3;
                int rr = r + dy, cc = c + dx;
                if (rr >= 0 && rr < IMGH && cc >= 0 && cc < IMGH)
                    acc += h[(long)(1 + rr*IMGH + cc)*DIM + ch] * wc[k][tid];
            }
        }
        out[(long)p*DIM + ch] = acc;
    }
}

__global__ void ppeg_copyback(float* __restrict__ h, const float* __restrict__ y) {
    long i = (long)blockIdx.x * blockDim.x + threadIdx.x;
    if (i < (long)NPIX*DIM) h[DIM + i] = y[i];
}

__global__ void final_head(const float* __restrict__ h, const float* __restrict__ g,
                           const float* __restrict__ b, const float* __restrict__ W,
                           const float* __restrict__ bias, float* __restrict__ out,
                           int out_size)
{
    __shared__ float red[512];
    __shared__ float xn[512];
    int tid = threadIdx.x;
    float x = h[tid];
    red[tid] = x; __syncthreads();
    for (int st = 256; st > 0; st >>= 1) {
        if (tid < st) red[tid] += red[tid+st];
        __syncthreads();
    }
    float mu = red[0] / DIM; __syncthreads();
    float d = x - mu;
    red[tid] = d*d; __syncthreads();
    for (int st = 256; st > 0; st >>= 1) {
        if (tid < st) red[tid] += red[tid+st];
        __syncthreads();
    }
    float rstd = rsqrtf(red[0]/DIM + 1e-5f); __syncthreads();
    xn[tid] = d*rstd*g[tid] + b[tid];
    __syncthreads();
    if (tid < 5) {
        float s = bias[tid];
        for (int c = 0; c < DIM; c++) s += xn[c] * W[c*5 + tid];
        red[tid] = s;
    }
    __syncthreads();
    if (tid == 0) {
        float lg[5], mx = -1e30f;
        for (int j = 0; j < 5; j++) { lg[j] = red[j]; mx = fmaxf(mx, lg[j]); }
        float se = 0.f, pr[5];
        for (int j = 0; j < 5; j++) { pr[j] = expf(lg[j]-mx); se += pr[j]; }
        int am = 0;
        for (int j = 1; j < 5; j++) if (lg[j] > lg[am]) am = j;
        for (int j = 0; j < 5; j++) {
            if (j < out_size)     out[j]     = lg[j];
            if (5 + j < out_size) out[5 + j] = pr[j]/se;
        }
        if (10 < out_size) out[10] = (float)am;
        for (int j = 11; j < out_size; j++) out[j] = 0.f;
    }
}

// ---------------- host orchestration ----------------
struct Ptrs {
    float *h, *xln, *qkv, *QL, *KL, *A3;
    float *S2, *XZ, *T1, *T2, *Z, *Z2, *T, *U, *attn, *y, *scal;
};

static void get_ptrs(Ptrs& P) {
    cudaGetSymbolAddress((void**)&P.h,    g_h);
    cudaGetSymbolAddress((void**)&P.xln,  g_xln);
    cudaGetSymbolAddress((void**)&P.qkv,  g_qkv);
    cudaGetSymbolAddress((void**)&P.QL,   g_QL);
    cudaGetSymbolAddress((void**)&P.KL,   g_KL);
    cudaGetSymbolAddress((void**)&P.A3,   g_A3);
    cudaGetSymbolAddress((void**)&P.S2,   g_S2);
    cudaGetSymbolAddress((void**)&P.XZ,   g_XZ);
    cudaGetSymbolAddress((void**)&P.T1,   g_T1);
    cudaGetSymbolAddress((void**)&P.T2,   g_T2);
    cudaGetSymbolAddress((void**)&P.Z,    g_Zb);
    cudaGetSymbolAddress((void**)&P.Z2,   g_Z2b);
    cudaGetSymbolAddress((void**)&P.T,    g_Tb);
    cudaGetSymbolAddress((void**)&P.U,    g_Ub);
    cudaGetSymbolAddress((void**)&P.attn, g_attn);
    cudaGetSymbolAddress((void**)&P.y,    g_y);
    cudaGetSymbolAddress((void**)&P.scal, g_scal);
}

#define MMA_BIG_NN  gemm_mma<128,128,64,32,false,false>
#define MMA_BIG_NT  gemm_mma<128,128,64,32,true ,false>
#define MMA_SM_NN   gemm_mma<64,64,32,32,false,false>
#define MMA_SM_NT   gemm_mma<64,64,32,32,true ,false>
#define MMA_SM_SPK  gemm_mma<64,64,32,32,false,true >

static inline dim3 grid128(int M, int N, int batch) {
    return dim3(N / 128, (M + 127) / 128, batch);
}
static inline dim3 grid64(int M, int N, int batch) {
    return dim3(N / 64, (M + 63) / 64, batch);
}

static void run_attention(const Ptrs& P, const float* lng, const float* lnb,
                          const float* Wqkv, const float* Wout, const float* bout,
                          const float* resw)
{
    const long sLnd = (long)NL*DH;
    const long sQ   = (long)NL*NL;
    const float QS = 0.125f;

    const float* Kv = P.qkv + DIM;
    const float* Vv = P.qkv + 2*DIM;

    ln_pad<<<NPAD, 256>>>(P.h, P.xln, lng, lnb);
    MMA_BIG_NN<<<grid128(NPAD, 3*DIM, 1), 256>>>(
        P.xln, Wqkv, P.qkv, NPAD, 3*DIM, DIM, DIM, 3*DIM, 3*DIM,
        0, 0, 0, 1.f, 0.f, 0.f, nullptr, 0);
    // residual conv writes attn (=); attn1_fused accumulates later
    res_conv2<<<NPAD/8, 512>>>(P.attn, P.qkv, resw);
    landmarks_k<<<(HEADS*NL*DH + 255)/256, 256>>>(P.qkv, P.QL, P.KL);
    // sim2 + softmax + pinv
    MMA_SM_NT<<<grid64(NL, NL, HEADS), 128>>>(
        P.QL, P.KL, P.S2, NL, NL, DH, DH, DH, NL,
        sLnd, sLnd, sQ, QS, 0.f, 0.f, nullptr, 0);
    softmax256<<<HEADS*NL, 128>>>(P.S2);
    pinv_persist<<<PBLOCKS, 128>>>(P.S2, P.Z, P.Z2, P.XZ, P.T1, P.T2, P.scal);
    // a3 = softmax(QL @ K^T)
    MMA_BIG_NT<<<grid128(NL, NPAD, HEADS), 256>>>(
        P.QL, Kv, P.A3, NL, NPAD, DH, DH, QKVD, NPAD,
        sLnd, (long)DH, (long)NL*NPAD, QS, 0.f, 0.f, nullptr, 0);
    softmax_wide<<<HEADS*NL, 256>>>(P.A3);
    // T = a3 @ V (split-K)
    zero_kernel<<<(HEADS*NL*DH + 255)/256, 256>>>(P.T, (long)HEADS*NL*DH);
    MMA_SM_SPK<<<grid64(NL, DH, HEADS*NSPLIT), 128>>>(
        P.A3, Vv, P.T, NL, DH, NPAD, NPAD, QKVD, DH,
        (long)NL*NPAD, (long)DH, sLnd, 1.f, 0.f, 0.f, nullptr, 0);
    // U = a2_inv @ T
    MMA_SM_NN<<<grid64(NL, DH, HEADS), 128>>>(
        P.Z, P.T, P.U, NL, DH, NL, NL, DH, DH,
        sQ, sLnd, sLnd, 1.f, 0.f, 0.f, nullptr, 0);
    // fused a1: attn += softmax(0.125 Q@KL^T) @ U
    attn1_fused<<<dim3(NPAD/64, HEADS), 128, A1_SMEMB>>>(P.qkv, P.KL, P.U, P.attn);
    // out projection with fused residual add into h (mode 2)
    MMA_BIG_NN<<<grid128(NPAD, DIM, 1), 256>>>(
        P.attn, Wout, P.h, NPAD, DIM, DIM, DIM, DIM, DIM,
        0, 0, 0, 1.f, 0.f, 0.f, bout, 2);
}

extern "C" void kernel_launch(void* const* d_in, const int* in_sizes, int n_in,
                              void* d_out, int out_size)
{
    const float* data      = (const float*)d_in[0];
    const float* W_fc1     = (const float*)d_in[1];
    const float* b_fc1     = (const float*)d_in[2];
    const float* cls_token = (const float*)d_in[3];
    const float* ln1_g     = (const float*)d_in[4];
    const float* ln1_b     = (const float*)d_in[5];
    const float* qkv1      = (const float*)d_in[6];
    const float* out1_w    = (const float*)d_in[7];
    const float* out1_b    = (const float*)d_in[8];
    const float* res1      = (const float*)d_in[9];
    const float* w7        = (const float*)d_in[10];
    const float* b7        = (const float*)d_in[11];
    const float* w5        = (const float*)d_in[12];
    const float* b5        = (const float*)d_in[13];
    const float* w3        = (const float*)d_in[14];
    const float* b3        = (const float*)d_in[15];
    const float* ln2_g     = (const float*)d_in[16];
    const float* ln2_b     = (const float*)d_in[17];
    const float* qkv2      = (const float*)d_in[18];
    const float* out2_w    = (const float*)d_in[19];
    const float* out2_b    = (const float*)d_in[20];
    const float* res2      = (const float*)d_in[21];
    const float* norm_g    = (const float*)d_in[22];
    const float* norm_b    = (const float*)d_in[23];
    const float* W_fc2     = (const float*)d_in[24];
    const float* b_fc2     = (const float*)d_in[25];

    Ptrs P;
    get_ptrs(P);

    cudaFuncSetAttribute(attn1_fused,
        cudaFuncAttributeMaxDynamicSharedMemorySize, A1_SMEMB);

    set_cls<<<1, DIM>>>(P.h, cls_token);
    MMA_BIG_NN<<<grid128(15000, DIM, 1), 256>>>(
        data, W_fc1, P.h + DIM, 15000, DIM, 1024, 1024, DIM, DIM,
        0, 0, 0, 1.f, 0.f, 0.f, b_fc1, 1);
    dup_rows<<<(129*DIM + 255)/256, 256>>>(P.h);

    run_attention(P, ln1_g, ln1_b, qkv1, out1_w, out1_b, res1);

    ppeg2<<<dim3((NPIX + PPP - 1)/PPP, DIM/128), 128>>>(
        P.h, P.y, w7, b7, w5, b5, w3, b3);
    ppeg_copyback<<<(int)(((long)NPIX*DIM + 255)/256), 256>>>(P.h, P.y);

    run_attention(P, ln2_g, ln2_b, qkv2, out2_w, out2_b, res2);

    final_head<<<1, DIM>>>(P.h, norm_g, norm_b, W_fc2, b_fc2, (float*)d_out, out_size);
}